// round 11
// baseline (speedup 1.0000x reference)
#include <cuda_runtime.h>
#include <cuda_bf16.h>
#include <math.h>
#include <stdint.h>

#define TT   2048
#define DD   2048
#define NQ   16
#define NKV  4
#define HDIM 128
#define NE   16
#define NF   1024
#define TOPK 4

#define QKVW 3072
#define KOFF 2048
#define VOFF 2560

// ---------------- scratch ----------------
__device__ float g_qkv  [TT * QKVW];
__device__ float g_hmid [TT * DD];
__device__ float g_h2   [TT * DD];
__device__ float g_rw   [TT * TOPK];
__device__ int   g_ecnt [NE];
__device__ int   g_erows[NE * TT];

__device__ __nv_bfloat16 g_hn_h   [TT * DD];
__device__ __nv_bfloat16 g_hn_l   [TT * DD];
__device__ __nv_bfloat16 g_q_h    [TT * NQ * HDIM];
__device__ __nv_bfloat16 g_q_l    [TT * NQ * HDIM];
__device__ __nv_bfloat16 g_k_h    [TT * NKV * HDIM];
__device__ __nv_bfloat16 g_k_l    [TT * NKV * HDIM];
__device__ __nv_bfloat16 g_v_h    [TT * NKV * HDIM];
__device__ __nv_bfloat16 g_v_l    [TT * NKV * HDIM];
__device__ __nv_bfloat16 g_attn_h [TT * DD];
__device__ __nv_bfloat16 g_attn_l [TT * DD];
__device__ __nv_bfloat16 g_h2_h   [TT * DD];
__device__ __nv_bfloat16 g_h2_l   [TT * DD];
__device__ __nv_bfloat16 g_gated_h[TT * TOPK * NF];
__device__ __nv_bfloat16 g_gated_l[TT * TOPK * NF];

// split-bf16 weights in NATURAL [K][N] layout (gate_up column-interleaved)
__device__ __nv_bfloat16 g_wqkv_h[DD * QKVW];
__device__ __nv_bfloat16 g_wqkv_l[DD * QKVW];
__device__ __nv_bfloat16 g_wo_h  [DD * DD];
__device__ __nv_bfloat16 g_wo_l  [DD * DD];
__device__ __nv_bfloat16 g_wgu_h [NE * DD * (2 * NF)];
__device__ __nv_bfloat16 g_wgu_l [NE * DD * (2 * NF)];
__device__ __nv_bfloat16 g_wdn_h [NE * NF * DD];
__device__ __nv_bfloat16 g_wdn_l [NE * NF * DD];

// ================= helpers =================
__device__ __forceinline__ uint32_t smem_u32(const void* p) {
    uint32_t r;
    asm("{ .reg .u64 t; cvta.to.shared.u64 t, %1; cvt.u32.u64 %0, t; }" : "=r"(r) : "l"(p));
    return r;
}
__device__ __forceinline__ uint32_t pack2bf(__nv_bfloat16 a, __nv_bfloat16 b) {
    return (uint32_t)__bfloat16_as_ushort(a) | ((uint32_t)__bfloat16_as_ushort(b) << 16);
}
__device__ __forceinline__ void ldsm4(uint32_t* r, uint32_t a) {
    asm volatile("ldmatrix.sync.aligned.m8n8.x4.shared.b16 {%0,%1,%2,%3}, [%4];"
                 : "=r"(r[0]), "=r"(r[1]), "=r"(r[2]), "=r"(r[3]) : "r"(a));
}
__device__ __forceinline__ void ldsm4t(uint32_t* r, uint32_t a) {
    asm volatile("ldmatrix.sync.aligned.m8n8.x4.trans.shared.b16 {%0,%1,%2,%3}, [%4];"
                 : "=r"(r[0]), "=r"(r[1]), "=r"(r[2]), "=r"(r[3]) : "r"(a));
}
__device__ __forceinline__ void mma16816(float* c, const uint32_t* a, const uint32_t* b) {
    asm volatile("mma.sync.aligned.m16n8k16.row.col.f32.bf16.bf16.f32 "
                 "{%0,%1,%2,%3}, {%4,%5,%6,%7}, {%8,%9}, {%0,%1,%2,%3};"
                 : "+f"(c[0]), "+f"(c[1]), "+f"(c[2]), "+f"(c[3])
                 : "r"(a[0]), "r"(a[1]), "r"(a[2]), "r"(a[3]), "r"(b[0]), "r"(b[1]));
}
#define CP16(dst, src) \
    asm volatile("cp.async.cg.shared.global [%0], [%1], 16;" :: "r"(dst), "l"(src))
#define CP_COMMIT() asm volatile("cp.async.commit_group;" ::: "memory")
#define CP_WAIT1()  asm volatile("cp.async.wait_group 1;" ::: "memory")
#define CP_WAIT0()  asm volatile("cp.async.wait_group 0;" ::: "memory")

__device__ __forceinline__ void split_bf16(float v, __nv_bfloat16& h, __nv_bfloat16& l) {
    h = __float2bfloat16(v);
    l = __float2bfloat16(v - __bfloat162float(h));
}

// ================= streaming weight split =================
__global__ void wsplit_kernel(const float4* __restrict__ in,
                              uint2* __restrict__ oh, uint2* __restrict__ ol, int n4)
{
    int i = blockIdx.x * blockDim.x + threadIdx.x;
    if (i >= n4) return;
    float4 v = in[i];
    __nv_bfloat16 h0, l0, h1, l1, h2, l2, h3, l3;
    split_bf16(v.x, h0, l0); split_bf16(v.y, h1, l1);
    split_bf16(v.z, h2, l2); split_bf16(v.w, h3, l3);
    oh[i] = make_uint2(pack2bf(h0, h1), pack2bf(h2, h3));
    ol[i] = make_uint2(pack2bf(l0, l1), pack2bf(l2, l3));
}
__global__ void wsplit_qkv_kernel(const float4* __restrict__ q, const float4* __restrict__ k,
                                  const float4* __restrict__ v,
                                  uint2* __restrict__ oh, uint2* __restrict__ ol)
{
    int i = blockIdx.x * 256 + threadIdx.x;   // over 2048*768
    int row = i / 768, c4 = i % 768;
    float4 val;
    if (c4 < 512)      val = q[row * 512 + c4];
    else if (c4 < 640) val = k[row * 128 + (c4 - 512)];
    else               val = v[row * 128 + (c4 - 640)];
    __nv_bfloat16 h0, l0, h1, l1, h2, l2, h3, l3;
    split_bf16(val.x, h0, l0); split_bf16(val.y, h1, l1);
    split_bf16(val.z, h2, l2); split_bf16(val.w, h3, l3);
    oh[i] = make_uint2(pack2bf(h0, h1), pack2bf(h2, h3));
    ol[i] = make_uint2(pack2bf(l0, l1), pack2bf(l2, l3));
}
// gate_up with column interleave: out[d][2f] = gate[d][f], out[d][2f+1] = up[d][f]
__global__ void wsplit_gu_kernel(const float* __restrict__ in,   // [NE][DD][2NF]
                                 uint2* __restrict__ oh, uint2* __restrict__ ol)
{
    int i = blockIdx.x * 256 + threadIdx.x;       // uint2 index: 4 out bf16 = 2 f values
    // i covers NE*DD*2NF/4 elements
    int per_row = (2 * NF) / 4;                   // 512 uint2 per [e][d] row
    int row = i / per_row;                        // e*DD + d
    int j = i % per_row;                          // out cols 4j..4j+3 -> f = 2j, 2j+1
    const float* base = in + (size_t)row * (2 * NF);
    float g0 = base[2 * j],      g1 = base[2 * j + 1];
    float u0 = base[NF + 2 * j], u1 = base[NF + 2 * j + 1];
    __nv_bfloat16 gh0, gl0, uh0, ul0, gh1, gl1, uh1, ul1;
    split_bf16(g0, gh0, gl0); split_bf16(u0, uh0, ul0);
    split_bf16(g1, gh1, gl1); split_bf16(u1, uh1, ul1);
    oh[i] = make_uint2(pack2bf(gh0, uh0), pack2bf(gh1, uh1));
    ol[i] = make_uint2(pack2bf(gl0, ul0), pack2bf(gl1, ul1));
}

// ================= bf16x3 GEMM: 16 warps x (32x64), trans-B from [K][N] =================
#define KC 32
#define ARS 80
#define BRS 528
#define A_SZ (128 * ARS)
#define B_SZ (KC * BRS)
#define STG  (2 * A_SZ + 2 * B_SZ)
#define AH_O 0
#define AL_O A_SZ
#define BH_O (2 * A_SZ)
#define BL_O (2 * A_SZ + B_SZ)
#define EROFF (3 * STG)
#define GEMM_SMEM (EROFF + 512)

// mode 0: dense C = A @ B (+addsrc)
// mode 1: moe gate_up with FUSED SiLU: writes g_gated_h/l (C unused)
// mode 2: moe down: atomicAdd into C[tok] * g_rw
__global__ void __launch_bounds__(512) bf16x3_gemm_kernel(
    int mode,
    const __nv_bfloat16* __restrict__ Ah, const __nv_bfloat16* __restrict__ Al,
    const __nv_bfloat16* __restrict__ Bh, const __nv_bfloat16* __restrict__ Bl,
    float* __restrict__ C, const float* __restrict__ addsrc, int N, int K)
{
    int e  = blockIdx.z;
    int m0 = blockIdx.y * 128;
    int n0 = blockIdx.x * 256;
    int cnt = 0;
    if (mode != 0) {
        cnt = g_ecnt[e];
        if (m0 >= cnt) return;
        Bh += (size_t)e * K * N;
        Bl += (size_t)e * K * N;
    }
    extern __shared__ char sm[];
    uint32_t sb = smem_u32(sm);
    int tid = threadIdx.x, wid = tid >> 5, l = tid & 31;
    int* erows_s = (int*)(sm + EROFF);
    if (mode != 0 && tid < 128)
        erows_s[tid] = (m0 + tid < cnt) ? g_erows[e * TT + m0 + tid] : 0;
    __syncthreads();

    int arow = tid >> 2, apart = tid & 3;
    size_t aro;
    if (mode == 0)      aro = (size_t)(m0 + arow) * K;
    else if (mode == 1) aro = (size_t)(erows_s[arow] >> 2) * DD;
    else                aro = (size_t)erows_s[arow] * NF;
    const __nv_bfloat16* aph = Ah + aro + apart * 8;
    const __nv_bfloat16* apl = Al + aro + apart * 8;
    uint32_t a_dst = (uint32_t)(arow * ARS + apart * 16);

    int brow = tid >> 4, bpart = tid & 15;
    size_t bo = (size_t)brow * N + n0 + bpart * 16;
    uint32_t b_dst = (uint32_t)(brow * BRS + bpart * 32);

    int NC = K / KC;

    int wm = wid >> 2, wn = wid & 3;
    int a_r = (l & 7) + ((l >> 3) & 1) * 8;
    int a_c = (l >> 4) * 8;
    uint32_t a_base = (uint32_t)((wm * 32 + a_r) * ARS + a_c * 2);
    uint32_t b_base = (uint32_t)(a_r * BRS + (wn * 64 + a_c) * 2);

    float acc[2][8][4];
#pragma unroll
    for (int mi = 0; mi < 2; mi++)
#pragma unroll
        for (int ni = 0; ni < 8; ni++)
#pragma unroll
            for (int j = 0; j < 4; j++) acc[mi][ni][j] = 0.f;

#pragma unroll
    for (int p = 0; p < 2; p++) {
        if (p < NC) {
            uint32_t st = sb + p * STG;
            int k0 = p * KC;
            CP16(st + AH_O + a_dst, aph + k0);
            CP16(st + AL_O + a_dst, apl + k0);
            const __nv_bfloat16* bsh = Bh + bo + (size_t)k0 * N;
            const __nv_bfloat16* bsl = Bl + bo + (size_t)k0 * N;
            CP16(st + BH_O + b_dst,      bsh);
            CP16(st + BH_O + b_dst + 16, bsh + 8);
            CP16(st + BL_O + b_dst,      bsl);
            CP16(st + BL_O + b_dst + 16, bsl + 8);
        }
        CP_COMMIT();
    }

    for (int c = 0; c < NC; c++) {
        if (c + 1 < NC) CP_WAIT1(); else CP_WAIT0();
        __syncthreads();
        if (c + 2 < NC) {
            int n2 = c + 2;
            uint32_t st = sb + (n2 % 3) * STG;
            int k0 = n2 * KC;
            CP16(st + AH_O + a_dst, aph + k0);
            CP16(st + AL_O + a_dst, apl + k0);
            const __nv_bfloat16* bsh = Bh + bo + (size_t)k0 * N;
            const __nv_bfloat16* bsl = Bl + bo + (size_t)k0 * N;
            CP16(st + BH_O + b_dst,      bsh);
            CP16(st + BH_O + b_dst + 16, bsh + 8);
            CP16(st + BL_O + b_dst,      bsl);
            CP16(st + BL_O + b_dst + 16, bsl + 8);
        }
        CP_COMMIT();

        uint32_t st = sb + (c % 3) * STG;
#pragma unroll
        for (int kk = 0; kk < 2; kk++) {
            uint32_t bh[4][4], bl[4][4];
#pragma unroll
            for (int q = 0; q < 4; q++)
                ldsm4t(bh[q], st + BH_O + b_base + kk * (16 * BRS) + q * 32);
#pragma unroll
            for (int q = 0; q < 4; q++)
                ldsm4t(bl[q], st + BL_O + b_base + kk * (16 * BRS) + q * 32);
#pragma unroll
            for (int mi = 0; mi < 2; mi++) {
                uint32_t ah[4], al[4];
                ldsm4(ah, st + AH_O + a_base + mi * (16 * ARS) + kk * 32);
                ldsm4(al, st + AL_O + a_base + mi * (16 * ARS) + kk * 32);
#pragma unroll
                for (int q = 0; q < 4; q++) {
                    mma16816(acc[mi][2 * q],     ah, &bh[q][0]);
                    mma16816(acc[mi][2 * q + 1], ah, &bh[q][2]);
                }
#pragma unroll
                for (int q = 0; q < 4; q++) {
                    mma16816(acc[mi][2 * q],     ah, &bl[q][0]);
                    mma16816(acc[mi][2 * q + 1], ah, &bl[q][2]);
                }
#pragma unroll
                for (int q = 0; q < 4; q++) {
                    mma16816(acc[mi][2 * q],     al, &bh[q][0]);
                    mma16816(acc[mi][2 * q + 1], al, &bh[q][2]);
                }
            }
        }
    }

    // epilogue
    int g = l >> 2, tig = l & 3;
#pragma unroll
    for (int mi = 0; mi < 2; mi++) {
        int r0 = wm * 32 + mi * 16 + g;
        int r1 = r0 + 8;
        bool v0 = true, v1 = true;
        size_t ro0 = 0, ro1 = 0;
        int rowid0 = 0, rowid1 = 0;
        float w0 = 0.f, w1 = 0.f;
        if (mode == 0) {
            ro0 = (size_t)(m0 + r0) * N;
            ro1 = (size_t)(m0 + r1) * N;
        } else {
            v0 = (m0 + r0) < cnt;
            v1 = (m0 + r1) < cnt;
            rowid0 = erows_s[r0]; rowid1 = erows_s[r1];
            if (mode == 2) {
                ro0 = (size_t)(rowid0 >> 2) * DD;
                ro1 = (size_t)(rowid1 >> 2) * DD;
                if (v0) w0 = g_rw[rowid0];
                if (v1) w1 = g_rw[rowid1];
            }
        }
#pragma unroll
        for (int ni = 0; ni < 8; ni++) {
            int cc = n0 + wn * 64 + ni * 8 + tig * 2;
            float* a = acc[mi][ni];
            if (mode == 0) {
                if (addsrc) {
                    float2 s0 = *(const float2*)(addsrc + ro0 + cc);
                    float2 s1 = *(const float2*)(addsrc + ro1 + cc);
                    *(float2*)(C + ro0 + cc) = make_float2(a[0] + s0.x, a[1] + s0.y);
                    *(float2*)(C + ro1 + cc) = make_float2(a[2] + s1.x, a[3] + s1.y);
                } else {
                    *(float2*)(C + ro0 + cc) = make_float2(a[0], a[1]);
                    *(float2*)(C + ro1 + cc) = make_float2(a[2], a[3]);
                }
            } else if (mode == 1) {
                // fused SiLU: (a[0], a[1]) = (gate_f, up_f) for row0; (a[2], a[3]) for row1
                int f = cc >> 1;
                if (v0) {
                    float gt = a[0];
                    float gated = a[1] * (gt / (1.f + __expf(-gt)));
                    __nv_bfloat16 h, lo;
                    split_bf16(gated, h, lo);
                    g_gated_h[(size_t)rowid0 * NF + f] = h;
                    g_gated_l[(size_t)rowid0 * NF + f] = lo;
                }
                if (v1) {
                    float gt = a[2];
                    float gated = a[3] * (gt / (1.f + __expf(-gt)));
                    __nv_bfloat16 h, lo;
                    split_bf16(gated, h, lo);
                    g_gated_h[(size_t)rowid1 * NF + f] = h;
                    g_gated_l[(size_t)rowid1 * NF + f] = lo;
                }
            } else {
                if (v0) { atomicAdd(C + ro0 + cc, w0 * a[0]); atomicAdd(C + ro0 + cc + 1, w0 * a[1]); }
                if (v1) { atomicAdd(C + ro1 + cc, w1 * a[2]); atomicAdd(C + ro1 + cc + 1, w1 * a[3]); }
            }
        }
    }
}

// ================= RMSNorm (split-bf16 + optional fp32 out + optional passthrough copy) =================
__global__ void rmsnorm_kernel(const float* __restrict__ x,
                               const float* __restrict__ w,
                               float* __restrict__ ofp,
                               __nv_bfloat16* __restrict__ oh,
                               __nv_bfloat16* __restrict__ ol,
                               float* __restrict__ ocopy)
{
    int t = blockIdx.x;
    const float4* xr = (const float4*)(x + (size_t)t * DD);
    const float4* wr = (const float4*)w;
    int tid = threadIdx.x;
    float4 v0 = xr[tid], v1 = xr[tid + 256];
    if (ocopy) {
        float4* orow = (float4*)(ocopy + (size_t)t * DD);
        orow[tid] = v0; orow[tid + 256] = v1;
    }
    float ss = v0.x*v0.x + v0.y*v0.y + v0.z*v0.z + v0.w*v0.w
             + v1.x*v1.x + v1.y*v1.y + v1.z*v1.z + v1.w*v1.w;
#pragma unroll
    for (int o = 16; o; o >>= 1) ss += __shfl_xor_sync(0xffffffffu, ss, o);
    __shared__ float red[8];
    if ((tid & 31) == 0) red[tid >> 5] = ss;
    __syncthreads();
    float tot = red[0]+red[1]+red[2]+red[3]+red[4]+red[5]+red[6]+red[7];
    float r = rsqrtf(tot / (float)DD + 1e-6f);
    float4 w0 = wr[tid], w1 = wr[tid + 256];
    float4 o0, o1;
    o0.x = v0.x*r*w0.x; o0.y = v0.y*r*w0.y; o0.z = v0.z*r*w0.z; o0.w = v0.w*r*w0.w;
    o1.x = v1.x*r*w1.x; o1.y = v1.y*r*w1.y; o1.z = v1.z*r*w1.z; o1.w = v1.w*r*w1.w;
    if (ofp) {
        float4* orow = (float4*)(ofp + (size_t)t * DD);
        orow[tid] = o0; orow[tid + 256] = o1;
    }
    __nv_bfloat16 h[8], lo[8];
    split_bf16(o0.x, h[0], lo[0]); split_bf16(o0.y, h[1], lo[1]);
    split_bf16(o0.z, h[2], lo[2]); split_bf16(o0.w, h[3], lo[3]);
    split_bf16(o1.x, h[4], lo[4]); split_bf16(o1.y, h[5], lo[5]);
    split_bf16(o1.z, h[6], lo[6]); split_bf16(o1.w, h[7], lo[7]);
    uint2* ohr = (uint2*)(oh + (size_t)t * DD);
    uint2* olr = (uint2*)(ol + (size_t)t * DD);
    ohr[tid]       = make_uint2(pack2bf(h[0], h[1]),  pack2bf(h[2], h[3]));
    ohr[tid + 256] = make_uint2(pack2bf(h[4], h[5]),  pack2bf(h[6], h[7]));
    olr[tid]       = make_uint2(pack2bf(lo[0], lo[1]), pack2bf(lo[2], lo[3]));
    olr[tid + 256] = make_uint2(pack2bf(lo[4], lo[5]), pack2bf(lo[6], lo[7]));
}

// ================= per-head RMSNorm + RoPE + split =================
__global__ void normrope_kernel(const float* __restrict__ cosb,
                                const float* __restrict__ sinb,
                                const float* __restrict__ qnw,
                                const float* __restrict__ knw)
{
    int t = blockIdx.x;
    int head = blockIdx.y;      // 0..15 q, 16..19 k, 20..23 v
    int h = threadIdx.x;
    if (head >= 20) {
        int kvh = head - 20;
        float v = g_qkv[(size_t)t * QKVW + VOFF + kvh * HDIM + h];
        __nv_bfloat16 hh, ll;
        split_bf16(v, hh, ll);
        size_t o = ((size_t)t * NKV + kvh) * HDIM + h;
        g_v_h[o] = hh; g_v_l[o] = ll;
        return;
    }
    const float* src;
    const float* nw;
    if (head < NQ) { src = g_qkv + (size_t)t * QKVW + head * HDIM;               nw = qnw; }
    else           { src = g_qkv + (size_t)t * QKVW + KOFF + (head - NQ) * HDIM; nw = knw; }
    float v = src[h];
    float ss = v * v;
#pragma unroll
    for (int o = 16; o; o >>= 1) ss += __shfl_xor_sync(0xffffffffu, ss, o);
    __shared__ float red[4];
    __shared__ float xs[128];
    if ((h & 31) == 0) red[h >> 5] = ss;
    __syncthreads();
    float tot = red[0] + red[1] + red[2] + red[3];
    float xn = v * rsqrtf(tot / (float)HDIM + 1e-6f) * nw[h];
    xs[h] = xn;
    __syncthreads();
    float c = cosb[(size_t)t * HDIM + h];
    float s = sinb[(size_t)t * HDIM + h];
    float other = (h < 64) ? xs[h + 64] : xs[h - 64];
    float outv = (h < 64) ? (xn * c - other * s) : (xn * c + other * s);
    __nv_bfloat16 hh, ll;
    split_bf16(outv, hh, ll);
    if (head < NQ) {
        size_t o = ((size_t)t * NQ + head) * HDIM + h;
        g_q_h[o] = hh; g_q_l[o] = ll;
    } else {
        size_t o = ((size_t)t * NKV + (head - NQ)) * HDIM + h;
        g_k_h[o] = hh; g_k_l[o] = ll;
    }
}

// ================= flash attention, bf16x3 HMMA =================
#define AT_RST  272
#define AT_TILE (64 * AT_RST)
#define AT_QH 0
#define AT_QL (1 * AT_TILE)
#define AT_KH (2 * AT_TILE)
#define AT_KL (3 * AT_TILE)
#define AT_VH (4 * AT_TILE)
#define AT_VL (5 * AT_TILE)
#define AT_SMEM (6 * AT_TILE)

__device__ __forceinline__ void attn_issue_kv(uint32_t sb, int j0, int kvh,
                                              int srow, int spart)
{
    size_t base = ((size_t)(j0 + srow) * NKV + kvh) * HDIM + spart * 64;
    uint32_t d = (uint32_t)(srow * AT_RST + spart * 128);
#pragma unroll
    for (int i = 0; i < 8; i++) {
        CP16(sb + AT_KH + d + i * 16, g_k_h + base + i * 8);
        CP16(sb + AT_KL + d + i * 16, g_k_l + base + i * 8);
        CP16(sb + AT_VH + d + i * 16, g_v_h + base + i * 8);
        CP16(sb + AT_VL + d + i * 16, g_v_l + base + i * 8);
    }
}

__global__ void __launch_bounds__(128) attn_kernel()
{
    extern __shared__ char sm[];
    uint32_t sb = smem_u32(sm);
    int m0 = blockIdx.x * 64;
    int head = blockIdx.y;
    int kvh = head >> 2;
    int tid = threadIdx.x, wid = tid >> 5, l = tid & 31;
    const float scale = 0.08838834764831843f;

    int srow = tid >> 1, spart = tid & 1;
    {
        size_t qb = ((size_t)(m0 + srow) * NQ + head) * HDIM + spart * 64;
        uint32_t d = (uint32_t)(srow * AT_RST + spart * 128);
#pragma unroll
        for (int i = 0; i < 8; i++) {
            CP16(sb + AT_QH + d + i * 16, g_q_h + qb + i * 8);
            CP16(sb + AT_QL + d + i * 16, g_q_l + qb + i * 8);
        }
    }
    attn_issue_kv(sb, 0, kvh, srow, spart);
    CP_COMMIT();

    int a_r = (l & 7) + ((l >> 3) & 1) * 8;
    int a_c = (l >> 4) * 8;
    int b_r = (l & 7) + (l >> 4) * 8;
    int b_c = ((l >> 3) & 1) * 8;

    float o[16][4];
#pragma unroll
    for (int nd = 0; nd < 16; nd++)
#pragma unroll
        for (int j = 0; j < 4; j++) o[nd][j] = 0.f;
    float m_i0 = -1e30f, m_i1 = -1e30f, l0 = 0.f, l1 = 0.f;

    int njt = blockIdx.x + 1;
    for (int jt = 0; jt < njt; jt++) {
        CP_WAIT0();
        __syncthreads();

        float s[8][4];
#pragma unroll
        for (int ni = 0; ni < 8; ni++)
#pragma unroll
            for (int j = 0; j < 4; j++) s[ni][j] = 0.f;
#pragma unroll
        for (int ks = 0; ks < 8; ks++) {
            uint32_t qh4[4], ql4[4];
            uint32_t qa = sb + (uint32_t)((wid * 16 + a_r) * AT_RST + (ks * 16 + a_c) * 2);
            ldsm4(qh4, qa + AT_QH);
            ldsm4(ql4, qa + AT_QL);
            uint32_t kh[4][4], kl[4][4];
#pragma unroll
            for (int q2 = 0; q2 < 4; q2++) {
                uint32_t ka = sb + (uint32_t)((q2 * 16 + b_r) * AT_RST + (ks * 16 + b_c) * 2);
                ldsm4(kh[q2], ka + AT_KH);
                ldsm4(kl[q2], ka + AT_KL);
            }
#pragma unroll
            for (int q2 = 0; q2 < 4; q2++) {
                mma16816(s[2 * q2],     qh4, &kh[q2][0]);
                mma16816(s[2 * q2 + 1], qh4, &kh[q2][2]);
            }
#pragma unroll
            for (int q2 = 0; q2 < 4; q2++) {
                mma16816(s[2 * q2],     qh4, &kl[q2][0]);
                mma16816(s[2 * q2 + 1], qh4, &kl[q2][2]);
            }
#pragma unroll
            for (int q2 = 0; q2 < 4; q2++) {
                mma16816(s[2 * q2],     ql4, &kh[q2][0]);
                mma16816(s[2 * q2 + 1], ql4, &kh[q2][2]);
            }
        }
#pragma unroll
        for (int ni = 0; ni < 8; ni++)
#pragma unroll
            for (int j = 0; j < 4; j++) s[ni][j] *= scale;
        if (jt == njt - 1) {
            int rA = wid * 16 + (l >> 2), rB = rA + 8;
#pragma unroll
            for (int ni = 0; ni < 8; ni++) {
                int c0 = ni * 8 + 2 * (l & 3), c1 = c0 + 1;
                if (c0 > rA) s[ni][0] = -1e30f;
                if (c1 > rA) s[ni][1] = -1e30f;
                if (c0 > rB) s[ni][2] = -1e30f;
                if (c1 > rB) s[ni][3] = -1e30f;
            }
        }
        float mt0 = -1e30f, mt1 = -1e30f;
#pragma unroll
        for (int ni = 0; ni < 8; ni++) {
            mt0 = fmaxf(mt0, fmaxf(s[ni][0], s[ni][1]));
            mt1 = fmaxf(mt1, fmaxf(s[ni][2], s[ni][3]));
        }
        mt0 = fmaxf(mt0, __shfl_xor_sync(0xffffffffu, mt0, 1));
        mt0 = fmaxf(mt0, __shfl_xor_sync(0xffffffffu, mt0, 2));
        mt1 = fmaxf(mt1, __shfl_xor_sync(0xffffffffu, mt1, 1));
        mt1 = fmaxf(mt1, __shfl_xor_sync(0xffffffffu, mt1, 2));
        float mn0 = fmaxf(m_i0, mt0), mn1 = fmaxf(m_i1, mt1);
        float c0 = __expf(m_i0 - mn0), c1 = __expf(m_i1 - mn1);
        l0 *= c0; l1 *= c1;
#pragma unroll
        for (int nd = 0; nd < 16; nd++) {
            o[nd][0] *= c0; o[nd][1] *= c0; o[nd][2] *= c1; o[nd][3] *= c1;
        }
        m_i0 = mn0; m_i1 = mn1;
        float rs0 = 0.f, rs1 = 0.f;
        uint32_t pha[16], pla[16];
#pragma unroll
        for (int ni = 0; ni < 8; ni++) {
            float p0 = __expf(s[ni][0] - mn0), p1 = __expf(s[ni][1] - mn0);
            float p2 = __expf(s[ni][2] - mn1), p3 = __expf(s[ni][3] - mn1);
            rs0 += p0 + p1; rs1 += p2 + p3;
            __nv_bfloat16 h0, l0b, h1, l1b, h2, l2b, h3, l3b;
            split_bf16(p0, h0, l0b); split_bf16(p1, h1, l1b);
            split_bf16(p2, h2, l2b); split_bf16(p3, h3, l3b);
            pha[2 * ni]     = pack2bf(h0, h1);
            pha[2 * ni + 1] = pack2bf(h2, h3);
            pla[2 * ni]     = pack2bf(l0b, l1b);
            pla[2 * ni + 1] = pack2bf(l2b, l3b);
        }
        rs0 += __shfl_xor_sync(0xffffffffu, rs0, 1);
        rs0 += __shfl_xor_sync(0xffffffffu, rs0, 2);
        rs1 += __shfl_xor_sync(0xffffffffu, rs1, 1);
        rs1 += __shfl_xor_sync(0xffffffffu, rs1, 2);
        l0 += rs0; l1 += rs1;

#pragma unroll
        for (int ks = 0; ks < 4; ks++) {
            const uint32_t* ph = &pha[4 * ks];
            const uint32_t* pl = &pla[4 * ks];
#pragma unroll
            for (int dp = 0; dp < 4; dp++) {
                uint32_t vh[2][4], vl[2][4];
#pragma unroll
                for (int u = 0; u < 2; u++) {
                    uint32_t va = sb + (uint32_t)((ks * 16 + a_r) * AT_RST +
                                                  ((2 * dp + u) * 16 + a_c) * 2);
                    ldsm4t(vh[u], va + AT_VH);
                    ldsm4t(vl[u], va + AT_VL);
                }
                mma16816(o[4 * dp],     ph, &vh[0][0]);
                mma16816(o[4 * dp + 1], ph, &vh[0][2]);
                mma16816(o[4 * dp + 2], ph, &vh[1][0]);
                mma16816(o[4 * dp + 3], ph, &vh[1][2]);
                mma16816(o[4 * dp],     pl, &vh[0][0]);
                mma16816(o[4 * dp + 1], pl, &vh[0][2]);
                mma16816(o[4 * dp + 2], pl, &vh[1][0]);
                mma16816(o[4 * dp + 3], pl, &vh[1][2]);
                mma16816(o[4 * dp],     ph, &vl[0][0]);
                mma16816(o[4 * dp + 1], ph, &vl[0][2]);
                mma16816(o[4 * dp + 2], ph, &vl[1][0]);
                mma16816(o[4 * dp + 3], ph, &vl[1][2]);
            }
        }
        __syncthreads();
        if (jt + 1 < njt) attn_issue_kv(sb, (jt + 1) * 64, kvh, srow, spart);
        CP_COMMIT();
    }

    float inv0 = 1.f / l0, inv1 = 1.f / l1;
    int rA = m0 + wid * 16 + (l >> 2);
    int rB = rA + 8;
#pragma unroll
    for (int nd = 0; nd < 16; nd++) {
        int d = nd * 8 + 2 * (l & 3);
        float v0 = o[nd][0] * inv0, v1 = o[nd][1] * inv0;
        float v2 = o[nd][2] * inv1, v3 = o[nd][3] * inv1;
        __nv_bfloat16 h0, lo0, h1, lo1, h2, lo2, h3, lo3;
        split_bf16(v0, h0, lo0); split_bf16(v1, h1, lo1);
        split_bf16(v2, h2, lo2); split_bf16(v3, h3, lo3);
        size_t oA = (size_t)rA * DD + head * HDIM + d;
        size_t oB = (size_t)rB * DD + head * HDIM + d;
        *(uint32_t*)(g_attn_h + oA) = pack2bf(h0, h1);
        *(uint32_t*)(g_attn_l + oA) = pack2bf(lo0, lo1);
        *(uint32_t*)(g_attn_h + oB) = pack2bf(h2, h3);
        *(uint32_t*)(g_attn_l + oB) = pack2bf(lo2, lo3);
    }
}

// ================= routing =================
__global__ void zero_cnt_kernel() { if (threadIdx.x < NE) g_ecnt[threadIdx.x] = 0; }

__global__ void route_kernel(const float* __restrict__ gate_w)
{
    int t = blockIdx.x;
    int tid = threadIdx.x;
    const float* x = g_h2 + (size_t)t * DD;
    float acc[NE];
#pragma unroll
    for (int e = 0; e < NE; e++) acc[e] = 0.f;
    for (int d = tid; d < DD; d += 128) {
        float xv = x[d];
        const float* gw = gate_w + (size_t)d * NE;
#pragma unroll
        for (int e = 0; e < NE; e++) acc[e] += xv * gw[e];
    }
    __shared__ float s[NE * 128];
#pragma unroll
    for (int e = 0; e < NE; e++) s[e * 128 + tid] = acc[e];
    __syncthreads();
    __shared__ float logits[NE];
    if (tid < NE) {
        float sum = 0.f;
        for (int i = 0; i < 128; i++) sum += s[tid * 128 + i];
        logits[tid] = sum;
    }
    __syncthreads();
    if (tid == 0) {
        float mx = -1e30f;
        for (int e = 0; e < NE; e++) mx = fmaxf(mx, logits[e]);
        float p[NE], Z = 0.f;
        for (int e = 0; e < NE; e++) { p[e] = expf(logits[e] - mx); Z += p[e]; }
        for (int e = 0; e < NE; e++) p[e] /= Z;
        int idx[TOPK]; float val[TOPK]; bool used[NE] = {};
        float wsum = 0.f;
        for (int k = 0; k < TOPK; k++) {
            int best = -1; float bv = -1.f;
            for (int e = 0; e < NE; e++)
                if (!used[e] && p[e] > bv) { bv = p[e]; best = e; }
            used[best] = true; idx[k] = best; val[k] = bv; wsum += bv;
        }
        for (int k = 0; k < TOPK; k++) {
            int rowid = t * TOPK + k;
            g_rw[rowid] = val[k] / wsum;
            int e = idx[k];
            int pos = atomicAdd(&g_ecnt[e], 1);
            g_erows[e * TT + pos] = rowid;
        }
    }
}

// ================= launch =================
extern "C" void kernel_launch(void* const* d_in, const int* in_sizes, int n_in,
                              void* d_out, int out_size)
{
    const float* hidden  = (const float*)d_in[0];
    const float* cosb    = (const float*)d_in[1];
    const float* sinb    = (const float*)d_in[2];
    const float* in_ln   = (const float*)d_in[4];
    const float* post_ln = (const float*)d_in[5];
    const float* q_w     = (const float*)d_in[6];
    const float* k_w     = (const float*)d_in[7];
    const float* v_w     = (const float*)d_in[8];
    const float* o_w     = (const float*)d_in[9];
    const float* q_nw    = (const float*)d_in[10];
    const float* k_nw    = (const float*)d_in[11];
    const float* gate_w  = (const float*)d_in[12];
    const float* gup_w   = (const float*)d_in[13];
    const float* down_w  = (const float*)d_in[14];
    float* out = (float*)d_out;

    float *qkv, *hmid, *h2;
    __nv_bfloat16 *hn_h, *hn_l, *attn_h, *attn_l, *h2_h, *h2_l, *gated_h, *gated_l;
    __nv_bfloat16 *wqkv_h, *wqkv_l, *wo_h, *wo_l, *wgu_h, *wgu_l, *wdn_h, *wdn_l;
    cudaGetSymbolAddress((void**)&qkv,  g_qkv);
    cudaGetSymbolAddress((void**)&hmid, g_hmid);
    cudaGetSymbolAddress((void**)&h2,   g_h2);
    cudaGetSymbolAddress((void**)&hn_h, g_hn_h);
    cudaGetSymbolAddress((void**)&hn_l, g_hn_l);
    cudaGetSymbolAddress((void**)&attn_h, g_attn_h);
    cudaGetSymbolAddress((void**)&attn_l, g_attn_l);
    cudaGetSymbolAddress((void**)&h2_h, g_h2_h);
    cudaGetSymbolAddress((void**)&h2_l, g_h2_l);
    cudaGetSymbolAddress((void**)&gated_h, g_gated_h);
    cudaGetSymbolAddress((void**)&gated_l, g_gated_l);
    cudaGetSymbolAddress((void**)&wqkv_h, g_wqkv_h);
    cudaGetSymbolAddress((void**)&wqkv_l, g_wqkv_l);
    cudaGetSymbolAddress((void**)&wo_h,   g_wo_h);
    cudaGetSymbolAddress((void**)&wo_l,   g_wo_l);
    cudaGetSymbolAddress((void**)&wgu_h,  g_wgu_h);
    cudaGetSymbolAddress((void**)&wgu_l,  g_wgu_l);
    cudaGetSymbolAddress((void**)&wdn_h,  g_wdn_h);
    cudaGetSymbolAddress((void**)&wdn_l,  g_wdn_l);

    cudaFuncSetAttribute(bf16x3_gemm_kernel, cudaFuncAttributeMaxDynamicSharedMemorySize, GEMM_SMEM);
    cudaFuncSetAttribute(attn_kernel, cudaFuncAttributeMaxDynamicSharedMemorySize, AT_SMEM);

    // streaming weight split (gate_up interleaved for fused SiLU)
    wsplit_qkv_kernel<<<6144, 256>>>((const float4*)q_w, (const float4*)k_w,
                                     (const float4*)v_w, (uint2*)wqkv_h, (uint2*)wqkv_l);
    wsplit_kernel<<<4096, 256>>>((const float4*)o_w,    (uint2*)wo_h,  (uint2*)wo_l,  DD * DD / 4);
    wsplit_gu_kernel<<<65536, 256>>>(gup_w, (uint2*)wgu_h, (uint2*)wgu_l);
    wsplit_kernel<<<32768, 256>>>((const float4*)down_w,(uint2*)wdn_h, (uint2*)wdn_l, NE * NF * DD / 4);

    // 1. pre-attn rmsnorm
    rmsnorm_kernel<<<TT, 256>>>(hidden, in_ln, nullptr, hn_h, hn_l, nullptr);
    // 2. fused QKV projection
    bf16x3_gemm_kernel<<<dim3(QKVW / 256, TT / 128), 512, GEMM_SMEM>>>(
        0, hn_h, hn_l, wqkv_h, wqkv_l, qkv, nullptr, QKVW, DD);
    // 3. per-head norm + rope + split
    normrope_kernel<<<dim3(TT, NQ + NKV + NKV), 128>>>(cosb, sinb, q_nw, k_nw);
    // 4. attention
    attn_kernel<<<dim3(TT / 64, NQ), 128, AT_SMEM>>>();
    // 5. O projection + residual
    bf16x3_gemm_kernel<<<dim3(DD / 256, TT / 128), 512, GEMM_SMEM>>>(
        0, attn_h, attn_l, wo_h, wo_l, hmid, hidden, DD, DD);
    // 6. post-attn rmsnorm (+ copies hmid into out as the residual init)
    rmsnorm_kernel<<<TT, 256>>>(hmid, post_ln, h2, h2_h, h2_l, out);
    // 7. routing
    zero_cnt_kernel<<<1, 32>>>();
    route_kernel<<<TT, 128>>>(gate_w);
    // 8. sparse expert GEMMs (gate_up has fused SiLU epilogue)
    bf16x3_gemm_kernel<<<dim3((2 * NF) / 256, 16, NE), 512, GEMM_SMEM>>>(
        1, h2_h, h2_l, wgu_h, wgu_l, nullptr, nullptr, 2 * NF, DD);
    bf16x3_gemm_kernel<<<dim3(DD / 256, 16, NE), 512, GEMM_SMEM>>>(
        2, gated_h, gated_l, wdn_h, wdn_l, out, nullptr, DD, NF);
}

// round 12
// speedup vs baseline: 1.0112x; 1.0112x over previous
#include <cuda_runtime.h>
#include <cuda_bf16.h>
#include <math.h>
#include <stdint.h>

#define TT   2048
#define DD   2048
#define NQ   16
#define NKV  4
#define HDIM 128
#define NE   16
#define NF   1024
#define TOPK 4

#define QKVW 3072
#define KOFF 2048
#define VOFF 2560

// ---------------- scratch ----------------
__device__ float g_qkv  [TT * QKVW];
__device__ float g_hmid [TT * DD];
__device__ float g_h2   [TT * DD];
__device__ float g_rw   [TT * TOPK];
__device__ int   g_ecnt [NE];
__device__ int   g_erows[NE * TT];

__device__ __nv_bfloat16 g_hn_h   [TT * DD];
__device__ __nv_bfloat16 g_hn_l   [TT * DD];
__device__ __nv_bfloat16 g_q_h    [TT * NQ * HDIM];
__device__ __nv_bfloat16 g_q_l    [TT * NQ * HDIM];
__device__ __nv_bfloat16 g_k_h    [TT * NKV * HDIM];
__device__ __nv_bfloat16 g_k_l    [TT * NKV * HDIM];
__device__ __nv_bfloat16 g_v_h    [TT * NKV * HDIM];
__device__ __nv_bfloat16 g_v_l    [TT * NKV * HDIM];
__device__ __nv_bfloat16 g_attn_h [TT * DD];
__device__ __nv_bfloat16 g_attn_l [TT * DD];
__device__ __nv_bfloat16 g_h2_h   [TT * DD];
__device__ __nv_bfloat16 g_h2_l   [TT * DD];
__device__ __nv_bfloat16 g_gated_h[TT * TOPK * NF];
__device__ __nv_bfloat16 g_gated_l[TT * TOPK * NF];

// split-bf16 weights in NATURAL [K][N] layout (gate_up column-interleaved)
__device__ __nv_bfloat16 g_wqkv_h[DD * QKVW];
__device__ __nv_bfloat16 g_wqkv_l[DD * QKVW];
__device__ __nv_bfloat16 g_wo_h  [DD * DD];
__device__ __nv_bfloat16 g_wo_l  [DD * DD];
__device__ __nv_bfloat16 g_wgu_h [NE * DD * (2 * NF)];
__device__ __nv_bfloat16 g_wgu_l [NE * DD * (2 * NF)];
__device__ __nv_bfloat16 g_wdn_h [NE * NF * DD];
__device__ __nv_bfloat16 g_wdn_l [NE * NF * DD];

// ================= helpers =================
__device__ __forceinline__ uint32_t smem_u32(const void* p) {
    uint32_t r;
    asm("{ .reg .u64 t; cvta.to.shared.u64 t, %1; cvt.u32.u64 %0, t; }" : "=r"(r) : "l"(p));
    return r;
}
__device__ __forceinline__ uint32_t pack2bf(__nv_bfloat16 a, __nv_bfloat16 b) {
    return (uint32_t)__bfloat16_as_ushort(a) | ((uint32_t)__bfloat16_as_ushort(b) << 16);
}
__device__ __forceinline__ void ldsm4(uint32_t* r, uint32_t a) {
    asm volatile("ldmatrix.sync.aligned.m8n8.x4.shared.b16 {%0,%1,%2,%3}, [%4];"
                 : "=r"(r[0]), "=r"(r[1]), "=r"(r[2]), "=r"(r[3]) : "r"(a));
}
__device__ __forceinline__ void ldsm4t(uint32_t* r, uint32_t a) {
    asm volatile("ldmatrix.sync.aligned.m8n8.x4.trans.shared.b16 {%0,%1,%2,%3}, [%4];"
                 : "=r"(r[0]), "=r"(r[1]), "=r"(r[2]), "=r"(r[3]) : "r"(a));
}
__device__ __forceinline__ void mma16816(float* c, const uint32_t* a, const uint32_t* b) {
    asm volatile("mma.sync.aligned.m16n8k16.row.col.f32.bf16.bf16.f32 "
                 "{%0,%1,%2,%3}, {%4,%5,%6,%7}, {%8,%9}, {%0,%1,%2,%3};"
                 : "+f"(c[0]), "+f"(c[1]), "+f"(c[2]), "+f"(c[3])
                 : "r"(a[0]), "r"(a[1]), "r"(a[2]), "r"(a[3]), "r"(b[0]), "r"(b[1]));
}
#define CP16(dst, src) \
    asm volatile("cp.async.cg.shared.global [%0], [%1], 16;" :: "r"(dst), "l"(src))
#define CP_COMMIT() asm volatile("cp.async.commit_group;" ::: "memory")
#define CP_WAIT1()  asm volatile("cp.async.wait_group 1;" ::: "memory")
#define CP_WAIT0()  asm volatile("cp.async.wait_group 0;" ::: "memory")

__device__ __forceinline__ void split_bf16(float v, __nv_bfloat16& h, __nv_bfloat16& l) {
    h = __float2bfloat16(v);
    l = __float2bfloat16(v - __bfloat162float(h));
}

// ================= streaming weight split =================
__global__ void wsplit_kernel(const float4* __restrict__ in,
                              uint2* __restrict__ oh, uint2* __restrict__ ol, int n4)
{
    int i = blockIdx.x * blockDim.x + threadIdx.x;
    if (i >= n4) return;
    float4 v = in[i];
    __nv_bfloat16 h0, l0, h1, l1, h2, l2, h3, l3;
    split_bf16(v.x, h0, l0); split_bf16(v.y, h1, l1);
    split_bf16(v.z, h2, l2); split_bf16(v.w, h3, l3);
    oh[i] = make_uint2(pack2bf(h0, h1), pack2bf(h2, h3));
    ol[i] = make_uint2(pack2bf(l0, l1), pack2bf(l2, l3));
}
__global__ void wsplit_qkv_kernel(const float4* __restrict__ q, const float4* __restrict__ k,
                                  const float4* __restrict__ v,
                                  uint2* __restrict__ oh, uint2* __restrict__ ol)
{
    int i = blockIdx.x * 256 + threadIdx.x;   // over 2048*768
    int row = i / 768, c4 = i % 768;
    float4 val;
    if (c4 < 512)      val = q[row * 512 + c4];
    else if (c4 < 640) val = k[row * 128 + (c4 - 512)];
    else               val = v[row * 128 + (c4 - 640)];
    __nv_bfloat16 h0, l0, h1, l1, h2, l2, h3, l3;
    split_bf16(val.x, h0, l0); split_bf16(val.y, h1, l1);
    split_bf16(val.z, h2, l2); split_bf16(val.w, h3, l3);
    oh[i] = make_uint2(pack2bf(h0, h1), pack2bf(h2, h3));
    ol[i] = make_uint2(pack2bf(l0, l1), pack2bf(l2, l3));
}
// gate_up with column interleave, fully vectorized:
// thread handles 4 f-values -> float4 load from gate half + float4 from up half,
// uint4 store of 8 interleaved bf16 (g0,u0,g1,u1,g2,u2,g3,u3) to oh and ol.
__global__ void wsplit_gu_kernel(const float4* __restrict__ in,   // [NE*DD][2NF/4]
                                 uint4* __restrict__ oh, uint4* __restrict__ ol)
{
    int i = blockIdx.x * 256 + threadIdx.x;       // over NE*DD*NF/4
    int per_row = NF / 4;                          // 256
    int row = i / per_row;                         // e*DD + d
    int j = i % per_row;                           // f base = 4j
    const float4* base = in + (size_t)row * (2 * NF / 4);
    float4 gv = base[j];
    float4 uv = base[NF / 4 + j];
    __nv_bfloat16 gh[4], gl[4], uh[4], ul[4];
    split_bf16(gv.x, gh[0], gl[0]); split_bf16(gv.y, gh[1], gl[1]);
    split_bf16(gv.z, gh[2], gl[2]); split_bf16(gv.w, gh[3], gl[3]);
    split_bf16(uv.x, uh[0], ul[0]); split_bf16(uv.y, uh[1], ul[1]);
    split_bf16(uv.z, uh[2], ul[2]); split_bf16(uv.w, ul[3] = __nv_bfloat16(), uh[3]), // placeholder avoided below
    split_bf16(uv.w, uh[3], ul[3]);
    oh[i] = make_uint4(pack2bf(gh[0], uh[0]), pack2bf(gh[1], uh[1]),
                       pack2bf(gh[2], uh[2]), pack2bf(gh[3], uh[3]));
    ol[i] = make_uint4(pack2bf(gl[0], ul[0]), pack2bf(gl[1], ul[1]),
                       pack2bf(gl[2], ul[2]), pack2bf(gl[3], ul[3]));
}

// ================= bf16x3 GEMM: 16 warps x (32x64), trans-B from [K][N] =================
#define KC 32
#define ARS 80
#define BRS 528
#define A_SZ (128 * ARS)
#define B_SZ (KC * BRS)
#define STG  (2 * A_SZ + 2 * B_SZ)
#define AH_O 0
#define AL_O A_SZ
#define BH_O (2 * A_SZ)
#define BL_O (2 * A_SZ + B_SZ)
#define EROFF (3 * STG)
#define GEMM_SMEM (EROFF + 512)

// mode 0: dense C = A @ B (+addsrc)
// mode 1: moe gate_up with FUSED SiLU: writes g_gated_h/l (C unused)
// mode 2: moe down: atomicAdd into C[tok] * g_rw
__global__ void __launch_bounds__(512) bf16x3_gemm_kernel(
    int mode,
    const __nv_bfloat16* __restrict__ Ah, const __nv_bfloat16* __restrict__ Al,
    const __nv_bfloat16* __restrict__ Bh, const __nv_bfloat16* __restrict__ Bl,
    float* __restrict__ C, const float* __restrict__ addsrc, int N, int K)
{
    int e  = blockIdx.z;
    int m0 = blockIdx.y * 128;
    int n0 = blockIdx.x * 256;
    int cnt = 0;
    if (mode != 0) {
        cnt = g_ecnt[e];
        if (m0 >= cnt) return;
        Bh += (size_t)e * K * N;
        Bl += (size_t)e * K * N;
    }
    extern __shared__ char sm[];
    uint32_t sb = smem_u32(sm);
    int tid = threadIdx.x, wid = tid >> 5, l = tid & 31;
    int* erows_s = (int*)(sm + EROFF);
    if (mode != 0 && tid < 128)
        erows_s[tid] = (m0 + tid < cnt) ? g_erows[e * TT + m0 + tid] : 0;
    __syncthreads();

    int arow = tid >> 2, apart = tid & 3;
    size_t aro;
    if (mode == 0)      aro = (size_t)(m0 + arow) * K;
    else if (mode == 1) aro = (size_t)(erows_s[arow] >> 2) * DD;
    else                aro = (size_t)erows_s[arow] * NF;
    const __nv_bfloat16* aph = Ah + aro + apart * 8;
    const __nv_bfloat16* apl = Al + aro + apart * 8;
    uint32_t a_dst = (uint32_t)(arow * ARS + apart * 16);

    int brow = tid >> 4, bpart = tid & 15;
    size_t bo = (size_t)brow * N + n0 + bpart * 16;
    uint32_t b_dst = (uint32_t)(brow * BRS + bpart * 32);

    int NC = K / KC;

    int wm = wid >> 2, wn = wid & 3;
    int a_r = (l & 7) + ((l >> 3) & 1) * 8;
    int a_c = (l >> 4) * 8;
    uint32_t a_base = (uint32_t)((wm * 32 + a_r) * ARS + a_c * 2);
    uint32_t b_base = (uint32_t)(a_r * BRS + (wn * 64 + a_c) * 2);

    float acc[2][8][4];
#pragma unroll
    for (int mi = 0; mi < 2; mi++)
#pragma unroll
        for (int ni = 0; ni < 8; ni++)
#pragma unroll
            for (int j = 0; j < 4; j++) acc[mi][ni][j] = 0.f;

#pragma unroll
    for (int p = 0; p < 2; p++) {
        if (p < NC) {
            uint32_t st = sb + p * STG;
            int k0 = p * KC;
            CP16(st + AH_O + a_dst, aph + k0);
            CP16(st + AL_O + a_dst, apl + k0);
            const __nv_bfloat16* bsh = Bh + bo + (size_t)k0 * N;
            const __nv_bfloat16* bsl = Bl + bo + (size_t)k0 * N;
            CP16(st + BH_O + b_dst,      bsh);
            CP16(st + BH_O + b_dst + 16, bsh + 8);
            CP16(st + BL_O + b_dst,      bsl);
            CP16(st + BL_O + b_dst + 16, bsl + 8);
        }
        CP_COMMIT();
    }

    for (int c = 0; c < NC; c++) {
        if (c + 1 < NC) CP_WAIT1(); else CP_WAIT0();
        __syncthreads();
        if (c + 2 < NC) {
            int n2 = c + 2;
            uint32_t st = sb + (n2 % 3) * STG;
            int k0 = n2 * KC;
            CP16(st + AH_O + a_dst, aph + k0);
            CP16(st + AL_O + a_dst, apl + k0);
            const __nv_bfloat16* bsh = Bh + bo + (size_t)k0 * N;
            const __nv_bfloat16* bsl = Bl + bo + (size_t)k0 * N;
            CP16(st + BH_O + b_dst,      bsh);
            CP16(st + BH_O + b_dst + 16, bsh + 8);
            CP16(st + BL_O + b_dst,      bsl);
            CP16(st + BL_O + b_dst + 16, bsl + 8);
        }
        CP_COMMIT();

        uint32_t st = sb + (c % 3) * STG;
#pragma unroll
        for (int kk = 0; kk < 2; kk++) {
            uint32_t bh[4][4], bl[4][4];
#pragma unroll
            for (int q = 0; q < 4; q++)
                ldsm4t(bh[q], st + BH_O + b_base + kk * (16 * BRS) + q * 32);
#pragma unroll
            for (int q = 0; q < 4; q++)
                ldsm4t(bl[q], st + BL_O + b_base + kk * (16 * BRS) + q * 32);
#pragma unroll
            for (int mi = 0; mi < 2; mi++) {
                uint32_t ah[4], al[4];
                ldsm4(ah, st + AH_O + a_base + mi * (16 * ARS) + kk * 32);
                ldsm4(al, st + AL_O + a_base + mi * (16 * ARS) + kk * 32);
#pragma unroll
                for (int q = 0; q < 4; q++) {
                    mma16816(acc[mi][2 * q],     ah, &bh[q][0]);
                    mma16816(acc[mi][2 * q + 1], ah, &bh[q][2]);
                }
#pragma unroll
                for (int q = 0; q < 4; q++) {
                    mma16816(acc[mi][2 * q],     ah, &bl[q][0]);
                    mma16816(acc[mi][2 * q + 1], ah, &bl[q][2]);
                }
#pragma unroll
                for (int q = 0; q < 4; q++) {
                    mma16816(acc[mi][2 * q],     al, &bh[q][0]);
                    mma16816(acc[mi][2 * q + 1], al, &bh[q][2]);
                }
            }
        }
    }

    // epilogue
    int g = l >> 2, tig = l & 3;
#pragma unroll
    for (int mi = 0; mi < 2; mi++) {
        int r0 = wm * 32 + mi * 16 + g;
        int r1 = r0 + 8;
        bool v0 = true, v1 = true;
        size_t ro0 = 0, ro1 = 0;
        int rowid0 = 0, rowid1 = 0;
        float w0 = 0.f, w1 = 0.f;
        if (mode == 0) {
            ro0 = (size_t)(m0 + r0) * N;
            ro1 = (size_t)(m0 + r1) * N;
        } else {
            v0 = (m0 + r0) < cnt;
            v1 = (m0 + r1) < cnt;
            rowid0 = erows_s[r0]; rowid1 = erows_s[r1];
            if (mode == 2) {
                ro0 = (size_t)(rowid0 >> 2) * DD;
                ro1 = (size_t)(rowid1 >> 2) * DD;
                if (v0) w0 = g_rw[rowid0];
                if (v1) w1 = g_rw[rowid1];
            }
        }
#pragma unroll
        for (int ni = 0; ni < 8; ni++) {
            int cc = n0 + wn * 64 + ni * 8 + tig * 2;
            float* a = acc[mi][ni];
            if (mode == 0) {
                if (addsrc) {
                    float2 s0 = *(const float2*)(addsrc + ro0 + cc);
                    float2 s1 = *(const float2*)(addsrc + ro1 + cc);
                    *(float2*)(C + ro0 + cc) = make_float2(a[0] + s0.x, a[1] + s0.y);
                    *(float2*)(C + ro1 + cc) = make_float2(a[2] + s1.x, a[3] + s1.y);
                } else {
                    *(float2*)(C + ro0 + cc) = make_float2(a[0], a[1]);
                    *(float2*)(C + ro1 + cc) = make_float2(a[2], a[3]);
                }
            } else if (mode == 1) {
                int f = cc >> 1;
                if (v0) {
                    float gt = a[0];
                    float gated = a[1] * (gt / (1.f + __expf(-gt)));
                    __nv_bfloat16 h, lo;
                    split_bf16(gated, h, lo);
                    g_gated_h[(size_t)rowid0 * NF + f] = h;
                    g_gated_l[(size_t)rowid0 * NF + f] = lo;
                }
                if (v1) {
                    float gt = a[2];
                    float gated = a[3] * (gt / (1.f + __expf(-gt)));
                    __nv_bfloat16 h, lo;
                    split_bf16(gated, h, lo);
                    g_gated_h[(size_t)rowid1 * NF + f] = h;
                    g_gated_l[(size_t)rowid1 * NF + f] = lo;
                }
            } else {
                if (v0) { atomicAdd(C + ro0 + cc, w0 * a[0]); atomicAdd(C + ro0 + cc + 1, w0 * a[1]); }
                if (v1) { atomicAdd(C + ro1 + cc, w1 * a[2]); atomicAdd(C + ro1 + cc + 1, w1 * a[3]); }
            }
        }
    }
}

// ================= RMSNorm (split-bf16 + optional fp32 out + optional passthrough copy) =================
__global__ void rmsnorm_kernel(const float* __restrict__ x,
                               const float* __restrict__ w,
                               float* __restrict__ ofp,
                               __nv_bfloat16* __restrict__ oh,
                               __nv_bfloat16* __restrict__ ol,
                               float* __restrict__ ocopy)
{
    int t = blockIdx.x;
    const float4* xr = (const float4*)(x + (size_t)t * DD);
    const float4* wr = (const float4*)w;
    int tid = threadIdx.x;
    float4 v0 = xr[tid], v1 = xr[tid + 256];
    if (ocopy) {
        float4* orow = (float4*)(ocopy + (size_t)t * DD);
        orow[tid] = v0; orow[tid + 256] = v1;
    }
    float ss = v0.x*v0.x + v0.y*v0.y + v0.z*v0.z + v0.w*v0.w
             + v1.x*v1.x + v1.y*v1.y + v1.z*v1.z + v1.w*v1.w;
#pragma unroll
    for (int o = 16; o; o >>= 1) ss += __shfl_xor_sync(0xffffffffu, ss, o);
    __shared__ float red[8];
    if ((tid & 31) == 0) red[tid >> 5] = ss;
    __syncthreads();
    float tot = red[0]+red[1]+red[2]+red[3]+red[4]+red[5]+red[6]+red[7];
    float r = rsqrtf(tot / (float)DD + 1e-6f);
    float4 w0 = wr[tid], w1 = wr[tid + 256];
    float4 o0, o1;
    o0.x = v0.x*r*w0.x; o0.y = v0.y*r*w0.y; o0.z = v0.z*r*w0.z; o0.w = v0.w*r*w0.w;
    o1.x = v1.x*r*w1.x; o1.y = v1.y*r*w1.y; o1.z = v1.z*r*w1.z; o1.w = v1.w*r*w1.w;
    if (ofp) {
        float4* orow = (float4*)(ofp + (size_t)t * DD);
        orow[tid] = o0; orow[tid + 256] = o1;
    }
    __nv_bfloat16 h[8], lo[8];
    split_bf16(o0.x, h[0], lo[0]); split_bf16(o0.y, h[1], lo[1]);
    split_bf16(o0.z, h[2], lo[2]); split_bf16(o0.w, h[3], lo[3]);
    split_bf16(o1.x, h[4], lo[4]); split_bf16(o1.y, h[5], lo[5]);
    split_bf16(o1.z, h[6], lo[6]); split_bf16(o1.w, h[7], lo[7]);
    uint2* ohr = (uint2*)(oh + (size_t)t * DD);
    uint2* olr = (uint2*)(ol + (size_t)t * DD);
    ohr[tid]       = make_uint2(pack2bf(h[0], h[1]),  pack2bf(h[2], h[3]));
    ohr[tid + 256] = make_uint2(pack2bf(h[4], h[5]),  pack2bf(h[6], h[7]));
    olr[tid]       = make_uint2(pack2bf(lo[0], lo[1]), pack2bf(lo[2], lo[3]));
    olr[tid + 256] = make_uint2(pack2bf(lo[4], lo[5]), pack2bf(lo[6], lo[7]));
}

// ================= per-head RMSNorm + RoPE + split =================
__global__ void normrope_kernel(const float* __restrict__ cosb,
                                const float* __restrict__ sinb,
                                const float* __restrict__ qnw,
                                const float* __restrict__ knw)
{
    int t = blockIdx.x;
    int head = blockIdx.y;      // 0..15 q, 16..19 k, 20..23 v
    int h = threadIdx.x;
    if (head >= 20) {
        int kvh = head - 20;
        float v = g_qkv[(size_t)t * QKVW + VOFF + kvh * HDIM + h];
        __nv_bfloat16 hh, ll;
        split_bf16(v, hh, ll);
        size_t o = ((size_t)t * NKV + kvh) * HDIM + h;
        g_v_h[o] = hh; g_v_l[o] = ll;
        return;
    }
    const float* src;
    const float* nw;
    if (head < NQ) { src = g_qkv + (size_t)t * QKVW + head * HDIM;               nw = qnw; }
    else           { src = g_qkv + (size_t)t * QKVW + KOFF + (head - NQ) * HDIM; nw = knw; }
    float v = src[h];
    float ss = v * v;
#pragma unroll
    for (int o = 16; o; o >>= 1) ss += __shfl_xor_sync(0xffffffffu, ss, o);
    __shared__ float red[4];
    __shared__ float xs[128];
    if ((h & 31) == 0) red[h >> 5] = ss;
    __syncthreads();
    float tot = red[0] + red[1] + red[2] + red[3];
    float xn = v * rsqrtf(tot / (float)HDIM + 1e-6f) * nw[h];
    xs[h] = xn;
    __syncthreads();
    float c = cosb[(size_t)t * HDIM + h];
    float s = sinb[(size_t)t * HDIM + h];
    float other = (h < 64) ? xs[h + 64] : xs[h - 64];
    float outv = (h < 64) ? (xn * c - other * s) : (xn * c + other * s);
    __nv_bfloat16 hh, ll;
    split_bf16(outv, hh, ll);
    if (head < NQ) {
        size_t o = ((size_t)t * NQ + head) * HDIM + h;
        g_q_h[o] = hh; g_q_l[o] = ll;
    } else {
        size_t o = ((size_t)t * NKV + (head - NQ)) * HDIM + h;
        g_k_h[o] = hh; g_k_l[o] = ll;
    }
}

// ================= flash attention, bf16x3 HMMA (LPT: heavy CTAs first) =================
#define AT_RST  272
#define AT_TILE (64 * AT_RST)
#define AT_QH 0
#define AT_QL (1 * AT_TILE)
#define AT_KH (2 * AT_TILE)
#define AT_KL (3 * AT_TILE)
#define AT_VH (4 * AT_TILE)
#define AT_VL (5 * AT_TILE)
#define AT_SMEM (6 * AT_TILE)

__device__ __forceinline__ void attn_issue_kv(uint32_t sb, int j0, int kvh,
                                              int srow, int spart)
{
    size_t base = ((size_t)(j0 + srow) * NKV + kvh) * HDIM + spart * 64;
    uint32_t d = (uint32_t)(srow * AT_RST + spart * 128);
#pragma unroll
    for (int i = 0; i < 8; i++) {
        CP16(sb + AT_KH + d + i * 16, g_k_h + base + i * 8);
        CP16(sb + AT_KL + d + i * 16, g_k_l + base + i * 8);
        CP16(sb + AT_VH + d + i * 16, g_v_h + base + i * 8);
        CP16(sb + AT_VL + d + i * 16, g_v_l + base + i * 8);
    }
}

__global__ void __launch_bounds__(128) attn_kernel()
{
    extern __shared__ char sm[];
    uint32_t sb = smem_u32(sm);
    int bx = gridDim.x - 1 - blockIdx.x;     // reversed: heaviest (most j-tiles) first
    int m0 = bx * 64;
    int head = blockIdx.y;
    int kvh = head >> 2;
    int tid = threadIdx.x, wid = tid >> 5, l = tid & 31;
    const float scale = 0.08838834764831843f;

    int srow = tid >> 1, spart = tid & 1;
    {
        size_t qb = ((size_t)(m0 + srow) * NQ + head) * HDIM + spart * 64;
        uint32_t d = (uint32_t)(srow * AT_RST + spart * 128);
#pragma unroll
        for (int i = 0; i < 8; i++) {
            CP16(sb + AT_QH + d + i * 16, g_q_h + qb + i * 8);
            CP16(sb + AT_QL + d + i * 16, g_q_l + qb + i * 8);
        }
    }
    attn_issue_kv(sb, 0, kvh, srow, spart);
    CP_COMMIT();

    int a_r = (l & 7) + ((l >> 3) & 1) * 8;
    int a_c = (l >> 4) * 8;
    int b_r = (l & 7) + (l >> 4) * 8;
    int b_c = ((l >> 3) & 1) * 8;

    float o[16][4];
#pragma unroll
    for (int nd = 0; nd < 16; nd++)
#pragma unroll
        for (int j = 0; j < 4; j++) o[nd][j] = 0.f;
    float m_i0 = -1e30f, m_i1 = -1e30f, l0 = 0.f, l1 = 0.f;

    int njt = bx + 1;
    for (int jt = 0; jt < njt; jt++) {
        CP_WAIT0();
        __syncthreads();

        float s[8][4];
#pragma unroll
        for (int ni = 0; ni < 8; ni++)
#pragma unroll
            for (int j = 0; j < 4; j++) s[ni][j] = 0.f;
#pragma unroll
        for (int ks = 0; ks < 8; ks++) {
            uint32_t qh4[4], ql4[4];
            uint32_t qa = sb + (uint32_t)((wid * 16 + a_r) * AT_RST + (ks * 16 + a_c) * 2);
            ldsm4(qh4, qa + AT_QH);
            ldsm4(ql4, qa + AT_QL);
            uint32_t kh[4][4], kl[4][4];
#pragma unroll
            for (int q2 = 0; q2 < 4; q2++) {
                uint32_t ka = sb + (uint32_t)((q2 * 16 + b_r) * AT_RST + (ks * 16 + b_c) * 2);
                ldsm4(kh[q2], ka + AT_KH);
                ldsm4(kl[q2], ka + AT_KL);
            }
#pragma unroll
            for (int q2 = 0; q2 < 4; q2++) {
                mma16816(s[2 * q2],     qh4, &kh[q2][0]);
                mma16816(s[2 * q2 + 1], qh4, &kh[q2][2]);
            }
#pragma unroll
            for (int q2 = 0; q2 < 4; q2++) {
                mma16816(s[2 * q2],     qh4, &kl[q2][0]);
                mma16816(s[2 * q2 + 1], qh4, &kl[q2][2]);
            }
#pragma unroll
            for (int q2 = 0; q2 < 4; q2++) {
                mma16816(s[2 * q2],     ql4, &kh[q2][0]);
                mma16816(s[2 * q2 + 1], ql4, &kh[q2][2]);
            }
        }
#pragma unroll
        for (int ni = 0; ni < 8; ni++)
#pragma unroll
            for (int j = 0; j < 4; j++) s[ni][j] *= scale;
        if (jt == njt - 1) {
            int rA = wid * 16 + (l >> 2), rB = rA + 8;
#pragma unroll
            for (int ni = 0; ni < 8; ni++) {
                int c0 = ni * 8 + 2 * (l & 3), c1 = c0 + 1;
                if (c0 > rA) s[ni][0] = -1e30f;
                if (c1 > rA) s[ni][1] = -1e30f;
                if (c0 > rB) s[ni][2] = -1e30f;
                if (c1 > rB) s[ni][3] = -1e30f;
            }
        }
        float mt0 = -1e30f, mt1 = -1e30f;
#pragma unroll
        for (int ni = 0; ni < 8; ni++) {
            mt0 = fmaxf(mt0, fmaxf(s[ni][0], s[ni][1]));
            mt1 = fmaxf(mt1, fmaxf(s[ni][2], s[ni][3]));
        }
        mt0 = fmaxf(mt0, __shfl_xor_sync(0xffffffffu, mt0, 1));
        mt0 = fmaxf(mt0, __shfl_xor_sync(0xffffffffu, mt0, 2));
        mt1 = fmaxf(mt1, __shfl_xor_sync(0xffffffffu, mt1, 1));
        mt1 = fmaxf(mt1, __shfl_xor_sync(0xffffffffu, mt1, 2));
        float mn0 = fmaxf(m_i0, mt0), mn1 = fmaxf(m_i1, mt1);
        float c0 = __expf(m_i0 - mn0), c1 = __expf(m_i1 - mn1);
        l0 *= c0; l1 *= c1;
#pragma unroll
        for (int nd = 0; nd < 16; nd++) {
            o[nd][0] *= c0; o[nd][1] *= c0; o[nd][2] *= c1; o[nd][3] *= c1;
        }
        m_i0 = mn0; m_i1 = mn1;
        float rs0 = 0.f, rs1 = 0.f;
        uint32_t pha[16], pla[16];
#pragma unroll
        for (int ni = 0; ni < 8; ni++) {
            float p0 = __expf(s[ni][0] - mn0), p1 = __expf(s[ni][1] - mn0);
            float p2 = __expf(s[ni][2] - mn1), p3 = __expf(s[ni][3] - mn1);
            rs0 += p0 + p1; rs1 += p2 + p3;
            __nv_bfloat16 h0, l0b, h1, l1b, h2, l2b, h3, l3b;
            split_bf16(p0, h0, l0b); split_bf16(p1, h1, l1b);
            split_bf16(p2, h2, l2b); split_bf16(p3, h3, l3b);
            pha[2 * ni]     = pack2bf(h0, h1);
            pha[2 * ni + 1] = pack2bf(h2, h3);
            pla[2 * ni]     = pack2bf(l0b, l1b);
            pla[2 * ni + 1] = pack2bf(l2b, l3b);
        }
        rs0 += __shfl_xor_sync(0xffffffffu, rs0, 1);
        rs0 += __shfl_xor_sync(0xffffffffu, rs0, 2);
        rs1 += __shfl_xor_sync(0xffffffffu, rs1, 1);
        rs1 += __shfl_xor_sync(0xffffffffu, rs1, 2);
        l0 += rs0; l1 += rs1;

#pragma unroll
        for (int ks = 0; ks < 4; ks++) {
            const uint32_t* ph = &pha[4 * ks];
            const uint32_t* pl = &pla[4 * ks];
#pragma unroll
            for (int dp = 0; dp < 4; dp++) {
                uint32_t vh[2][4], vl[2][4];
#pragma unroll
                for (int u = 0; u < 2; u++) {
                    uint32_t va = sb + (uint32_t)((ks * 16 + a_r) * AT_RST +
                                                  ((2 * dp + u) * 16 + a_c) * 2);
                    ldsm4t(vh[u], va + AT_VH);
                    ldsm4t(vl[u], va + AT_VL);
                }
                mma16816(o[4 * dp],     ph, &vh[0][0]);
                mma16816(o[4 * dp + 1], ph, &vh[0][2]);
                mma16816(o[4 * dp + 2], ph, &vh[1][0]);
                mma16816(o[4 * dp + 3], ph, &vh[1][2]);
                mma16816(o[4 * dp],     pl, &vh[0][0]);
                mma16816(o[4 * dp + 1], pl, &vh[0][2]);
                mma16816(o[4 * dp + 2], pl, &vh[1][0]);
                mma16816(o[4 * dp + 3], pl, &vh[1][2]);
                mma16816(o[4 * dp],     ph, &vl[0][0]);
                mma16816(o[4 * dp + 1], ph, &vl[0][2]);
                mma16816(o[4 * dp + 2], ph, &vl[1][0]);
                mma16816(o[4 * dp + 3], ph, &vl[1][2]);
            }
        }
        __syncthreads();
        if (jt + 1 < njt) attn_issue_kv(sb, (jt + 1) * 64, kvh, srow, spart);
        CP_COMMIT();
    }

    float inv0 = 1.f / l0, inv1 = 1.f / l1;
    int rA = m0 + wid * 16 + (l >> 2);
    int rB = rA + 8;
#pragma unroll
    for (int nd = 0; nd < 16; nd++) {
        int d = nd * 8 + 2 * (l & 3);
        float v0 = o[nd][0] * inv0, v1 = o[nd][1] * inv0;
        float v2 = o[nd][2] * inv1, v3 = o[nd][3] * inv1;
        __nv_bfloat16 h0, lo0, h1, lo1, h2, lo2, h3, lo3;
        split_bf16(v0, h0, lo0); split_bf16(v1, h1, lo1);
        split_bf16(v2, h2, lo2); split_bf16(v3, h3, lo3);
        size_t oA = (size_t)rA * DD + head * HDIM + d;
        size_t oB = (size_t)rB * DD + head * HDIM + d;
        *(uint32_t*)(g_attn_h + oA) = pack2bf(h0, h1);
        *(uint32_t*)(g_attn_l + oA) = pack2bf(lo0, lo1);
        *(uint32_t*)(g_attn_h + oB) = pack2bf(h2, h3);
        *(uint32_t*)(g_attn_l + oB) = pack2bf(lo2, lo3);
    }
}

// ================= routing =================
__global__ void zero_cnt_kernel() { if (threadIdx.x < NE) g_ecnt[threadIdx.x] = 0; }

__global__ void route_kernel(const float* __restrict__ gate_w)
{
    int t = blockIdx.x;
    int tid = threadIdx.x;
    const float* x = g_h2 + (size_t)t * DD;
    float acc[NE];
#pragma unroll
    for (int e = 0; e < NE; e++) acc[e] = 0.f;
    for (int d = tid; d < DD; d += 128) {
        float xv = x[d];
        const float* gw = gate_w + (size_t)d * NE;
#pragma unroll
        for (int e = 0; e < NE; e++) acc[e] += xv * gw[e];
    }
    __shared__ float s[NE * 128];
#pragma unroll
    for (int e = 0; e < NE; e++) s[e * 128 + tid] = acc[e];
    __syncthreads();
    __shared__ float logits[NE];
    if (tid < NE) {
        float sum = 0.f;
        for (int i = 0; i < 128; i++) sum += s[tid * 128 + i];
        logits[tid] = sum;
    }
    __syncthreads();
    if (tid == 0) {
        float mx = -1e30f;
        for (int e = 0; e < NE; e++) mx = fmaxf(mx, logits[e]);
        float p[NE], Z = 0.f;
        for (int e = 0; e < NE; e++) { p[e] = expf(logits[e] - mx); Z += p[e]; }
        for (int e = 0; e < NE; e++) p[e] /= Z;
        int idx[TOPK]; float val[TOPK]; bool used[NE] = {};
        float wsum = 0.f;
        for (int k = 0; k < TOPK; k++) {
            int best = -1; float bv = -1.f;
            for (int e = 0; e < NE; e++)
                if (!used[e] && p[e] > bv) { bv = p[e]; best = e; }
            used[best] = true; idx[k] = best; val[k] = bv; wsum += bv;
        }
        for (int k = 0; k < TOPK; k++) {
            int rowid = t * TOPK + k;
            g_rw[rowid] = val[k] / wsum;
            int e = idx[k];
            int pos = atomicAdd(&g_ecnt[e], 1);
            g_erows[e * TT + pos] = rowid;
        }
    }
}

// ================= launch =================
extern "C" void kernel_launch(void* const* d_in, const int* in_sizes, int n_in,
                              void* d_out, int out_size)
{
    const float* hidden  = (const float*)d_in[0];
    const float* cosb    = (const float*)d_in[1];
    const float* sinb    = (const float*)d_in[2];
    const float* in_ln   = (const float*)d_in[4];
    const float* post_ln = (const float*)d_in[5];
    const float* q_w     = (const float*)d_in[6];
    const float* k_w     = (const float*)d_in[7];
    const float* v_w     = (const float*)d_in[8];
    const float* o_w     = (const float*)d_in[9];
    const float* q_nw    = (const float*)d_in[10];
    const float* k_nw    = (const float*)d_in[11];
    const float* gate_w  = (const float*)d_in[12];
    const float* gup_w   = (const float*)d_in[13];
    const float* down_w  = (const float*)d_in[14];
    float* out = (float*)d_out;

    float *qkv, *hmid, *h2;
    __nv_bfloat16 *hn_h, *hn_l, *attn_h, *attn_l, *h2_h, *h2_l, *gated_h, *gated_l;
    __nv_bfloat16 *wqkv_h, *wqkv_l, *wo_h, *wo_l, *wgu_h, *wgu_l, *wdn_h, *wdn_l;
    cudaGetSymbolAddress((void**)&qkv,  g_qkv);
    cudaGetSymbolAddress((void**)&hmid, g_hmid);
    cudaGetSymbolAddress((void**)&h2,   g_h2);
    cudaGetSymbolAddress((void**)&hn_h, g_hn_h);
    cudaGetSymbolAddress((void**)&hn_l, g_hn_l);
    cudaGetSymbolAddress((void**)&attn_h, g_attn_h);
    cudaGetSymbolAddress((void**)&attn_l, g_attn_l);
    cudaGetSymbolAddress((void**)&h2_h, g_h2_h);
    cudaGetSymbolAddress((void**)&h2_l, g_h2_l);
    cudaGetSymbolAddress((void**)&gated_h, g_gated_h);
    cudaGetSymbolAddress((void**)&gated_l, g_gated_l);
    cudaGetSymbolAddress((void**)&wqkv_h, g_wqkv_h);
    cudaGetSymbolAddress((void**)&wqkv_l, g_wqkv_l);
    cudaGetSymbolAddress((void**)&wo_h,   g_wo_h);
    cudaGetSymbolAddress((void**)&wo_l,   g_wo_l);
    cudaGetSymbolAddress((void**)&wgu_h,  g_wgu_h);
    cudaGetSymbolAddress((void**)&wgu_l,  g_wgu_l);
    cudaGetSymbolAddress((void**)&wdn_h,  g_wdn_h);
    cudaGetSymbolAddress((void**)&wdn_l,  g_wdn_l);

    cudaFuncSetAttribute(bf16x3_gemm_kernel, cudaFuncAttributeMaxDynamicSharedMemorySize, GEMM_SMEM);
    cudaFuncSetAttribute(attn_kernel, cudaFuncAttributeMaxDynamicSharedMemorySize, AT_SMEM);

    // streaming weight split (gate_up interleaved for fused SiLU; fully vectorized)
    wsplit_qkv_kernel<<<6144, 256>>>((const float4*)q_w, (const float4*)k_w,
                                     (const float4*)v_w, (uint2*)wqkv_h, (uint2*)wqkv_l);
    wsplit_kernel<<<4096, 256>>>((const float4*)o_w,    (uint2*)wo_h,  (uint2*)wo_l,  DD * DD / 4);
    wsplit_gu_kernel<<<32768, 256>>>((const float4*)gup_w, (uint4*)wgu_h, (uint4*)wgu_l);
    wsplit_kernel<<<32768, 256>>>((const float4*)down_w,(uint2*)wdn_h, (uint2*)wdn_l, NE * NF * DD / 4);

    // 1. pre-attn rmsnorm
    rmsnorm_kernel<<<TT, 256>>>(hidden, in_ln, nullptr, hn_h, hn_l, nullptr);
    // 2. fused QKV projection
    bf16x3_gemm_kernel<<<dim3(QKVW / 256, TT / 128), 512, GEMM_SMEM>>>(
        0, hn_h, hn_l, wqkv_h, wqkv_l, qkv, nullptr, QKVW, DD);
    // 3. per-head norm + rope + split
    normrope_kernel<<<dim3(TT, NQ + NKV + NKV), 128>>>(cosb, sinb, q_nw, k_nw);
    // 4. attention (heavy CTAs first)
    attn_kernel<<<dim3(TT / 64, NQ), 128, AT_SMEM>>>();
    // 5. O projection + residual
    bf16x3_gemm_kernel<<<dim3(DD / 256, TT / 128), 512, GEMM_SMEM>>>(
        0, attn_h, attn_l, wo_h, wo_l, hmid, hidden, DD, DD);
    // 6. post-attn rmsnorm (+ copies hmid into out as the residual init)
    rmsnorm_kernel<<<TT, 256>>>(hmid, post_ln, h2, h2_h, h2_l, out);
    // 7. routing
    zero_cnt_kernel<<<1, 32>>>();
    route_kernel<<<TT, 128>>>(gate_w);
    // 8. sparse expert GEMMs (gate_up has fused SiLU epilogue)
    bf16x3_gemm_kernel<<<dim3((2 * NF) / 256, 16, NE), 512, GEMM_SMEM>>>(
        1, h2_h, h2_l, wgu_h, wgu_l, nullptr, nullptr, 2 * NF, DD);
    bf16x3_gemm_kernel<<<dim3(DD / 256, 16, NE), 512, GEMM_SMEM>>>(
        2, gated_h, gated_l, wdn_h, wdn_l, out, nullptr, DD, NF);
}

// round 13
// speedup vs baseline: 1.0400x; 1.0285x over previous
#include <cuda_runtime.h>
#include <cuda_bf16.h>
#include <math.h>
#include <stdint.h>

#define TT   2048
#define DD   2048
#define NQ   16
#define NKV  4
#define HDIM 128
#define NE   16
#define NF   1024
#define TOPK 4

#define QKVW 3072
#define KOFF 2048
#define VOFF 2560

// ---------------- scratch ----------------
__device__ float g_qkv  [TT * QKVW];
__device__ float g_hmid [TT * DD];
__device__ float g_h2   [TT * DD];
__device__ float g_gu   [TT * TOPK * 2 * NF];
__device__ float g_rw   [TT * TOPK];
__device__ int   g_ecnt [NE];
__device__ int   g_erows[NE * TT];

__device__ __nv_bfloat16 g_hn_h   [TT * DD];
__device__ __nv_bfloat16 g_hn_l   [TT * DD];
__device__ __nv_bfloat16 g_q_h    [TT * NQ * HDIM];
__device__ __nv_bfloat16 g_q_l    [TT * NQ * HDIM];
__device__ __nv_bfloat16 g_k_h    [TT * NKV * HDIM];
__device__ __nv_bfloat16 g_k_l    [TT * NKV * HDIM];
__device__ __nv_bfloat16 g_v_h    [TT * NKV * HDIM];
__device__ __nv_bfloat16 g_v_l    [TT * NKV * HDIM];
__device__ __nv_bfloat16 g_attn_h [TT * DD];
__device__ __nv_bfloat16 g_attn_l [TT * DD];
__device__ __nv_bfloat16 g_h2_h   [TT * DD];
__device__ __nv_bfloat16 g_h2_l   [TT * DD];
__device__ __nv_bfloat16 g_gated_h[TT * TOPK * NF];
__device__ __nv_bfloat16 g_gated_l[TT * TOPK * NF];

// split-bf16 weights in NATURAL [K][N] layout
__device__ __nv_bfloat16 g_wqkv_h[DD * QKVW];
__device__ __nv_bfloat16 g_wqkv_l[DD * QKVW];
__device__ __nv_bfloat16 g_wo_h  [DD * DD];
__device__ __nv_bfloat16 g_wo_l  [DD * DD];
__device__ __nv_bfloat16 g_wgu_h [NE * DD * (2 * NF)];
__device__ __nv_bfloat16 g_wgu_l [NE * DD * (2 * NF)];
__device__ __nv_bfloat16 g_wdn_h [NE * NF * DD];
__device__ __nv_bfloat16 g_wdn_l [NE * NF * DD];

// ================= helpers =================
__device__ __forceinline__ uint32_t smem_u32(const void* p) {
    uint32_t r;
    asm("{ .reg .u64 t; cvta.to.shared.u64 t, %1; cvt.u32.u64 %0, t; }" : "=r"(r) : "l"(p));
    return r;
}
__device__ __forceinline__ uint32_t pack2bf(__nv_bfloat16 a, __nv_bfloat16 b) {
    return (uint32_t)__bfloat16_as_ushort(a) | ((uint32_t)__bfloat16_as_ushort(b) << 16);
}
__device__ __forceinline__ void ldsm4(uint32_t* r, uint32_t a) {
    asm volatile("ldmatrix.sync.aligned.m8n8.x4.shared.b16 {%0,%1,%2,%3}, [%4];"
                 : "=r"(r[0]), "=r"(r[1]), "=r"(r[2]), "=r"(r[3]) : "r"(a));
}
__device__ __forceinline__ void ldsm4t(uint32_t* r, uint32_t a) {
    asm volatile("ldmatrix.sync.aligned.m8n8.x4.trans.shared.b16 {%0,%1,%2,%3}, [%4];"
                 : "=r"(r[0]), "=r"(r[1]), "=r"(r[2]), "=r"(r[3]) : "r"(a));
}
__device__ __forceinline__ void mma16816(float* c, const uint32_t* a, const uint32_t* b) {
    asm volatile("mma.sync.aligned.m16n8k16.row.col.f32.bf16.bf16.f32 "
                 "{%0,%1,%2,%3}, {%4,%5,%6,%7}, {%8,%9}, {%0,%1,%2,%3};"
                 : "+f"(c[0]), "+f"(c[1]), "+f"(c[2]), "+f"(c[3])
                 : "r"(a[0]), "r"(a[1]), "r"(a[2]), "r"(a[3]), "r"(b[0]), "r"(b[1]));
}
#define CP16(dst, src) \
    asm volatile("cp.async.cg.shared.global [%0], [%1], 16;" :: "r"(dst), "l"(src))
#define CP_COMMIT() asm volatile("cp.async.commit_group;" ::: "memory")
#define CP_WAIT1()  asm volatile("cp.async.wait_group 1;" ::: "memory")
#define CP_WAIT0()  asm volatile("cp.async.wait_group 0;" ::: "memory")

__device__ __forceinline__ void split_bf16(float v, __nv_bfloat16& h, __nv_bfloat16& l) {
    h = __float2bfloat16(v);
    l = __float2bfloat16(v - __bfloat162float(h));
}

// ================= streaming weight split =================
__global__ void wsplit_kernel(const float4* __restrict__ in,
                              uint2* __restrict__ oh, uint2* __restrict__ ol, int n4)
{
    int i = blockIdx.x * blockDim.x + threadIdx.x;
    if (i >= n4) return;
    float4 v = in[i];
    __nv_bfloat16 h0, l0, h1, l1, h2, l2, h3, l3;
    split_bf16(v.x, h0, l0); split_bf16(v.y, h1, l1);
    split_bf16(v.z, h2, l2); split_bf16(v.w, h3, l3);
    oh[i] = make_uint2(pack2bf(h0, h1), pack2bf(h2, h3));
    ol[i] = make_uint2(pack2bf(l0, l1), pack2bf(l2, l3));
}
__global__ void wsplit_qkv_kernel(const float4* __restrict__ q, const float4* __restrict__ k,
                                  const float4* __restrict__ v,
                                  uint2* __restrict__ oh, uint2* __restrict__ ol)
{
    int i = blockIdx.x * 256 + threadIdx.x;   // over 2048*768
    int row = i / 768, c4 = i % 768;
    float4 val;
    if (c4 < 512)      val = q[row * 512 + c4];
    else if (c4 < 640) val = k[row * 128 + (c4 - 512)];
    else               val = v[row * 128 + (c4 - 640)];
    __nv_bfloat16 h0, l0, h1, l1, h2, l2, h3, l3;
    split_bf16(val.x, h0, l0); split_bf16(val.y, h1, l1);
    split_bf16(val.z, h2, l2); split_bf16(val.w, h3, l3);
    oh[i] = make_uint2(pack2bf(h0, h1), pack2bf(h2, h3));
    ol[i] = make_uint2(pack2bf(l0, l1), pack2bf(l2, l3));
}

// ================= bf16x3 GEMM: 16 warps x (32x64), trans-B from [K][N] =================
#define KC 32
#define ARS 80
#define BRS 528
#define A_SZ (128 * ARS)
#define B_SZ (KC * BRS)
#define STG  (2 * A_SZ + 2 * B_SZ)
#define AH_O 0
#define AL_O A_SZ
#define BH_O (2 * A_SZ)
#define BL_O (2 * A_SZ + B_SZ)
#define EROFF (3 * STG)
#define GEMM_SMEM (EROFF + 512)

// mode 0: dense C = A @ B (+addsrc)
// mode 1: moe gate_up: C rows = g_gu[erows]
// mode 2: moe down: atomicAdd into C[tok] * g_rw
__global__ void __launch_bounds__(512) bf16x3_gemm_kernel(
    int mode,
    const __nv_bfloat16* __restrict__ Ah, const __nv_bfloat16* __restrict__ Al,
    const __nv_bfloat16* __restrict__ Bh, const __nv_bfloat16* __restrict__ Bl,
    float* __restrict__ C, const float* __restrict__ addsrc, int N, int K)
{
    int e  = blockIdx.z;
    int m0 = blockIdx.y * 128;
    int n0 = blockIdx.x * 256;
    int cnt = 0;
    if (mode != 0) {
        cnt = g_ecnt[e];
        if (m0 >= cnt) return;
        Bh += (size_t)e * K * N;
        Bl += (size_t)e * K * N;
    }
    extern __shared__ char sm[];
    uint32_t sb = smem_u32(sm);
    int tid = threadIdx.x, wid = tid >> 5, l = tid & 31;
    int* erows_s = (int*)(sm + EROFF);
    if (mode != 0 && tid < 128)
        erows_s[tid] = (m0 + tid < cnt) ? g_erows[e * TT + m0 + tid] : 0;
    __syncthreads();

    int arow = tid >> 2, apart = tid & 3;
    size_t aro;
    if (mode == 0)      aro = (size_t)(m0 + arow) * K;
    else if (mode == 1) aro = (size_t)(erows_s[arow] >> 2) * DD;
    else                aro = (size_t)erows_s[arow] * NF;
    const __nv_bfloat16* aph = Ah + aro + apart * 8;
    const __nv_bfloat16* apl = Al + aro + apart * 8;
    uint32_t a_dst = (uint32_t)(arow * ARS + apart * 16);

    int brow = tid >> 4, bpart = tid & 15;
    size_t bo = (size_t)brow * N + n0 + bpart * 16;
    uint32_t b_dst = (uint32_t)(brow * BRS + bpart * 32);

    int NC = K / KC;

    int wm = wid >> 2, wn = wid & 3;
    int a_r = (l & 7) + ((l >> 3) & 1) * 8;
    int a_c = (l >> 4) * 8;
    uint32_t a_base = (uint32_t)((wm * 32 + a_r) * ARS + a_c * 2);
    uint32_t b_base = (uint32_t)(a_r * BRS + (wn * 64 + a_c) * 2);

    float acc[2][8][4];
#pragma unroll
    for (int mi = 0; mi < 2; mi++)
#pragma unroll
        for (int ni = 0; ni < 8; ni++)
#pragma unroll
            for (int j = 0; j < 4; j++) acc[mi][ni][j] = 0.f;

#pragma unroll
    for (int p = 0; p < 2; p++) {
        if (p < NC) {
            uint32_t st = sb + p * STG;
            int k0 = p * KC;
            CP16(st + AH_O + a_dst, aph + k0);
            CP16(st + AL_O + a_dst, apl + k0);
            const __nv_bfloat16* bsh = Bh + bo + (size_t)k0 * N;
            const __nv_bfloat16* bsl = Bl + bo + (size_t)k0 * N;
            CP16(st + BH_O + b_dst,      bsh);
            CP16(st + BH_O + b_dst + 16, bsh + 8);
            CP16(st + BL_O + b_dst,      bsl);
            CP16(st + BL_O + b_dst + 16, bsl + 8);
        }
        CP_COMMIT();
    }

    for (int c = 0; c < NC; c++) {
        if (c + 1 < NC) CP_WAIT1(); else CP_WAIT0();
        __syncthreads();
        if (c + 2 < NC) {
            int n2 = c + 2;
            uint32_t st = sb + (n2 % 3) * STG;
            int k0 = n2 * KC;
            CP16(st + AH_O + a_dst, aph + k0);
            CP16(st + AL_O + a_dst, apl + k0);
            const __nv_bfloat16* bsh = Bh + bo + (size_t)k0 * N;
            const __nv_bfloat16* bsl = Bl + bo + (size_t)k0 * N;
            CP16(st + BH_O + b_dst,      bsh);
            CP16(st + BH_O + b_dst + 16, bsh + 8);
            CP16(st + BL_O + b_dst,      bsl);
            CP16(st + BL_O + b_dst + 16, bsl + 8);
        }
        CP_COMMIT();

        uint32_t st = sb + (c % 3) * STG;
#pragma unroll
        for (int kk = 0; kk < 2; kk++) {
            uint32_t bh[4][4], bl[4][4];
#pragma unroll
            for (int q = 0; q < 4; q++)
                ldsm4t(bh[q], st + BH_O + b_base + kk * (16 * BRS) + q * 32);
#pragma unroll
            for (int q = 0; q < 4; q++)
                ldsm4t(bl[q], st + BL_O + b_base + kk * (16 * BRS) + q * 32);
#pragma unroll
            for (int mi = 0; mi < 2; mi++) {
                uint32_t ah[4], al[4];
                ldsm4(ah, st + AH_O + a_base + mi * (16 * ARS) + kk * 32);
                ldsm4(al, st + AL_O + a_base + mi * (16 * ARS) + kk * 32);
#pragma unroll
                for (int q = 0; q < 4; q++) {
                    mma16816(acc[mi][2 * q],     ah, &bh[q][0]);
                    mma16816(acc[mi][2 * q + 1], ah, &bh[q][2]);
                }
#pragma unroll
                for (int q = 0; q < 4; q++) {
                    mma16816(acc[mi][2 * q],     ah, &bl[q][0]);
                    mma16816(acc[mi][2 * q + 1], ah, &bl[q][2]);
                }
#pragma unroll
                for (int q = 0; q < 4; q++) {
                    mma16816(acc[mi][2 * q],     al, &bh[q][0]);
                    mma16816(acc[mi][2 * q + 1], al, &bh[q][2]);
                }
            }
        }
    }

    // epilogue
    int g = l >> 2, tig = l & 3;
#pragma unroll
    for (int mi = 0; mi < 2; mi++) {
        int r0 = wm * 32 + mi * 16 + g;
        int r1 = r0 + 8;
        bool v0 = true, v1 = true;
        size_t ro0 = 0, ro1 = 0;
        float w0 = 0.f, w1 = 0.f;
        if (mode == 0) {
            ro0 = (size_t)(m0 + r0) * N;
            ro1 = (size_t)(m0 + r1) * N;
        } else {
            v0 = (m0 + r0) < cnt;
            v1 = (m0 + r1) < cnt;
            int rowid0 = erows_s[r0], rowid1 = erows_s[r1];
            if (mode == 1) {
                ro0 = (size_t)rowid0 * (2 * NF);
                ro1 = (size_t)rowid1 * (2 * NF);
            } else {
                ro0 = (size_t)(rowid0 >> 2) * DD;
                ro1 = (size_t)(rowid1 >> 2) * DD;
                if (v0) w0 = g_rw[rowid0];
                if (v1) w1 = g_rw[rowid1];
            }
        }
#pragma unroll
        for (int ni = 0; ni < 8; ni++) {
            int cc = n0 + wn * 64 + ni * 8 + tig * 2;
            float* a = acc[mi][ni];
            if (mode == 0) {
                if (addsrc) {
                    float2 s0 = *(const float2*)(addsrc + ro0 + cc);
                    float2 s1 = *(const float2*)(addsrc + ro1 + cc);
                    *(float2*)(C + ro0 + cc) = make_float2(a[0] + s0.x, a[1] + s0.y);
                    *(float2*)(C + ro1 + cc) = make_float2(a[2] + s1.x, a[3] + s1.y);
                } else {
                    *(float2*)(C + ro0 + cc) = make_float2(a[0], a[1]);
                    *(float2*)(C + ro1 + cc) = make_float2(a[2], a[3]);
                }
            } else if (mode == 1) {
                if (v0) *(float2*)(C + ro0 + cc) = make_float2(a[0], a[1]);
                if (v1) *(float2*)(C + ro1 + cc) = make_float2(a[2], a[3]);
            } else {
                if (v0) { atomicAdd(C + ro0 + cc, w0 * a[0]); atomicAdd(C + ro0 + cc + 1, w0 * a[1]); }
                if (v1) { atomicAdd(C + ro1 + cc, w1 * a[2]); atomicAdd(C + ro1 + cc + 1, w1 * a[3]); }
            }
        }
    }
}

// ================= RMSNorm (split-bf16 + optional fp32 out + optional passthrough copy) =================
__global__ void rmsnorm_kernel(const float* __restrict__ x,
                               const float* __restrict__ w,
                               float* __restrict__ ofp,
                               __nv_bfloat16* __restrict__ oh,
                               __nv_bfloat16* __restrict__ ol,
                               float* __restrict__ ocopy)
{
    int t = blockIdx.x;
    const float4* xr = (const float4*)(x + (size_t)t * DD);
    const float4* wr = (const float4*)w;
    int tid = threadIdx.x;
    float4 v0 = xr[tid], v1 = xr[tid + 256];
    if (ocopy) {
        float4* orow = (float4*)(ocopy + (size_t)t * DD);
        orow[tid] = v0; orow[tid + 256] = v1;
    }
    float ss = v0.x*v0.x + v0.y*v0.y + v0.z*v0.z + v0.w*v0.w
             + v1.x*v1.x + v1.y*v1.y + v1.z*v1.z + v1.w*v1.w;
#pragma unroll
    for (int o = 16; o; o >>= 1) ss += __shfl_xor_sync(0xffffffffu, ss, o);
    __shared__ float red[8];
    if ((tid & 31) == 0) red[tid >> 5] = ss;
    __syncthreads();
    float tot = red[0]+red[1]+red[2]+red[3]+red[4]+red[5]+red[6]+red[7];
    float r = rsqrtf(tot / (float)DD + 1e-6f);
    float4 w0 = wr[tid], w1 = wr[tid + 256];
    float4 o0, o1;
    o0.x = v0.x*r*w0.x; o0.y = v0.y*r*w0.y; o0.z = v0.z*r*w0.z; o0.w = v0.w*r*w0.w;
    o1.x = v1.x*r*w1.x; o1.y = v1.y*r*w1.y; o1.z = v1.z*r*w1.z; o1.w = v1.w*r*w1.w;
    if (ofp) {
        float4* orow = (float4*)(ofp + (size_t)t * DD);
        orow[tid] = o0; orow[tid + 256] = o1;
    }
    __nv_bfloat16 h[8], lo[8];
    split_bf16(o0.x, h[0], lo[0]); split_bf16(o0.y, h[1], lo[1]);
    split_bf16(o0.z, h[2], lo[2]); split_bf16(o0.w, h[3], lo[3]);
    split_bf16(o1.x, h[4], lo[4]); split_bf16(o1.y, h[5], lo[5]);
    split_bf16(o1.z, h[6], lo[6]); split_bf16(o1.w, h[7], lo[7]);
    uint2* ohr = (uint2*)(oh + (size_t)t * DD);
    uint2* olr = (uint2*)(ol + (size_t)t * DD);
    ohr[tid]       = make_uint2(pack2bf(h[0], h[1]),  pack2bf(h[2], h[3]));
    ohr[tid + 256] = make_uint2(pack2bf(h[4], h[5]),  pack2bf(h[6], h[7]));
    olr[tid]       = make_uint2(pack2bf(lo[0], lo[1]), pack2bf(lo[2], lo[3]));
    olr[tid + 256] = make_uint2(pack2bf(lo[4], lo[5]), pack2bf(lo[6], lo[7]));
}

// ================= per-head RMSNorm + RoPE + split =================
__global__ void normrope_kernel(const float* __restrict__ cosb,
                                const float* __restrict__ sinb,
                                const float* __restrict__ qnw,
                                const float* __restrict__ knw)
{
    int t = blockIdx.x;
    int head = blockIdx.y;      // 0..15 q, 16..19 k, 20..23 v
    int h = threadIdx.x;
    if (head >= 20) {
        int kvh = head - 20;
        float v = g_qkv[(size_t)t * QKVW + VOFF + kvh * HDIM + h];
        __nv_bfloat16 hh, ll;
        split_bf16(v, hh, ll);
        size_t o = ((size_t)t * NKV + kvh) * HDIM + h;
        g_v_h[o] = hh; g_v_l[o] = ll;
        return;
    }
    const float* src;
    const float* nw;
    if (head < NQ) { src = g_qkv + (size_t)t * QKVW + head * HDIM;               nw = qnw; }
    else           { src = g_qkv + (size_t)t * QKVW + KOFF + (head - NQ) * HDIM; nw = knw; }
    float v = src[h];
    float ss = v * v;
#pragma unroll
    for (int o = 16; o; o >>= 1) ss += __shfl_xor_sync(0xffffffffu, ss, o);
    __shared__ float red[4];
    __shared__ float xs[128];
    if ((h & 31) == 0) red[h >> 5] = ss;
    __syncthreads();
    float tot = red[0] + red[1] + red[2] + red[3];
    float xn = v * rsqrtf(tot / (float)HDIM + 1e-6f) * nw[h];
    xs[h] = xn;
    __syncthreads();
    float c = cosb[(size_t)t * HDIM + h];
    float s = sinb[(size_t)t * HDIM + h];
    float other = (h < 64) ? xs[h + 64] : xs[h - 64];
    float outv = (h < 64) ? (xn * c - other * s) : (xn * c + other * s);
    __nv_bfloat16 hh, ll;
    split_bf16(outv, hh, ll);
    if (head < NQ) {
        size_t o = ((size_t)t * NQ + head) * HDIM + h;
        g_q_h[o] = hh; g_q_l[o] = ll;
    } else {
        size_t o = ((size_t)t * NKV + (head - NQ)) * HDIM + h;
        g_k_h[o] = hh; g_k_l[o] = ll;
    }
}

// ================= flash attention, bf16x3 HMMA, 128 q-rows / 8 warps =================
#define AT_RST  272
#define QT  (128 * AT_RST)           // 34816
#define KVT (64 * AT_RST)            // 17408
#define AT_QH 0
#define AT_QL QT
#define AT_KH (2 * QT)
#define AT_KL (2 * QT + KVT)
#define AT_VH (2 * QT + 2 * KVT)
#define AT_VL (2 * QT + 3 * KVT)
#define AT_SMEM (2 * QT + 4 * KVT)   // 139264

__device__ __forceinline__ void attn_issue_kv(uint32_t sb, int j0, int kvh, int tid)
{
    int srow = tid >> 2, sp = tid & 3;   // 64 rows, 4 threads/row, 64B each
    size_t base = ((size_t)(j0 + srow) * NKV + kvh) * HDIM + sp * 32;
    uint32_t d = (uint32_t)(srow * AT_RST + sp * 64);
#pragma unroll
    for (int i = 0; i < 4; i++) {
        CP16(sb + AT_KH + d + i * 16, g_k_h + base + i * 8);
        CP16(sb + AT_KL + d + i * 16, g_k_l + base + i * 8);
        CP16(sb + AT_VH + d + i * 16, g_v_h + base + i * 8);
        CP16(sb + AT_VL + d + i * 16, g_v_l + base + i * 8);
    }
}

__global__ void __launch_bounds__(256) attn_kernel()
{
    extern __shared__ char sm[];
    uint32_t sb = smem_u32(sm);
    int bx = blockIdx.x;
    int m0 = bx * 128;
    int head = blockIdx.y;
    int kvh = head >> 2;
    int tid = threadIdx.x, wid = tid >> 5, l = tid & 31;
    const float scale = 0.08838834764831843f;

    // Q staging: 128 rows, 2 threads/row, 128B each per array
    {
        int srow = tid >> 1, sp = tid & 1;
        size_t qb = ((size_t)(m0 + srow) * NQ + head) * HDIM + sp * 64;
        uint32_t d = (uint32_t)(srow * AT_RST + sp * 128);
#pragma unroll
        for (int i = 0; i < 8; i++) {
            CP16(sb + AT_QH + d + i * 16, g_q_h + qb + i * 8);
            CP16(sb + AT_QL + d + i * 16, g_q_l + qb + i * 8);
        }
    }
    attn_issue_kv(sb, 0, kvh, tid);
    CP_COMMIT();

    int a_r = (l & 7) + ((l >> 3) & 1) * 8;
    int a_c = (l >> 4) * 8;
    int b_r = (l & 7) + (l >> 4) * 8;
    int b_c = ((l >> 3) & 1) * 8;

    float o[16][4];
#pragma unroll
    for (int nd = 0; nd < 16; nd++)
#pragma unroll
        for (int j = 0; j < 4; j++) o[nd][j] = 0.f;
    float m_i0 = -1e30f, m_i1 = -1e30f, l0 = 0.f, l1 = 0.f;

    int rA_glob = m0 + wid * 16 + (l >> 2);
    int rB_glob = rA_glob + 8;

    int njt = 2 * bx + 2;
    for (int jt = 0; jt < njt; jt++) {
        CP_WAIT0();
        __syncthreads();

        float s[8][4];
#pragma unroll
        for (int ni = 0; ni < 8; ni++)
#pragma unroll
            for (int j = 0; j < 4; j++) s[ni][j] = 0.f;
#pragma unroll
        for (int ks = 0; ks < 8; ks++) {
            uint32_t qh4[4], ql4[4];
            uint32_t qa = sb + (uint32_t)((wid * 16 + a_r) * AT_RST + (ks * 16 + a_c) * 2);
            ldsm4(qh4, qa + AT_QH);
            ldsm4(ql4, qa + AT_QL);
            uint32_t kh[4][4], kl[4][4];
#pragma unroll
            for (int q2 = 0; q2 < 4; q2++) {
                uint32_t ka = sb + (uint32_t)((q2 * 16 + b_r) * AT_RST + (ks * 16 + b_c) * 2);
                ldsm4(kh[q2], ka + AT_KH);
                ldsm4(kl[q2], ka + AT_KL);
            }
#pragma unroll
            for (int q2 = 0; q2 < 4; q2++) {
                mma16816(s[2 * q2],     qh4, &kh[q2][0]);
                mma16816(s[2 * q2 + 1], qh4, &kh[q2][2]);
            }
#pragma unroll
            for (int q2 = 0; q2 < 4; q2++) {
                mma16816(s[2 * q2],     qh4, &kl[q2][0]);
                mma16816(s[2 * q2 + 1], qh4, &kl[q2][2]);
            }
#pragma unroll
            for (int q2 = 0; q2 < 4; q2++) {
                mma16816(s[2 * q2],     ql4, &kh[q2][0]);
                mma16816(s[2 * q2 + 1], ql4, &kh[q2][2]);
            }
        }
#pragma unroll
        for (int ni = 0; ni < 8; ni++)
#pragma unroll
            for (int j = 0; j < 4; j++) s[ni][j] *= scale;
        // causal mask on the last two j-tiles (global column vs global row)
        if (jt >= njt - 2) {
            int jbase = jt * 64;
#pragma unroll
            for (int ni = 0; ni < 8; ni++) {
                int c0 = jbase + ni * 8 + 2 * (l & 3), c1 = c0 + 1;
                if (c0 > rA_glob) s[ni][0] = -1e30f;
                if (c1 > rA_glob) s[ni][1] = -1e30f;
                if (c0 > rB_glob) s[ni][2] = -1e30f;
                if (c1 > rB_glob) s[ni][3] = -1e30f;
            }
        }
        float mt0 = -1e30f, mt1 = -1e30f;
#pragma unroll
        for (int ni = 0; ni < 8; ni++) {
            mt0 = fmaxf(mt0, fmaxf(s[ni][0], s[ni][1]));
            mt1 = fmaxf(mt1, fmaxf(s[ni][2], s[ni][3]));
        }
        mt0 = fmaxf(mt0, __shfl_xor_sync(0xffffffffu, mt0, 1));
        mt0 = fmaxf(mt0, __shfl_xor_sync(0xffffffffu, mt0, 2));
        mt1 = fmaxf(mt1, __shfl_xor_sync(0xffffffffu, mt1, 1));
        mt1 = fmaxf(mt1, __shfl_xor_sync(0xffffffffu, mt1, 2));
        float mn0 = fmaxf(m_i0, mt0), mn1 = fmaxf(m_i1, mt1);
        float c0 = __expf(m_i0 - mn0), c1 = __expf(m_i1 - mn1);
        l0 *= c0; l1 *= c1;
#pragma unroll
        for (int nd = 0; nd < 16; nd++) {
            o[nd][0] *= c0; o[nd][1] *= c0; o[nd][2] *= c1; o[nd][3] *= c1;
        }
        m_i0 = mn0; m_i1 = mn1;
        float rs0 = 0.f, rs1 = 0.f;
        uint32_t pha[16], pla[16];
#pragma unroll
        for (int ni = 0; ni < 8; ni++) {
            float p0 = __expf(s[ni][0] - mn0), p1 = __expf(s[ni][1] - mn0);
            float p2 = __expf(s[ni][2] - mn1), p3 = __expf(s[ni][3] - mn1);
            rs0 += p0 + p1; rs1 += p2 + p3;
            __nv_bfloat16 h0, l0b, h1, l1b, h2, l2b, h3, l3b;
            split_bf16(p0, h0, l0b); split_bf16(p1, h1, l1b);
            split_bf16(p2, h2, l2b); split_bf16(p3, h3, l3b);
            pha[2 * ni]     = pack2bf(h0, h1);
            pha[2 * ni + 1] = pack2bf(h2, h3);
            pla[2 * ni]     = pack2bf(l0b, l1b);
            pla[2 * ni + 1] = pack2bf(l2b, l3b);
        }
        rs0 += __shfl_xor_sync(0xffffffffu, rs0, 1);
        rs0 += __shfl_xor_sync(0xffffffffu, rs0, 2);
        rs1 += __shfl_xor_sync(0xffffffffu, rs1, 1);
        rs1 += __shfl_xor_sync(0xffffffffu, rs1, 2);
        l0 += rs0; l1 += rs1;

#pragma unroll
        for (int ks = 0; ks < 4; ks++) {
            const uint32_t* ph = &pha[4 * ks];
            const uint32_t* pl = &pla[4 * ks];
#pragma unroll
            for (int dp = 0; dp < 4; dp++) {
                uint32_t vh[2][4], vl[2][4];
#pragma unroll
                for (int u = 0; u < 2; u++) {
                    uint32_t va = sb + (uint32_t)((ks * 16 + a_r) * AT_RST +
                                                  ((2 * dp + u) * 16 + a_c) * 2);
                    ldsm4t(vh[u], va + AT_VH);
                    ldsm4t(vl[u], va + AT_VL);
                }
                mma16816(o[4 * dp],     ph, &vh[0][0]);
                mma16816(o[4 * dp + 1], ph, &vh[0][2]);
                mma16816(o[4 * dp + 2], ph, &vh[1][0]);
                mma16816(o[4 * dp + 3], ph, &vh[1][2]);
                mma16816(o[4 * dp],     pl, &vh[0][0]);
                mma16816(o[4 * dp + 1], pl, &vh[0][2]);
                mma16816(o[4 * dp + 2], pl, &vh[1][0]);
                mma16816(o[4 * dp + 3], pl, &vh[1][2]);
                mma16816(o[4 * dp],     ph, &vl[0][0]);
                mma16816(o[4 * dp + 1], ph, &vl[0][2]);
                mma16816(o[4 * dp + 2], ph, &vl[1][0]);
                mma16816(o[4 * dp + 3], ph, &vl[1][2]);
            }
        }
        __syncthreads();
        if (jt + 1 < njt) attn_issue_kv(sb, (jt + 1) * 64, kvh, tid);
        CP_COMMIT();
    }

    float inv0 = 1.f / l0, inv1 = 1.f / l1;
#pragma unroll
    for (int nd = 0; nd < 16; nd++) {
        int d = nd * 8 + 2 * (l & 3);
        float v0 = o[nd][0] * inv0, v1 = o[nd][1] * inv0;
        float v2 = o[nd][2] * inv1, v3 = o[nd][3] * inv1;
        __nv_bfloat16 h0, lo0, h1, lo1, h2, lo2, h3, lo3;
        split_bf16(v0, h0, lo0); split_bf16(v1, h1, lo1);
        split_bf16(v2, h2, lo2); split_bf16(v3, h3, lo3);
        size_t oA = (size_t)rA_glob * DD + head * HDIM + d;
        size_t oB = (size_t)rB_glob * DD + head * HDIM + d;
        *(uint32_t*)(g_attn_h + oA) = pack2bf(h0, h1);
        *(uint32_t*)(g_attn_l + oA) = pack2bf(lo0, lo1);
        *(uint32_t*)(g_attn_h + oB) = pack2bf(h2, h3);
        *(uint32_t*)(g_attn_l + oB) = pack2bf(lo2, lo3);
    }
}

// ================= routing =================
__global__ void zero_cnt_kernel() { if (threadIdx.x < NE) g_ecnt[threadIdx.x] = 0; }

__global__ void route_kernel(const float* __restrict__ gate_w)
{
    int t = blockIdx.x;
    int tid = threadIdx.x;
    const float* x = g_h2 + (size_t)t * DD;
    float acc[NE];
#pragma unroll
    for (int e = 0; e < NE; e++) acc[e] = 0.f;
    for (int d = tid; d < DD; d += 128) {
        float xv = x[d];
        const float* gw = gate_w + (size_t)d * NE;
#pragma unroll
        for (int e = 0; e < NE; e++) acc[e] += xv * gw[e];
    }
    __shared__ float s[NE * 128];
#pragma unroll
    for (int e = 0; e < NE; e++) s[e * 128 + tid] = acc[e];
    __syncthreads();
    __shared__ float logits[NE];
    if (tid < NE) {
        float sum = 0.f;
        for (int i = 0; i < 128; i++) sum += s[tid * 128 + i];
        logits[tid] = sum;
    }
    __syncthreads();
    if (tid == 0) {
        float mx = -1e30f;
        for (int e = 0; e < NE; e++) mx = fmaxf(mx, logits[e]);
        float p[NE], Z = 0.f;
        for (int e = 0; e < NE; e++) { p[e] = expf(logits[e] - mx); Z += p[e]; }
        for (int e = 0; e < NE; e++) p[e] /= Z;
        int idx[TOPK]; float val[TOPK]; bool used[NE] = {};
        float wsum = 0.f;
        for (int k = 0; k < TOPK; k++) {
            int best = -1; float bv = -1.f;
            for (int e = 0; e < NE; e++)
                if (!used[e] && p[e] > bv) { bv = p[e]; best = e; }
            used[best] = true; idx[k] = best; val[k] = bv; wsum += bv;
        }
        for (int k = 0; k < TOPK; k++) {
            int rowid = t * TOPK + k;
            g_rw[rowid] = val[k] / wsum;
            int e = idx[k];
            int pos = atomicAdd(&g_ecnt[e], 1);
            g_erows[e * TT + pos] = rowid;
        }
    }
}

__global__ void silu_kernel()
{
    size_t i = (size_t)blockIdx.x * 256 + threadIdx.x;
    int r = (int)(i >> 10);
    int f = (int)(i & 1023);
    float g = g_gu[(size_t)r * (2 * NF) + f];
    float u = g_gu[(size_t)r * (2 * NF) + NF + f];
    float v = u * (g / (1.f + __expf(-g)));
    __nv_bfloat16 h, lo;
    split_bf16(v, h, lo);
    g_gated_h[i] = h;
    g_gated_l[i] = lo;
}

// ================= launch =================
extern "C" void kernel_launch(void* const* d_in, const int* in_sizes, int n_in,
                              void* d_out, int out_size)
{
    const float* hidden  = (const float*)d_in[0];
    const float* cosb    = (const float*)d_in[1];
    const float* sinb    = (const float*)d_in[2];
    const float* in_ln   = (const float*)d_in[4];
    const float* post_ln = (const float*)d_in[5];
    const float* q_w     = (const float*)d_in[6];
    const float* k_w     = (const float*)d_in[7];
    const float* v_w     = (const float*)d_in[8];
    const float* o_w     = (const float*)d_in[9];
    const float* q_nw    = (const float*)d_in[10];
    const float* k_nw    = (const float*)d_in[11];
    const float* gate_w  = (const float*)d_in[12];
    const float* gup_w   = (const float*)d_in[13];
    const float* down_w  = (const float*)d_in[14];
    float* out = (float*)d_out;

    float *qkv, *hmid, *h2, *gu;
    __nv_bfloat16 *hn_h, *hn_l, *attn_h, *attn_l, *h2_h, *h2_l, *gated_h, *gated_l;
    __nv_bfloat16 *wqkv_h, *wqkv_l, *wo_h, *wo_l, *wgu_h, *wgu_l, *wdn_h, *wdn_l;
    cudaGetSymbolAddress((void**)&qkv,  g_qkv);
    cudaGetSymbolAddress((void**)&hmid, g_hmid);
    cudaGetSymbolAddress((void**)&h2,   g_h2);
    cudaGetSymbolAddress((void**)&gu,   g_gu);
    cudaGetSymbolAddress((void**)&hn_h, g_hn_h);
    cudaGetSymbolAddress((void**)&hn_l, g_hn_l);
    cudaGetSymbolAddress((void**)&attn_h, g_attn_h);
    cudaGetSymbolAddress((void**)&attn_l, g_attn_l);
    cudaGetSymbolAddress((void**)&h2_h, g_h2_h);
    cudaGetSymbolAddress((void**)&h2_l, g_h2_l);
    cudaGetSymbolAddress((void**)&gated_h, g_gated_h);
    cudaGetSymbolAddress((void**)&gated_l, g_gated_l);
    cudaGetSymbolAddress((void**)&wqkv_h, g_wqkv_h);
    cudaGetSymbolAddress((void**)&wqkv_l, g_wqkv_l);
    cudaGetSymbolAddress((void**)&wo_h,   g_wo_h);
    cudaGetSymbolAddress((void**)&wo_l,   g_wo_l);
    cudaGetSymbolAddress((void**)&wgu_h,  g_wgu_h);
    cudaGetSymbolAddress((void**)&wgu_l,  g_wgu_l);
    cudaGetSymbolAddress((void**)&wdn_h,  g_wdn_h);
    cudaGetSymbolAddress((void**)&wdn_l,  g_wdn_l);

    cudaFuncSetAttribute(bf16x3_gemm_kernel, cudaFuncAttributeMaxDynamicSharedMemorySize, GEMM_SMEM);
    cudaFuncSetAttribute(attn_kernel, cudaFuncAttributeMaxDynamicSharedMemorySize, AT_SMEM);

    // streaming weight split
    wsplit_qkv_kernel<<<6144, 256>>>((const float4*)q_w, (const float4*)k_w,
                                     (const float4*)v_w, (uint2*)wqkv_h, (uint2*)wqkv_l);
    wsplit_kernel<<<4096, 256>>>((const float4*)o_w,    (uint2*)wo_h,  (uint2*)wo_l,  DD * DD / 4);
    wsplit_kernel<<<65536, 256>>>((const float4*)gup_w, (uint2*)wgu_h, (uint2*)wgu_l, NE * DD * 2 * NF / 4);
    wsplit_kernel<<<32768, 256>>>((const float4*)down_w,(uint2*)wdn_h, (uint2*)wdn_l, NE * NF * DD / 4);

    // 1. pre-attn rmsnorm
    rmsnorm_kernel<<<TT, 256>>>(hidden, in_ln, nullptr, hn_h, hn_l, nullptr);
    // 2. fused QKV projection
    bf16x3_gemm_kernel<<<dim3(QKVW / 256, TT / 128), 512, GEMM_SMEM>>>(
        0, hn_h, hn_l, wqkv_h, wqkv_l, qkv, nullptr, QKVW, DD);
    // 3. per-head norm + rope + split
    normrope_kernel<<<dim3(TT, NQ + NKV + NKV), 128>>>(cosb, sinb, q_nw, k_nw);
    // 4. attention (128-row CTAs, 8 warps)
    attn_kernel<<<dim3(TT / 128, NQ), 256, AT_SMEM>>>();
    // 5. O projection + residual
    bf16x3_gemm_kernel<<<dim3(DD / 256, TT / 128), 512, GEMM_SMEM>>>(
        0, attn_h, attn_l, wo_h, wo_l, hmid, hidden, DD, DD);
    // 6. post-attn rmsnorm (+ copies hmid into out as residual init)
    rmsnorm_kernel<<<TT, 256>>>(hmid, post_ln, h2, h2_h, h2_l, out);
    // 7. routing
    zero_cnt_kernel<<<1, 32>>>();
    route_kernel<<<TT, 128>>>(gate_w);
    // 8. sparse expert GEMMs
    bf16x3_gemm_kernel<<<dim3((2 * NF) / 256, 16, NE), 512, GEMM_SMEM>>>(
        1, h2_h, h2_l, wgu_h, wgu_l, gu, nullptr, 2 * NF, DD);
    silu_kernel<<<(TT * TOPK * NF) / 256, 256>>>();
    bf16x3_gemm_kernel<<<dim3(DD / 256, 16, NE), 512, GEMM_SMEM>>>(
        2, gated_h, gated_l, wdn_h, wdn_l, out, nullptr, DD, NF);
}

// round 14
// speedup vs baseline: 1.0762x; 1.0348x over previous
#include <cuda_runtime.h>
#include <cuda_bf16.h>
#include <math.h>
#include <stdint.h>

#define TT   2048
#define DD   2048
#define NQ   16
#define NKV  4
#define HDIM 128
#define NE   16
#define NF   1024
#define TOPK 4

#define QKVW 3072
#define KOFF 2048
#define VOFF 2560

// ---------------- scratch ----------------
__device__ float g_qkv  [TT * QKVW];
__device__ float g_hmid [TT * DD];
__device__ float g_h2   [TT * DD];
__device__ float g_rw   [TT * TOPK];
__device__ int   g_ecnt [NE];
__device__ int   g_erows[NE * TT];

__device__ __nv_bfloat16 g_hn_h   [TT * DD];
__device__ __nv_bfloat16 g_hn_l   [TT * DD];
__device__ __nv_bfloat16 g_q_h    [TT * NQ * HDIM];
__device__ __nv_bfloat16 g_q_l    [TT * NQ * HDIM];
__device__ __nv_bfloat16 g_k_h    [TT * NKV * HDIM];
__device__ __nv_bfloat16 g_k_l    [TT * NKV * HDIM];
__device__ __nv_bfloat16 g_v_h    [TT * NKV * HDIM];
__device__ __nv_bfloat16 g_v_l    [TT * NKV * HDIM];
__device__ __nv_bfloat16 g_attn_h [TT * DD];
__device__ __nv_bfloat16 g_attn_l [TT * DD];
__device__ __nv_bfloat16 g_h2_h   [TT * DD];
__device__ __nv_bfloat16 g_h2_l   [TT * DD];
__device__ __nv_bfloat16 g_gated_h[TT * TOPK * NF];
__device__ __nv_bfloat16 g_gated_l[TT * TOPK * NF];

// split-bf16 weights in NATURAL [K][N] layout (gate_up column-interleaved: 2f=gate_f, 2f+1=up_f)
__device__ __nv_bfloat16 g_wqkv_h[DD * QKVW];
__device__ __nv_bfloat16 g_wqkv_l[DD * QKVW];
__device__ __nv_bfloat16 g_wo_h  [DD * DD];
__device__ __nv_bfloat16 g_wo_l  [DD * DD];
__device__ __nv_bfloat16 g_wgu_h [NE * DD * (2 * NF)];
__device__ __nv_bfloat16 g_wgu_l [NE * DD * (2 * NF)];
__device__ __nv_bfloat16 g_wdn_h [NE * NF * DD];
__device__ __nv_bfloat16 g_wdn_l [NE * NF * DD];

// ================= helpers =================
__device__ __forceinline__ uint32_t smem_u32(const void* p) {
    uint32_t r;
    asm("{ .reg .u64 t; cvta.to.shared.u64 t, %1; cvt.u32.u64 %0, t; }" : "=r"(r) : "l"(p));
    return r;
}
__device__ __forceinline__ uint32_t pack2bf(__nv_bfloat16 a, __nv_bfloat16 b) {
    return (uint32_t)__bfloat16_as_ushort(a) | ((uint32_t)__bfloat16_as_ushort(b) << 16);
}
__device__ __forceinline__ void ldsm4(uint32_t* r, uint32_t a) {
    asm volatile("ldmatrix.sync.aligned.m8n8.x4.shared.b16 {%0,%1,%2,%3}, [%4];"
                 : "=r"(r[0]), "=r"(r[1]), "=r"(r[2]), "=r"(r[3]) : "r"(a));
}
__device__ __forceinline__ void ldsm4t(uint32_t* r, uint32_t a) {
    asm volatile("ldmatrix.sync.aligned.m8n8.x4.trans.shared.b16 {%0,%1,%2,%3}, [%4];"
                 : "=r"(r[0]), "=r"(r[1]), "=r"(r[2]), "=r"(r[3]) : "r"(a));
}
__device__ __forceinline__ void mma16816(float* c, const uint32_t* a, const uint32_t* b) {
    asm volatile("mma.sync.aligned.m16n8k16.row.col.f32.bf16.bf16.f32 "
                 "{%0,%1,%2,%3}, {%4,%5,%6,%7}, {%8,%9}, {%0,%1,%2,%3};"
                 : "+f"(c[0]), "+f"(c[1]), "+f"(c[2]), "+f"(c[3])
                 : "r"(a[0]), "r"(a[1]), "r"(a[2]), "r"(a[3]), "r"(b[0]), "r"(b[1]));
}
#define CP16(dst, src) \
    asm volatile("cp.async.cg.shared.global [%0], [%1], 16;" :: "r"(dst), "l"(src))
#define CP_COMMIT() asm volatile("cp.async.commit_group;" ::: "memory")
#define CP_WAIT1()  asm volatile("cp.async.wait_group 1;" ::: "memory")
#define CP_WAIT0()  asm volatile("cp.async.wait_group 0;" ::: "memory")

__device__ __forceinline__ void split_bf16(float v, __nv_bfloat16& h, __nv_bfloat16& l) {
    h = __float2bfloat16(v);
    l = __float2bfloat16(v - __bfloat162float(h));
}

// ================= streaming weight split =================
__global__ void wsplit_kernel(const float4* __restrict__ in,
                              uint2* __restrict__ oh, uint2* __restrict__ ol, int n4)
{
    int i = blockIdx.x * blockDim.x + threadIdx.x;
    if (i >= n4) return;
    float4 v = in[i];
    __nv_bfloat16 h0, l0, h1, l1, h2, l2, h3, l3;
    split_bf16(v.x, h0, l0); split_bf16(v.y, h1, l1);
    split_bf16(v.z, h2, l2); split_bf16(v.w, h3, l3);
    oh[i] = make_uint2(pack2bf(h0, h1), pack2bf(h2, h3));
    ol[i] = make_uint2(pack2bf(l0, l1), pack2bf(l2, l3));
}
__global__ void wsplit_qkv_kernel(const float4* __restrict__ q, const float4* __restrict__ k,
                                  const float4* __restrict__ v,
                                  uint2* __restrict__ oh, uint2* __restrict__ ol)
{
    int i = blockIdx.x * 256 + threadIdx.x;   // over 2048*768
    int row = i / 768, c4 = i % 768;
    float4 val;
    if (c4 < 512)      val = q[row * 512 + c4];
    else if (c4 < 640) val = k[row * 128 + (c4 - 512)];
    else               val = v[row * 128 + (c4 - 640)];
    __nv_bfloat16 h0, l0, h1, l1, h2, l2, h3, l3;
    split_bf16(val.x, h0, l0); split_bf16(val.y, h1, l1);
    split_bf16(val.z, h2, l2); split_bf16(val.w, h3, l3);
    oh[i] = make_uint2(pack2bf(h0, h1), pack2bf(h2, h3));
    ol[i] = make_uint2(pack2bf(l0, l1), pack2bf(l2, l3));
}
// gate_up, column-interleaved (2f=gate, 2f+1=up), fully vectorized 16B loads/stores
__global__ void wsplit_gu_kernel(const float4* __restrict__ in,   // [NE*DD][2NF/4]
                                 uint4* __restrict__ oh, uint4* __restrict__ ol)
{
    int i = blockIdx.x * 256 + threadIdx.x;   // over NE*DD*NF/4
    int per_row = NF / 4;                      // 256
    int row = i / per_row;
    int j = i % per_row;                       // f base = 4j
    const float4* base = in + (size_t)row * (2 * NF / 4);
    float4 gv = base[j];
    float4 uv = base[NF / 4 + j];
    __nv_bfloat16 gh0, gl0, gh1, gl1, gh2, gl2, gh3, gl3;
    __nv_bfloat16 uh0, ul0, uh1, ul1, uh2, ul2, uh3, ul3;
    split_bf16(gv.x, gh0, gl0); split_bf16(gv.y, gh1, gl1);
    split_bf16(gv.z, gh2, gl2); split_bf16(gv.w, gh3, gl3);
    split_bf16(uv.x, uh0, ul0); split_bf16(uv.y, uh1, ul1);
    split_bf16(uv.z, uh2, ul2); split_bf16(uv.w, uh3, ul3);
    oh[i] = make_uint4(pack2bf(gh0, uh0), pack2bf(gh1, uh1),
                       pack2bf(gh2, uh2), pack2bf(gh3, uh3));
    ol[i] = make_uint4(pack2bf(gl0, ul0), pack2bf(gl1, ul1),
                       pack2bf(gl2, ul2), pack2bf(gl3, ul3));
}

// ================= bf16x3 GEMM: 16 warps x (32x64), trans-B from [K][N] =================
#define KC 32
#define ARS 80
#define BRS 528
#define A_SZ (128 * ARS)
#define B_SZ (KC * BRS)
#define STG  (2 * A_SZ + 2 * B_SZ)
#define AH_O 0
#define AL_O A_SZ
#define BH_O (2 * A_SZ)
#define BL_O (2 * A_SZ + B_SZ)
#define EROFF (3 * STG)
#define GEMM_SMEM (EROFF + 512)
#define GRS 272                    // gated smem row stride (mode-1 epilogue)

// mode 0: dense C = A @ B (+addsrc)
// mode 1: moe gate_up, FUSED SiLU, smem-recoalesced -> g_gated_h/l (C unused)
// mode 2: moe down: atomicAdd into C[tok] * g_rw
__global__ void __launch_bounds__(512) bf16x3_gemm_kernel(
    int mode,
    const __nv_bfloat16* __restrict__ Ah, const __nv_bfloat16* __restrict__ Al,
    const __nv_bfloat16* __restrict__ Bh, const __nv_bfloat16* __restrict__ Bl,
    float* __restrict__ C, const float* __restrict__ addsrc, int N, int K)
{
    int e  = blockIdx.z;
    int m0 = blockIdx.y * 128;
    int n0 = blockIdx.x * 256;
    int cnt = 0;
    if (mode != 0) {
        cnt = g_ecnt[e];
        if (m0 >= cnt) return;
        Bh += (size_t)e * K * N;
        Bl += (size_t)e * K * N;
    }
    extern __shared__ char sm[];
    uint32_t sb = smem_u32(sm);
    int tid = threadIdx.x, wid = tid >> 5, l = tid & 31;
    int* erows_s = (int*)(sm + EROFF);
    if (mode != 0 && tid < 128)
        erows_s[tid] = (m0 + tid < cnt) ? g_erows[e * TT + m0 + tid] : 0;
    __syncthreads();

    int arow = tid >> 2, apart = tid & 3;
    size_t aro;
    if (mode == 0)      aro = (size_t)(m0 + arow) * K;
    else if (mode == 1) aro = (size_t)(erows_s[arow] >> 2) * DD;
    else                aro = (size_t)erows_s[arow] * NF;
    const __nv_bfloat16* aph = Ah + aro + apart * 8;
    const __nv_bfloat16* apl = Al + aro + apart * 8;
    uint32_t a_dst = (uint32_t)(arow * ARS + apart * 16);

    int brow = tid >> 4, bpart = tid & 15;
    size_t bo = (size_t)brow * N + n0 + bpart * 16;
    uint32_t b_dst = (uint32_t)(brow * BRS + bpart * 32);

    int NC = K / KC;

    int wm = wid >> 2, wn = wid & 3;
    int a_r = (l & 7) + ((l >> 3) & 1) * 8;
    int a_c = (l >> 4) * 8;
    uint32_t a_base = (uint32_t)((wm * 32 + a_r) * ARS + a_c * 2);
    uint32_t b_base = (uint32_t)(a_r * BRS + (wn * 64 + a_c) * 2);

    float acc[2][8][4];
#pragma unroll
    for (int mi = 0; mi < 2; mi++)
#pragma unroll
        for (int ni = 0; ni < 8; ni++)
#pragma unroll
            for (int j = 0; j < 4; j++) acc[mi][ni][j] = 0.f;

#pragma unroll
    for (int p = 0; p < 2; p++) {
        if (p < NC) {
            uint32_t st = sb + p * STG;
            int k0 = p * KC;
            CP16(st + AH_O + a_dst, aph + k0);
            CP16(st + AL_O + a_dst, apl + k0);
            const __nv_bfloat16* bsh = Bh + bo + (size_t)k0 * N;
            const __nv_bfloat16* bsl = Bl + bo + (size_t)k0 * N;
            CP16(st + BH_O + b_dst,      bsh);
            CP16(st + BH_O + b_dst + 16, bsh + 8);
            CP16(st + BL_O + b_dst,      bsl);
            CP16(st + BL_O + b_dst + 16, bsl + 8);
        }
        CP_COMMIT();
    }

    for (int c = 0; c < NC; c++) {
        if (c + 1 < NC) CP_WAIT1(); else CP_WAIT0();
        __syncthreads();
        if (c + 2 < NC) {
            int n2 = c + 2;
            uint32_t st = sb + (n2 % 3) * STG;
            int k0 = n2 * KC;
            CP16(st + AH_O + a_dst, aph + k0);
            CP16(st + AL_O + a_dst, apl + k0);
            const __nv_bfloat16* bsh = Bh + bo + (size_t)k0 * N;
            const __nv_bfloat16* bsl = Bl + bo + (size_t)k0 * N;
            CP16(st + BH_O + b_dst,      bsh);
            CP16(st + BH_O + b_dst + 16, bsh + 8);
            CP16(st + BL_O + b_dst,      bsl);
            CP16(st + BL_O + b_dst + 16, bsl + 8);
        }
        CP_COMMIT();

        uint32_t st = sb + (c % 3) * STG;
#pragma unroll
        for (int kk = 0; kk < 2; kk++) {
            uint32_t bh[4][4], bl[4][4];
#pragma unroll
            for (int q = 0; q < 4; q++)
                ldsm4t(bh[q], st + BH_O + b_base + kk * (16 * BRS) + q * 32);
#pragma unroll
            for (int q = 0; q < 4; q++)
                ldsm4t(bl[q], st + BL_O + b_base + kk * (16 * BRS) + q * 32);
#pragma unroll
            for (int mi = 0; mi < 2; mi++) {
                uint32_t ah[4], al[4];
                ldsm4(ah, st + AH_O + a_base + mi * (16 * ARS) + kk * 32);
                ldsm4(al, st + AL_O + a_base + mi * (16 * ARS) + kk * 32);
#pragma unroll
                for (int q = 0; q < 4; q++) {
                    mma16816(acc[mi][2 * q],     ah, &bh[q][0]);
                    mma16816(acc[mi][2 * q + 1], ah, &bh[q][2]);
                }
#pragma unroll
                for (int q = 0; q < 4; q++) {
                    mma16816(acc[mi][2 * q],     ah, &bl[q][0]);
                    mma16816(acc[mi][2 * q + 1], ah, &bl[q][2]);
                }
#pragma unroll
                for (int q = 0; q < 4; q++) {
                    mma16816(acc[mi][2 * q],     al, &bh[q][0]);
                    mma16816(acc[mi][2 * q + 1], al, &bh[q][2]);
                }
            }
        }
    }

    int g = l >> 2, tig = l & 3;

    if (mode == 1) {
        // ---- fused SiLU epilogue with smem re-coalescing ----
        __syncthreads();   // mainloop smem reads done; reuse stage buffers
        // gated smem: hi at [0, 128*GRS), lo at [128*GRS, 2*128*GRS)
#pragma unroll
        for (int mi = 0; mi < 2; mi++) {
            int r0 = wm * 32 + mi * 16 + g;
            int r1 = r0 + 8;
#pragma unroll
            for (int ni = 0; ni < 8; ni++) {
                int f_loc = wn * 32 + ni * 4 + tig;   // 0..127
                float* a = acc[mi][ni];
                float gt0 = a[0];
                float gd0 = a[1] * (gt0 / (1.f + __expf(-gt0)));
                float gt1 = a[2];
                float gd1 = a[3] * (gt1 / (1.f + __expf(-gt1)));
                __nv_bfloat16 h0, lo0, h1, lo1;
                split_bf16(gd0, h0, lo0);
                split_bf16(gd1, h1, lo1);
                *(__nv_bfloat16*)(sm + r0 * GRS + f_loc * 2)             = h0;
                *(__nv_bfloat16*)(sm + 128 * GRS + r0 * GRS + f_loc * 2) = lo0;
                *(__nv_bfloat16*)(sm + r1 * GRS + f_loc * 2)             = h1;
                *(__nv_bfloat16*)(sm + 128 * GRS + r1 * GRS + f_loc * 2) = lo1;
            }
        }
        __syncthreads();
        int fb = n0 >> 1;    // CTA f base
        for (int it = tid; it < 2048; it += 512) {
            int row = it >> 4, seg = it & 15;
            if (m0 + row < cnt) {
                int rowid = erows_s[row];
                uint4 vh = *(uint4*)(sm + row * GRS + seg * 16);
                uint4 vl = *(uint4*)(sm + 128 * GRS + row * GRS + seg * 16);
                *(uint4*)(g_gated_h + (size_t)rowid * NF + fb + seg * 8) = vh;
                *(uint4*)(g_gated_l + (size_t)rowid * NF + fb + seg * 8) = vl;
            }
        }
        return;
    }

    // ---- standard epilogue (mode 0 / 2) ----
#pragma unroll
    for (int mi = 0; mi < 2; mi++) {
        int r0 = wm * 32 + mi * 16 + g;
        int r1 = r0 + 8;
        bool v0 = true, v1 = true;
        size_t ro0 = 0, ro1 = 0;
        float w0 = 0.f, w1 = 0.f;
        if (mode == 0) {
            ro0 = (size_t)(m0 + r0) * N;
            ro1 = (size_t)(m0 + r1) * N;
        } else {
            v0 = (m0 + r0) < cnt;
            v1 = (m0 + r1) < cnt;
            int rowid0 = erows_s[r0], rowid1 = erows_s[r1];
            ro0 = (size_t)(rowid0 >> 2) * DD;
            ro1 = (size_t)(rowid1 >> 2) * DD;
            if (v0) w0 = g_rw[rowid0];
            if (v1) w1 = g_rw[rowid1];
        }
#pragma unroll
        for (int ni = 0; ni < 8; ni++) {
            int cc = n0 + wn * 64 + ni * 8 + tig * 2;
            float* a = acc[mi][ni];
            if (mode == 0) {
                if (addsrc) {
                    float2 s0 = *(const float2*)(addsrc + ro0 + cc);
                    float2 s1 = *(const float2*)(addsrc + ro1 + cc);
                    *(float2*)(C + ro0 + cc) = make_float2(a[0] + s0.x, a[1] + s0.y);
                    *(float2*)(C + ro1 + cc) = make_float2(a[2] + s1.x, a[3] + s1.y);
                } else {
                    *(float2*)(C + ro0 + cc) = make_float2(a[0], a[1]);
                    *(float2*)(C + ro1 + cc) = make_float2(a[2], a[3]);
                }
            } else {
                if (v0) { atomicAdd(C + ro0 + cc, w0 * a[0]); atomicAdd(C + ro0 + cc + 1, w0 * a[1]); }
                if (v1) { atomicAdd(C + ro1 + cc, w1 * a[2]); atomicAdd(C + ro1 + cc + 1, w1 * a[3]); }
            }
        }
    }
}

// ================= RMSNorm (split-bf16 + optional fp32 out + optional passthrough copy) =================
__global__ void rmsnorm_kernel(const float* __restrict__ x,
                               const float* __restrict__ w,
                               float* __restrict__ ofp,
                               __nv_bfloat16* __restrict__ oh,
                               __nv_bfloat16* __restrict__ ol,
                               float* __restrict__ ocopy)
{
    int t = blockIdx.x;
    const float4* xr = (const float4*)(x + (size_t)t * DD);
    const float4* wr = (const float4*)w;
    int tid = threadIdx.x;
    float4 v0 = xr[tid], v1 = xr[tid + 256];
    if (ocopy) {
        float4* orow = (float4*)(ocopy + (size_t)t * DD);
        orow[tid] = v0; orow[tid + 256] = v1;
    }
    float ss = v0.x*v0.x + v0.y*v0.y + v0.z*v0.z + v0.w*v0.w
             + v1.x*v1.x + v1.y*v1.y + v1.z*v1.z + v1.w*v1.w;
#pragma unroll
    for (int o = 16; o; o >>= 1) ss += __shfl_xor_sync(0xffffffffu, ss, o);
    __shared__ float red[8];
    if ((tid & 31) == 0) red[tid >> 5] = ss;
    __syncthreads();
    float tot = red[0]+red[1]+red[2]+red[3]+red[4]+red[5]+red[6]+red[7];
    float r = rsqrtf(tot / (float)DD + 1e-6f);
    float4 w0 = wr[tid], w1 = wr[tid + 256];
    float4 o0, o1;
    o0.x = v0.x*r*w0.x; o0.y = v0.y*r*w0.y; o0.z = v0.z*r*w0.z; o0.w = v0.w*r*w0.w;
    o1.x = v1.x*r*w1.x; o1.y = v1.y*r*w1.y; o1.z = v1.z*r*w1.z; o1.w = v1.w*r*w1.w;
    if (ofp) {
        float4* orow = (float4*)(ofp + (size_t)t * DD);
        orow[tid] = o0; orow[tid + 256] = o1;
    }
    __nv_bfloat16 h[8], lo[8];
    split_bf16(o0.x, h[0], lo[0]); split_bf16(o0.y, h[1], lo[1]);
    split_bf16(o0.z, h[2], lo[2]); split_bf16(o0.w, h[3], lo[3]);
    split_bf16(o1.x, h[4], lo[4]); split_bf16(o1.y, h[5], lo[5]);
    split_bf16(o1.z, h[6], lo[6]); split_bf16(o1.w, h[7], lo[7]);
    uint2* ohr = (uint2*)(oh + (size_t)t * DD);
    uint2* olr = (uint2*)(ol + (size_t)t * DD);
    ohr[tid]       = make_uint2(pack2bf(h[0], h[1]),  pack2bf(h[2], h[3]));
    ohr[tid + 256] = make_uint2(pack2bf(h[4], h[5]),  pack2bf(h[6], h[7]));
    olr[tid]       = make_uint2(pack2bf(lo[0], lo[1]), pack2bf(lo[2], lo[3]));
    olr[tid + 256] = make_uint2(pack2bf(lo[4], lo[5]), pack2bf(lo[6], lo[7]));
}

// ================= per-head RMSNorm + RoPE + split =================
__global__ void normrope_kernel(const float* __restrict__ cosb,
                                const float* __restrict__ sinb,
                                const float* __restrict__ qnw,
                                const float* __restrict__ knw)
{
    int t = blockIdx.x;
    int head = blockIdx.y;      // 0..15 q, 16..19 k, 20..23 v
    int h = threadIdx.x;
    if (head >= 20) {
        int kvh = head - 20;
        float v = g_qkv[(size_t)t * QKVW + VOFF + kvh * HDIM + h];
        __nv_bfloat16 hh, ll;
        split_bf16(v, hh, ll);
        size_t o = ((size_t)t * NKV + kvh) * HDIM + h;
        g_v_h[o] = hh; g_v_l[o] = ll;
        return;
    }
    const float* src;
    const float* nw;
    if (head < NQ) { src = g_qkv + (size_t)t * QKVW + head * HDIM;               nw = qnw; }
    else           { src = g_qkv + (size_t)t * QKVW + KOFF + (head - NQ) * HDIM; nw = knw; }
    float v = src[h];
    float ss = v * v;
#pragma unroll
    for (int o = 16; o; o >>= 1) ss += __shfl_xor_sync(0xffffffffu, ss, o);
    __shared__ float red[4];
    __shared__ float xs[128];
    if ((h & 31) == 0) red[h >> 5] = ss;
    __syncthreads();
    float tot = red[0] + red[1] + red[2] + red[3];
    float xn = v * rsqrtf(tot / (float)HDIM + 1e-6f) * nw[h];
    xs[h] = xn;
    __syncthreads();
    float c = cosb[(size_t)t * HDIM + h];
    float s = sinb[(size_t)t * HDIM + h];
    float other = (h < 64) ? xs[h + 64] : xs[h - 64];
    float outv = (h < 64) ? (xn * c - other * s) : (xn * c + other * s);
    __nv_bfloat16 hh, ll;
    split_bf16(outv, hh, ll);
    if (head < NQ) {
        size_t o = ((size_t)t * NQ + head) * HDIM + h;
        g_q_h[o] = hh; g_q_l[o] = ll;
    } else {
        size_t o = ((size_t)t * NKV + (head - NQ)) * HDIM + h;
        g_k_h[o] = hh; g_k_l[o] = ll;
    }
}

// ================= flash attention, bf16x3 HMMA, 128 q-rows / 8 warps, LPT =================
#define AT_RST  272
#define QT  (128 * AT_RST)
#define KVT (64 * AT_RST)
#define AT_QH 0
#define AT_QL QT
#define AT_KH (2 * QT)
#define AT_KL (2 * QT + KVT)
#define AT_VH (2 * QT + 2 * KVT)
#define AT_VL (2 * QT + 3 * KVT)
#define AT_SMEM (2 * QT + 4 * KVT)

__device__ __forceinline__ void attn_issue_kv(uint32_t sb, int j0, int kvh, int tid)
{
    int srow = tid >> 2, sp = tid & 3;
    size_t base = ((size_t)(j0 + srow) * NKV + kvh) * HDIM + sp * 32;
    uint32_t d = (uint32_t)(srow * AT_RST + sp * 64);
#pragma unroll
    for (int i = 0; i < 4; i++) {
        CP16(sb + AT_KH + d + i * 16, g_k_h + base + i * 8);
        CP16(sb + AT_KL + d + i * 16, g_k_l + base + i * 8);
        CP16(sb + AT_VH + d + i * 16, g_v_h + base + i * 8);
        CP16(sb + AT_VL + d + i * 16, g_v_l + base + i * 8);
    }
}

__global__ void __launch_bounds__(256) attn_kernel()
{
    extern __shared__ char sm[];
    uint32_t sb = smem_u32(sm);
    int bx = gridDim.x - 1 - blockIdx.x;   // LPT: heaviest CTAs scheduled first
    int m0 = bx * 128;
    int head = blockIdx.y;
    int kvh = head >> 2;
    int tid = threadIdx.x, wid = tid >> 5, l = tid & 31;
    const float scale = 0.08838834764831843f;

    {
        int srow = tid >> 1, sp = tid & 1;
        size_t qb = ((size_t)(m0 + srow) * NQ + head) * HDIM + sp * 64;
        uint32_t d = (uint32_t)(srow * AT_RST + sp * 128);
#pragma unroll
        for (int i = 0; i < 8; i++) {
            CP16(sb + AT_QH + d + i * 16, g_q_h + qb + i * 8);
            CP16(sb + AT_QL + d + i * 16, g_q_l + qb + i * 8);
        }
    }
    attn_issue_kv(sb, 0, kvh, tid);
    CP_COMMIT();

    int a_r = (l & 7) + ((l >> 3) & 1) * 8;
    int a_c = (l >> 4) * 8;
    int b_r = (l & 7) + (l >> 4) * 8;
    int b_c = ((l >> 3) & 1) * 8;

    float o[16][4];
#pragma unroll
    for (int nd = 0; nd < 16; nd++)
#pragma unroll
        for (int j = 0; j < 4; j++) o[nd][j] = 0.f;
    float m_i0 = -1e30f, m_i1 = -1e30f, l0 = 0.f, l1 = 0.f;

    int rA_glob = m0 + wid * 16 + (l >> 2);
    int rB_glob = rA_glob + 8;

    int njt = 2 * bx + 2;
    for (int jt = 0; jt < njt; jt++) {
        CP_WAIT0();
        __syncthreads();

        float s[8][4];
#pragma unroll
        for (int ni = 0; ni < 8; ni++)
#pragma unroll
            for (int j = 0; j < 4; j++) s[ni][j] = 0.f;
#pragma unroll
        for (int ks = 0; ks < 8; ks++) {
            uint32_t qh4[4], ql4[4];
            uint32_t qa = sb + (uint32_t)((wid * 16 + a_r) * AT_RST + (ks * 16 + a_c) * 2);
            ldsm4(qh4, qa + AT_QH);
            ldsm4(ql4, qa + AT_QL);
            uint32_t kh[4][4], kl[4][4];
#pragma unroll
            for (int q2 = 0; q2 < 4; q2++) {
                uint32_t ka = sb + (uint32_t)((q2 * 16 + b_r) * AT_RST + (ks * 16 + b_c) * 2);
                ldsm4(kh[q2], ka + AT_KH);
                ldsm4(kl[q2], ka + AT_KL);
            }
#pragma unroll
            for (int q2 = 0; q2 < 4; q2++) {
                mma16816(s[2 * q2],     qh4, &kh[q2][0]);
                mma16816(s[2 * q2 + 1], qh4, &kh[q2][2]);
            }
#pragma unroll
            for (int q2 = 0; q2 < 4; q2++) {
                mma16816(s[2 * q2],     qh4, &kl[q2][0]);
                mma16816(s[2 * q2 + 1], qh4, &kl[q2][2]);
            }
#pragma unroll
            for (int q2 = 0; q2 < 4; q2++) {
                mma16816(s[2 * q2],     ql4, &kh[q2][0]);
                mma16816(s[2 * q2 + 1], ql4, &kh[q2][2]);
            }
        }
#pragma unroll
        for (int ni = 0; ni < 8; ni++)
#pragma unroll
            for (int j = 0; j < 4; j++) s[ni][j] *= scale;
        if (jt >= njt - 2) {
            int jbase = jt * 64;
#pragma unroll
            for (int ni = 0; ni < 8; ni++) {
                int c0 = jbase + ni * 8 + 2 * (l & 3), c1 = c0 + 1;
                if (c0 > rA_glob) s[ni][0] = -1e30f;
                if (c1 > rA_glob) s[ni][1] = -1e30f;
                if (c0 > rB_glob) s[ni][2] = -1e30f;
                if (c1 > rB_glob) s[ni][3] = -1e30f;
            }
        }
        float mt0 = -1e30f, mt1 = -1e30f;
#pragma unroll
        for (int ni = 0; ni < 8; ni++) {
            mt0 = fmaxf(mt0, fmaxf(s[ni][0], s[ni][1]));
            mt1 = fmaxf(mt1, fmaxf(s[ni][2], s[ni][3]));
        }
        mt0 = fmaxf(mt0, __shfl_xor_sync(0xffffffffu, mt0, 1));
        mt0 = fmaxf(mt0, __shfl_xor_sync(0xffffffffu, mt0, 2));
        mt1 = fmaxf(mt1, __shfl_xor_sync(0xffffffffu, mt1, 1));
        mt1 = fmaxf(mt1, __shfl_xor_sync(0xffffffffu, mt1, 2));
        float mn0 = fmaxf(m_i0, mt0), mn1 = fmaxf(m_i1, mt1);
        float c0 = __expf(m_i0 - mn0), c1 = __expf(m_i1 - mn1);
        l0 *= c0; l1 *= c1;
#pragma unroll
        for (int nd = 0; nd < 16; nd++) {
            o[nd][0] *= c0; o[nd][1] *= c0; o[nd][2] *= c1; o[nd][3] *= c1;
        }
        m_i0 = mn0; m_i1 = mn1;
        float rs0 = 0.f, rs1 = 0.f;
        uint32_t pha[16], pla[16];
#pragma unroll
        for (int ni = 0; ni < 8; ni++) {
            float p0 = __expf(s[ni][0] - mn0), p1 = __expf(s[ni][1] - mn0);
            float p2 = __expf(s[ni][2] - mn1), p3 = __expf(s[ni][3] - mn1);
            rs0 += p0 + p1; rs1 += p2 + p3;
            __nv_bfloat16 h0, l0b, h1, l1b, h2, l2b, h3, l3b;
            split_bf16(p0, h0, l0b); split_bf16(p1, h1, l1b);
            split_bf16(p2, h2, l2b); split_bf16(p3, h3, l3b);
            pha[2 * ni]     = pack2bf(h0, h1);
            pha[2 * ni + 1] = pack2bf(h2, h3);
            pla[2 * ni]     = pack2bf(l0b, l1b);
            pla[2 * ni + 1] = pack2bf(l2b, l3b);
        }
        rs0 += __shfl_xor_sync(0xffffffffu, rs0, 1);
        rs0 += __shfl_xor_sync(0xffffffffu, rs0, 2);
        rs1 += __shfl_xor_sync(0xffffffffu, rs1, 1);
        rs1 += __shfl_xor_sync(0xffffffffu, rs1, 2);
        l0 += rs0; l1 += rs1;

#pragma unroll
        for (int ks = 0; ks < 4; ks++) {
            const uint32_t* ph = &pha[4 * ks];
            const uint32_t* pl = &pla[4 * ks];
#pragma unroll
            for (int dp = 0; dp < 4; dp++) {
                uint32_t vh[2][4], vl[2][4];
#pragma unroll
                for (int u = 0; u < 2; u++) {
                    uint32_t va = sb + (uint32_t)((ks * 16 + a_r) * AT_RST +
                                                  ((2 * dp + u) * 16 + a_c) * 2);
                    ldsm4t(vh[u], va + AT_VH);
                    ldsm4t(vl[u], va + AT_VL);
                }
                mma16816(o[4 * dp],     ph, &vh[0][0]);
                mma16816(o[4 * dp + 1], ph, &vh[0][2]);
                mma16816(o[4 * dp + 2], ph, &vh[1][0]);
                mma16816(o[4 * dp + 3], ph, &vh[1][2]);
                mma16816(o[4 * dp],     pl, &vh[0][0]);
                mma16816(o[4 * dp + 1], pl, &vh[0][2]);
                mma16816(o[4 * dp + 2], pl, &vh[1][0]);
                mma16816(o[4 * dp + 3], pl, &vh[1][2]);
                mma16816(o[4 * dp],     ph, &vl[0][0]);
                mma16816(o[4 * dp + 1], ph, &vl[0][2]);
                mma16816(o[4 * dp + 2], ph, &vl[1][0]);
                mma16816(o[4 * dp + 3], ph, &vl[1][2]);
            }
        }
        __syncthreads();
        if (jt + 1 < njt) attn_issue_kv(sb, (jt + 1) * 64, kvh, tid);
        CP_COMMIT();
    }

    float inv0 = 1.f / l0, inv1 = 1.f / l1;
#pragma unroll
    for (int nd = 0; nd < 16; nd++) {
        int d = nd * 8 + 2 * (l & 3);
        float v0 = o[nd][0] * inv0, v1 = o[nd][1] * inv0;
        float v2 = o[nd][2] * inv1, v3 = o[nd][3] * inv1;
        __nv_bfloat16 h0, lo0, h1, lo1, h2, lo2, h3, lo3;
        split_bf16(v0, h0, lo0); split_bf16(v1, h1, lo1);
        split_bf16(v2, h2, lo2); split_bf16(v3, h3, lo3);
        size_t oA = (size_t)rA_glob * DD + head * HDIM + d;
        size_t oB = (size_t)rB_glob * DD + head * HDIM + d;
        *(uint32_t*)(g_attn_h + oA) = pack2bf(h0, h1);
        *(uint32_t*)(g_attn_l + oA) = pack2bf(lo0, lo1);
        *(uint32_t*)(g_attn_h + oB) = pack2bf(h2, h3);
        *(uint32_t*)(g_attn_l + oB) = pack2bf(lo2, lo3);
    }
}

// ================= routing =================
__global__ void zero_cnt_kernel() { if (threadIdx.x < NE) g_ecnt[threadIdx.x] = 0; }

__global__ void route_kernel(const float* __restrict__ gate_w)
{
    int t = blockIdx.x;
    int tid = threadIdx.x;
    const float* x = g_h2 + (size_t)t * DD;
    float acc[NE];
#pragma unroll
    for (int e = 0; e < NE; e++) acc[e] = 0.f;
    for (int d = tid; d < DD; d += 128) {
        float xv = x[d];
        const float* gw = gate_w + (size_t)d * NE;
#pragma unroll
        for (int e = 0; e < NE; e++) acc[e] += xv * gw[e];
    }
    __shared__ float s[NE * 128];
#pragma unroll
    for (int e = 0; e < NE; e++) s[e * 128 + tid] = acc[e];
    __syncthreads();
    __shared__ float logits[NE];
    if (tid < NE) {
        float sum = 0.f;
        for (int i = 0; i < 128; i++) sum += s[tid * 128 + i];
        logits[tid] = sum;
    }
    __syncthreads();
    if (tid == 0) {
        float mx = -1e30f;
        for (int e = 0; e < NE; e++) mx = fmaxf(mx, logits[e]);
        float p[NE], Z = 0.f;
        for (int e = 0; e < NE; e++) { p[e] = expf(logits[e] - mx); Z += p[e]; }
        for (int e = 0; e < NE; e++) p[e] /= Z;
        int idx[TOPK]; float val[TOPK]; bool used[NE] = {};
        float wsum = 0.f;
        for (int k = 0; k < TOPK; k++) {
            int best = -1; float bv = -1.f;
            for (int e = 0; e < NE; e++)
                if (!used[e] && p[e] > bv) { bv = p[e]; best = e; }
            used[best] = true; idx[k] = best; val[k] = bv; wsum += bv;
        }
        for (int k = 0; k < TOPK; k++) {
            int rowid = t * TOPK + k;
            g_rw[rowid] = val[k] / wsum;
            int e = idx[k];
            int pos = atomicAdd(&g_ecnt[e], 1);
            g_erows[e * TT + pos] = rowid;
        }
    }
}

// ================= launch =================
extern "C" void kernel_launch(void* const* d_in, const int* in_sizes, int n_in,
                              void* d_out, int out_size)
{
    const float* hidden  = (const float*)d_in[0];
    const float* cosb    = (const float*)d_in[1];
    const float* sinb    = (const float*)d_in[2];
    const float* in_ln   = (const float*)d_in[4];
    const float* post_ln = (const float*)d_in[5];
    const float* q_w     = (const float*)d_in[6];
    const float* k_w     = (const float*)d_in[7];
    const float* v_w     = (const float*)d_in[8];
    const float* o_w     = (const float*)d_in[9];
    const float* q_nw    = (const float*)d_in[10];
    const float* k_nw    = (const float*)d_in[11];
    const float* gate_w  = (const float*)d_in[12];
    const float* gup_w   = (const float*)d_in[13];
    const float* down_w  = (const float*)d_in[14];
    float* out = (float*)d_out;

    float *qkv, *hmid, *h2;
    __nv_bfloat16 *hn_h, *hn_l, *attn_h, *attn_l, *h2_h, *h2_l, *gated_h, *gated_l;
    __nv_bfloat16 *wqkv_h, *wqkv_l, *wo_h, *wo_l, *wgu_h, *wgu_l, *wdn_h, *wdn_l;
    cudaGetSymbolAddress((void**)&qkv,  g_qkv);
    cudaGetSymbolAddress((void**)&hmid, g_hmid);
    cudaGetSymbolAddress((void**)&h2,   g_h2);
    cudaGetSymbolAddress((void**)&hn_h, g_hn_h);
    cudaGetSymbolAddress((void**)&hn_l, g_hn_l);
    cudaGetSymbolAddress((void**)&attn_h, g_attn_h);
    cudaGetSymbolAddress((void**)&attn_l, g_attn_l);
    cudaGetSymbolAddress((void**)&h2_h, g_h2_h);
    cudaGetSymbolAddress((void**)&h2_l, g_h2_l);
    cudaGetSymbolAddress((void**)&gated_h, g_gated_h);
    cudaGetSymbolAddress((void**)&gated_l, g_gated_l);
    cudaGetSymbolAddress((void**)&wqkv_h, g_wqkv_h);
    cudaGetSymbolAddress((void**)&wqkv_l, g_wqkv_l);
    cudaGetSymbolAddress((void**)&wo_h,   g_wo_h);
    cudaGetSymbolAddress((void**)&wo_l,   g_wo_l);
    cudaGetSymbolAddress((void**)&wgu_h,  g_wgu_h);
    cudaGetSymbolAddress((void**)&wgu_l,  g_wgu_l);
    cudaGetSymbolAddress((void**)&wdn_h,  g_wdn_h);
    cudaGetSymbolAddress((void**)&wdn_l,  g_wdn_l);

    cudaFuncSetAttribute(bf16x3_gemm_kernel, cudaFuncAttributeMaxDynamicSharedMemorySize, GEMM_SMEM);
    cudaFuncSetAttribute(attn_kernel, cudaFuncAttributeMaxDynamicSharedMemorySize, AT_SMEM);

    // streaming weight split (gate_up column-interleaved for fused SiLU)
    wsplit_qkv_kernel<<<6144, 256>>>((const float4*)q_w, (const float4*)k_w,
                                     (const float4*)v_w, (uint2*)wqkv_h, (uint2*)wqkv_l);
    wsplit_kernel<<<4096, 256>>>((const float4*)o_w,    (uint2*)wo_h,  (uint2*)wo_l,  DD * DD / 4);
    wsplit_gu_kernel<<<32768, 256>>>((const float4*)gup_w, (uint4*)wgu_h, (uint4*)wgu_l);
    wsplit_kernel<<<32768, 256>>>((const float4*)down_w,(uint2*)wdn_h, (uint2*)wdn_l, NE * NF * DD / 4);

    // 1. pre-attn rmsnorm
    rmsnorm_kernel<<<TT, 256>>>(hidden, in_ln, nullptr, hn_h, hn_l, nullptr);
    // 2. fused QKV projection
    bf16x3_gemm_kernel<<<dim3(QKVW / 256, TT / 128), 512, GEMM_SMEM>>>(
        0, hn_h, hn_l, wqkv_h, wqkv_l, qkv, nullptr, QKVW, DD);
    // 3. per-head norm + rope + split
    normrope_kernel<<<dim3(TT, NQ + NKV + NKV), 128>>>(cosb, sinb, q_nw, k_nw);
    // 4. attention (128-row CTAs, 8 warps, LPT)
    attn_kernel<<<dim3(TT / 128, NQ), 256, AT_SMEM>>>();
    // 5. O projection + residual
    bf16x3_gemm_kernel<<<dim3(DD / 256, TT / 128), 512, GEMM_SMEM>>>(
        0, attn_h, attn_l, wo_h, wo_l, hmid, hidden, DD, DD);
    // 6. post-attn rmsnorm (+ copies hmid into out as residual init)
    rmsnorm_kernel<<<TT, 256>>>(hmid, post_ln, h2, h2_h, h2_l, out);
    // 7. routing
    zero_cnt_kernel<<<1, 32>>>();
    route_kernel<<<TT, 128>>>(gate_w);
    // 8. sparse expert GEMMs (gate_up fuses SiLU with coalesced stores)
    bf16x3_gemm_kernel<<<dim3((2 * NF) / 256, 16, NE), 512, GEMM_SMEM>>>(
        1, h2_h, h2_l, wgu_h, wgu_l, nullptr, nullptr, 2 * NF, DD);
    bf16x3_gemm_kernel<<<dim3(DD / 256, 16, NE), 512, GEMM_SMEM>>>(
        2, gated_h, gated_l, wdn_h, wdn_l, out, nullptr, DD, NF);
}

// round 15
// speedup vs baseline: 1.0799x; 1.0035x over previous
#include <cuda_runtime.h>
#include <cuda_bf16.h>
#include <math.h>
#include <stdint.h>

#define TT   2048
#define DD   2048
#define NQ   16
#define NKV  4
#define HDIM 128
#define NE   16
#define NF   1024
#define TOPK 4

#define QKVW 3072
#define KOFF 2048
#define VOFF 2560

// ---------------- scratch ----------------
__device__ float g_qkv  [TT * QKVW];
__device__ float g_hmid [TT * DD];
__device__ float g_h2   [TT * DD];
__device__ float g_rw   [TT * TOPK];
__device__ int   g_ecnt [NE];
__device__ int   g_erows[NE * TT];

__device__ __nv_bfloat16 g_hn_h   [TT * DD];
__device__ __nv_bfloat16 g_hn_l   [TT * DD];
__device__ __nv_bfloat16 g_q_h    [TT * NQ * HDIM];
__device__ __nv_bfloat16 g_q_l    [TT * NQ * HDIM];
__device__ __nv_bfloat16 g_k_h    [TT * NKV * HDIM];
__device__ __nv_bfloat16 g_k_l    [TT * NKV * HDIM];
__device__ __nv_bfloat16 g_v_h    [TT * NKV * HDIM];
__device__ __nv_bfloat16 g_v_l    [TT * NKV * HDIM];
__device__ __nv_bfloat16 g_attn_h [TT * DD];
__device__ __nv_bfloat16 g_attn_l [TT * DD];
__device__ __nv_bfloat16 g_h2_h   [TT * DD];
__device__ __nv_bfloat16 g_h2_l   [TT * DD];
__device__ __nv_bfloat16 g_gated_h[TT * TOPK * NF];
__device__ __nv_bfloat16 g_gated_l[TT * TOPK * NF];

// split-bf16 weights in NATURAL [K][N] layout (gate_up column-interleaved: 2f=gate_f, 2f+1=up_f)
__device__ __nv_bfloat16 g_wqkv_h[DD * QKVW];
__device__ __nv_bfloat16 g_wqkv_l[DD * QKVW];
__device__ __nv_bfloat16 g_wo_h  [DD * DD];
__device__ __nv_bfloat16 g_wo_l  [DD * DD];
__device__ __nv_bfloat16 g_wgu_h [NE * DD * (2 * NF)];
__device__ __nv_bfloat16 g_wgu_l [NE * DD * (2 * NF)];
__device__ __nv_bfloat16 g_wdn_h [NE * NF * DD];
__device__ __nv_bfloat16 g_wdn_l [NE * NF * DD];

// ================= helpers =================
__device__ __forceinline__ uint32_t smem_u32(const void* p) {
    uint32_t r;
    asm("{ .reg .u64 t; cvta.to.shared.u64 t, %1; cvt.u32.u64 %0, t; }" : "=r"(r) : "l"(p));
    return r;
}
__device__ __forceinline__ uint32_t pack2bf(__nv_bfloat16 a, __nv_bfloat16 b) {
    return (uint32_t)__bfloat16_as_ushort(a) | ((uint32_t)__bfloat16_as_ushort(b) << 16);
}
__device__ __forceinline__ void ldsm4(uint32_t* r, uint32_t a) {
    asm volatile("ldmatrix.sync.aligned.m8n8.x4.shared.b16 {%0,%1,%2,%3}, [%4];"
                 : "=r"(r[0]), "=r"(r[1]), "=r"(r[2]), "=r"(r[3]) : "r"(a));
}
__device__ __forceinline__ void ldsm4t(uint32_t* r, uint32_t a) {
    asm volatile("ldmatrix.sync.aligned.m8n8.x4.trans.shared.b16 {%0,%1,%2,%3}, [%4];"
                 : "=r"(r[0]), "=r"(r[1]), "=r"(r[2]), "=r"(r[3]) : "r"(a));
}
__device__ __forceinline__ void mma16816(float* c, const uint32_t* a, const uint32_t* b) {
    asm volatile("mma.sync.aligned.m16n8k16.row.col.f32.bf16.bf16.f32 "
                 "{%0,%1,%2,%3}, {%4,%5,%6,%7}, {%8,%9}, {%0,%1,%2,%3};"
                 : "+f"(c[0]), "+f"(c[1]), "+f"(c[2]), "+f"(c[3])
                 : "r"(a[0]), "r"(a[1]), "r"(a[2]), "r"(a[3]), "r"(b[0]), "r"(b[1]));
}
#define CP16(dst, src) \
    asm volatile("cp.async.cg.shared.global [%0], [%1], 16;" :: "r"(dst), "l"(src))
#define CP_COMMIT() asm volatile("cp.async.commit_group;" ::: "memory")
#define CP_WAIT1()  asm volatile("cp.async.wait_group 1;" ::: "memory")
#define CP_WAIT0()  asm volatile("cp.async.wait_group 0;" ::: "memory")

__device__ __forceinline__ void split_bf16(float v, __nv_bfloat16& h, __nv_bfloat16& l) {
    h = __float2bfloat16(v);
    l = __float2bfloat16(v - __bfloat162float(h));
}

// ================= streaming weight split =================
__global__ void wsplit_kernel(const float4* __restrict__ in,
                              uint2* __restrict__ oh, uint2* __restrict__ ol, int n4)
{
    int i = blockIdx.x * blockDim.x + threadIdx.x;
    if (i >= n4) return;
    float4 v = in[i];
    __nv_bfloat16 h0, l0, h1, l1, h2, l2, h3, l3;
    split_bf16(v.x, h0, l0); split_bf16(v.y, h1, l1);
    split_bf16(v.z, h2, l2); split_bf16(v.w, h3, l3);
    oh[i] = make_uint2(pack2bf(h0, h1), pack2bf(h2, h3));
    ol[i] = make_uint2(pack2bf(l0, l1), pack2bf(l2, l3));
}
__global__ void wsplit_qkv_kernel(const float4* __restrict__ q, const float4* __restrict__ k,
                                  const float4* __restrict__ v,
                                  uint2* __restrict__ oh, uint2* __restrict__ ol)
{
    int i = blockIdx.x * 256 + threadIdx.x;   // over 2048*768
    int row = i / 768, c4 = i % 768;
    float4 val;
    if (c4 < 512)      val = q[row * 512 + c4];
    else if (c4 < 640) val = k[row * 128 + (c4 - 512)];
    else               val = v[row * 128 + (c4 - 640)];
    __nv_bfloat16 h0, l0, h1, l1, h2, l2, h3, l3;
    split_bf16(val.x, h0, l0); split_bf16(val.y, h1, l1);
    split_bf16(val.z, h2, l2); split_bf16(val.w, h3, l3);
    oh[i] = make_uint2(pack2bf(h0, h1), pack2bf(h2, h3));
    ol[i] = make_uint2(pack2bf(l0, l1), pack2bf(l2, l3));
}
// gate_up, column-interleaved (2f=gate, 2f+1=up), fully vectorized 16B loads/stores
__global__ void wsplit_gu_kernel(const float4* __restrict__ in,   // [NE*DD][2NF/4]
                                 uint4* __restrict__ oh, uint4* __restrict__ ol)
{
    int i = blockIdx.x * 256 + threadIdx.x;   // over NE*DD*NF/4
    int per_row = NF / 4;                      // 256
    int row = i / per_row;
    int j = i % per_row;                       // f base = 4j
    const float4* base = in + (size_t)row * (2 * NF / 4);
    float4 gv = base[j];
    float4 uv = base[NF / 4 + j];
    __nv_bfloat16 gh0, gl0, gh1, gl1, gh2, gl2, gh3, gl3;
    __nv_bfloat16 uh0, ul0, uh1, ul1, uh2, ul2, uh3, ul3;
    split_bf16(gv.x, gh0, gl0); split_bf16(gv.y, gh1, gl1);
    split_bf16(gv.z, gh2, gl2); split_bf16(gv.w, gh3, gl3);
    split_bf16(uv.x, uh0, ul0); split_bf16(uv.y, uh1, ul1);
    split_bf16(uv.z, uh2, ul2); split_bf16(uv.w, uh3, ul3);
    oh[i] = make_uint4(pack2bf(gh0, uh0), pack2bf(gh1, uh1),
                       pack2bf(gh2, uh2), pack2bf(gh3, uh3));
    ol[i] = make_uint4(pack2bf(gl0, ul0), pack2bf(gl1, ul1),
                       pack2bf(gl2, ul2), pack2bf(gl3, ul3));
}

// ================= bf16x3 GEMM: 16 warps x (32x64), trans-B from [K][N] =================
#define KC 32
#define ARS 80
#define BRS 528
#define A_SZ (128 * ARS)
#define B_SZ (KC * BRS)
#define STG  (2 * A_SZ + 2 * B_SZ)
#define AH_O 0
#define AL_O A_SZ
#define BH_O (2 * A_SZ)
#define BL_O (2 * A_SZ + B_SZ)
#define EROFF (3 * STG)
#define GEMM_SMEM (EROFF + 512)
#define GRS 272                    // gated smem row stride (mode-1 epilogue)

// mode 0: dense C = A @ B (+addsrc)
// mode 1: moe gate_up, FUSED SiLU, smem-recoalesced -> g_gated_h/l (C unused)
// mode 2: moe down: atomicAdd into C[tok] * g_rw
__global__ void __launch_bounds__(512) bf16x3_gemm_kernel(
    int mode,
    const __nv_bfloat16* __restrict__ Ah, const __nv_bfloat16* __restrict__ Al,
    const __nv_bfloat16* __restrict__ Bh, const __nv_bfloat16* __restrict__ Bl,
    float* __restrict__ C, const float* __restrict__ addsrc, int N, int K)
{
    int e  = blockIdx.z;
    int m0 = blockIdx.y * 128;
    int n0 = blockIdx.x * 256;
    int cnt = 0;
    if (mode != 0) {
        cnt = g_ecnt[e];
        if (m0 >= cnt) return;
        Bh += (size_t)e * K * N;
        Bl += (size_t)e * K * N;
    }
    extern __shared__ char sm[];
    uint32_t sb = smem_u32(sm);
    int tid = threadIdx.x, wid = tid >> 5, l = tid & 31;
    int* erows_s = (int*)(sm + EROFF);
    if (mode != 0 && tid < 128)
        erows_s[tid] = (m0 + tid < cnt) ? g_erows[e * TT + m0 + tid] : 0;
    __syncthreads();

    int arow = tid >> 2, apart = tid & 3;
    size_t aro;
    if (mode == 0)      aro = (size_t)(m0 + arow) * K;
    else if (mode == 1) aro = (size_t)(erows_s[arow] >> 2) * DD;
    else                aro = (size_t)erows_s[arow] * NF;
    const __nv_bfloat16* aph = Ah + aro + apart * 8;
    const __nv_bfloat16* apl = Al + aro + apart * 8;
    uint32_t a_dst = (uint32_t)(arow * ARS + apart * 16);

    int brow = tid >> 4, bpart = tid & 15;
    size_t bo = (size_t)brow * N + n0 + bpart * 16;
    uint32_t b_dst = (uint32_t)(brow * BRS + bpart * 32);

    int NC = K / KC;

    int wm = wid >> 2, wn = wid & 3;
    int a_r = (l & 7) + ((l >> 3) & 1) * 8;
    int a_c = (l >> 4) * 8;
    uint32_t a_base = (uint32_t)((wm * 32 + a_r) * ARS + a_c * 2);
    uint32_t b_base = (uint32_t)(a_r * BRS + (wn * 64 + a_c) * 2);

    float acc[2][8][4];
#pragma unroll
    for (int mi = 0; mi < 2; mi++)
#pragma unroll
        for (int ni = 0; ni < 8; ni++)
#pragma unroll
            for (int j = 0; j < 4; j++) acc[mi][ni][j] = 0.f;

#pragma unroll
    for (int p = 0; p < 2; p++) {
        if (p < NC) {
            uint32_t st = sb + p * STG;
            int k0 = p * KC;
            CP16(st + AH_O + a_dst, aph + k0);
            CP16(st + AL_O + a_dst, apl + k0);
            const __nv_bfloat16* bsh = Bh + bo + (size_t)k0 * N;
            const __nv_bfloat16* bsl = Bl + bo + (size_t)k0 * N;
            CP16(st + BH_O + b_dst,      bsh);
            CP16(st + BH_O + b_dst + 16, bsh + 8);
            CP16(st + BL_O + b_dst,      bsl);
            CP16(st + BL_O + b_dst + 16, bsl + 8);
        }
        CP_COMMIT();
    }

    for (int c = 0; c < NC; c++) {
        if (c + 1 < NC) CP_WAIT1(); else CP_WAIT0();
        __syncthreads();
        if (c + 2 < NC) {
            int n2 = c + 2;
            uint32_t st = sb + (n2 % 3) * STG;
            int k0 = n2 * KC;
            CP16(st + AH_O + a_dst, aph + k0);
            CP16(st + AL_O + a_dst, apl + k0);
            const __nv_bfloat16* bsh = Bh + bo + (size_t)k0 * N;
            const __nv_bfloat16* bsl = Bl + bo + (size_t)k0 * N;
            CP16(st + BH_O + b_dst,      bsh);
            CP16(st + BH_O + b_dst + 16, bsh + 8);
            CP16(st + BL_O + b_dst,      bsl);
            CP16(st + BL_O + b_dst + 16, bsl + 8);
        }
        CP_COMMIT();

        uint32_t st = sb + (c % 3) * STG;
#pragma unroll
        for (int kk = 0; kk < 2; kk++) {
            uint32_t bh[4][4], bl[4][4];
#pragma unroll
            for (int q = 0; q < 4; q++)
                ldsm4t(bh[q], st + BH_O + b_base + kk * (16 * BRS) + q * 32);
#pragma unroll
            for (int q = 0; q < 4; q++)
                ldsm4t(bl[q], st + BL_O + b_base + kk * (16 * BRS) + q * 32);
#pragma unroll
            for (int mi = 0; mi < 2; mi++) {
                uint32_t ah[4], al[4];
                ldsm4(ah, st + AH_O + a_base + mi * (16 * ARS) + kk * 32);
                ldsm4(al, st + AL_O + a_base + mi * (16 * ARS) + kk * 32);
#pragma unroll
                for (int q = 0; q < 4; q++) {
                    mma16816(acc[mi][2 * q],     ah, &bh[q][0]);
                    mma16816(acc[mi][2 * q + 1], ah, &bh[q][2]);
                }
#pragma unroll
                for (int q = 0; q < 4; q++) {
                    mma16816(acc[mi][2 * q],     ah, &bl[q][0]);
                    mma16816(acc[mi][2 * q + 1], ah, &bl[q][2]);
                }
#pragma unroll
                for (int q = 0; q < 4; q++) {
                    mma16816(acc[mi][2 * q],     al, &bh[q][0]);
                    mma16816(acc[mi][2 * q + 1], al, &bh[q][2]);
                }
            }
        }
    }

    int g = l >> 2, tig = l & 3;

    if (mode == 1) {
        // ---- fused SiLU epilogue with smem re-coalescing ----
        __syncthreads();
#pragma unroll
        for (int mi = 0; mi < 2; mi++) {
            int r0 = wm * 32 + mi * 16 + g;
            int r1 = r0 + 8;
#pragma unroll
            for (int ni = 0; ni < 8; ni++) {
                int f_loc = wn * 32 + ni * 4 + tig;   // 0..127
                float* a = acc[mi][ni];
                float gt0 = a[0];
                float gd0 = a[1] * (gt0 / (1.f + __expf(-gt0)));
                float gt1 = a[2];
                float gd1 = a[3] * (gt1 / (1.f + __expf(-gt1)));
                __nv_bfloat16 h0, lo0, h1, lo1;
                split_bf16(gd0, h0, lo0);
                split_bf16(gd1, h1, lo1);
                *(__nv_bfloat16*)(sm + r0 * GRS + f_loc * 2)             = h0;
                *(__nv_bfloat16*)(sm + 128 * GRS + r0 * GRS + f_loc * 2) = lo0;
                *(__nv_bfloat16*)(sm + r1 * GRS + f_loc * 2)             = h1;
                *(__nv_bfloat16*)(sm + 128 * GRS + r1 * GRS + f_loc * 2) = lo1;
            }
        }
        __syncthreads();
        int fb = n0 >> 1;
        for (int it = tid; it < 2048; it += 512) {
            int row = it >> 4, seg = it & 15;
            if (m0 + row < cnt) {
                int rowid = erows_s[row];
                uint4 vh = *(uint4*)(sm + row * GRS + seg * 16);
                uint4 vl = *(uint4*)(sm + 128 * GRS + row * GRS + seg * 16);
                *(uint4*)(g_gated_h + (size_t)rowid * NF + fb + seg * 8) = vh;
                *(uint4*)(g_gated_l + (size_t)rowid * NF + fb + seg * 8) = vl;
            }
        }
        return;
    }

    // ---- standard epilogue (mode 0 / 2) ----
#pragma unroll
    for (int mi = 0; mi < 2; mi++) {
        int r0 = wm * 32 + mi * 16 + g;
        int r1 = r0 + 8;
        bool v0 = true, v1 = true;
        size_t ro0 = 0, ro1 = 0;
        float w0 = 0.f, w1 = 0.f;
        if (mode == 0) {
            ro0 = (size_t)(m0 + r0) * N;
            ro1 = (size_t)(m0 + r1) * N;
        } else {
            v0 = (m0 + r0) < cnt;
            v1 = (m0 + r1) < cnt;
            int rowid0 = erows_s[r0], rowid1 = erows_s[r1];
            ro0 = (size_t)(rowid0 >> 2) * DD;
            ro1 = (size_t)(rowid1 >> 2) * DD;
            if (v0) w0 = g_rw[rowid0];
            if (v1) w1 = g_rw[rowid1];
        }
#pragma unroll
        for (int ni = 0; ni < 8; ni++) {
            int cc = n0 + wn * 64 + ni * 8 + tig * 2;
            float* a = acc[mi][ni];
            if (mode == 0) {
                if (addsrc) {
                    float2 s0 = *(const float2*)(addsrc + ro0 + cc);
                    float2 s1 = *(const float2*)(addsrc + ro1 + cc);
                    *(float2*)(C + ro0 + cc) = make_float2(a[0] + s0.x, a[1] + s0.y);
                    *(float2*)(C + ro1 + cc) = make_float2(a[2] + s1.x, a[3] + s1.y);
                } else {
                    *(float2*)(C + ro0 + cc) = make_float2(a[0], a[1]);
                    *(float2*)(C + ro1 + cc) = make_float2(a[2], a[3]);
                }
            } else {
                if (v0) { atomicAdd(C + ro0 + cc, w0 * a[0]); atomicAdd(C + ro0 + cc + 1, w0 * a[1]); }
                if (v1) { atomicAdd(C + ro1 + cc, w1 * a[2]); atomicAdd(C + ro1 + cc + 1, w1 * a[3]); }
            }
        }
    }
}

// ================= RMSNorm (split-bf16 + optional fp32 out + optional passthrough copy) =================
__global__ void rmsnorm_kernel(const float* __restrict__ x,
                               const float* __restrict__ w,
                               float* __restrict__ ofp,
                               __nv_bfloat16* __restrict__ oh,
                               __nv_bfloat16* __restrict__ ol,
                               float* __restrict__ ocopy)
{
    int t = blockIdx.x;
    const float4* xr = (const float4*)(x + (size_t)t * DD);
    const float4* wr = (const float4*)w;
    int tid = threadIdx.x;
    float4 v0 = xr[tid], v1 = xr[tid + 256];
    if (ocopy) {
        float4* orow = (float4*)(ocopy + (size_t)t * DD);
        orow[tid] = v0; orow[tid + 256] = v1;
    }
    float ss = v0.x*v0.x + v0.y*v0.y + v0.z*v0.z + v0.w*v0.w
             + v1.x*v1.x + v1.y*v1.y + v1.z*v1.z + v1.w*v1.w;
#pragma unroll
    for (int o = 16; o; o >>= 1) ss += __shfl_xor_sync(0xffffffffu, ss, o);
    __shared__ float red[8];
    if ((tid & 31) == 0) red[tid >> 5] = ss;
    __syncthreads();
    float tot = red[0]+red[1]+red[2]+red[3]+red[4]+red[5]+red[6]+red[7];
    float r = rsqrtf(tot / (float)DD + 1e-6f);
    float4 w0 = wr[tid], w1 = wr[tid + 256];
    float4 o0, o1;
    o0.x = v0.x*r*w0.x; o0.y = v0.y*r*w0.y; o0.z = v0.z*r*w0.z; o0.w = v0.w*r*w0.w;
    o1.x = v1.x*r*w1.x; o1.y = v1.y*r*w1.y; o1.z = v1.z*r*w1.z; o1.w = v1.w*r*w1.w;
    if (ofp) {
        float4* orow = (float4*)(ofp + (size_t)t * DD);
        orow[tid] = o0; orow[tid + 256] = o1;
    }
    __nv_bfloat16 h[8], lo[8];
    split_bf16(o0.x, h[0], lo[0]); split_bf16(o0.y, h[1], lo[1]);
    split_bf16(o0.z, h[2], lo[2]); split_bf16(o0.w, h[3], lo[3]);
    split_bf16(o1.x, h[4], lo[4]); split_bf16(o1.y, h[5], lo[5]);
    split_bf16(o1.z, h[6], lo[6]); split_bf16(o1.w, h[7], lo[7]);
    uint2* ohr = (uint2*)(oh + (size_t)t * DD);
    uint2* olr = (uint2*)(ol + (size_t)t * DD);
    ohr[tid]       = make_uint2(pack2bf(h[0], h[1]),  pack2bf(h[2], h[3]));
    ohr[tid + 256] = make_uint2(pack2bf(h[4], h[5]),  pack2bf(h[6], h[7]));
    olr[tid]       = make_uint2(pack2bf(lo[0], lo[1]), pack2bf(lo[2], lo[3]));
    olr[tid + 256] = make_uint2(pack2bf(lo[4], lo[5]), pack2bf(lo[6], lo[7]));
}

// ================= per-head RMSNorm + RoPE + split =================
__global__ void normrope_kernel(const float* __restrict__ cosb,
                                const float* __restrict__ sinb,
                                const float* __restrict__ qnw,
                                const float* __restrict__ knw)
{
    int t = blockIdx.x;
    int head = blockIdx.y;      // 0..15 q, 16..19 k, 20..23 v
    int h = threadIdx.x;
    if (head >= 20) {
        int kvh = head - 20;
        float v = g_qkv[(size_t)t * QKVW + VOFF + kvh * HDIM + h];
        __nv_bfloat16 hh, ll;
        split_bf16(v, hh, ll);
        size_t o = ((size_t)t * NKV + kvh) * HDIM + h;
        g_v_h[o] = hh; g_v_l[o] = ll;
        return;
    }
    const float* src;
    const float* nw;
    if (head < NQ) { src = g_qkv + (size_t)t * QKVW + head * HDIM;               nw = qnw; }
    else           { src = g_qkv + (size_t)t * QKVW + KOFF + (head - NQ) * HDIM; nw = knw; }
    float v = src[h];
    float ss = v * v;
#pragma unroll
    for (int o = 16; o; o >>= 1) ss += __shfl_xor_sync(0xffffffffu, ss, o);
    __shared__ float red[4];
    __shared__ float xs[128];
    if ((h & 31) == 0) red[h >> 5] = ss;
    __syncthreads();
    float tot = red[0] + red[1] + red[2] + red[3];
    float xn = v * rsqrtf(tot / (float)HDIM + 1e-6f) * nw[h];
    xs[h] = xn;
    __syncthreads();
    float c = cosb[(size_t)t * HDIM + h];
    float s = sinb[(size_t)t * HDIM + h];
    float other = (h < 64) ? xs[h + 64] : xs[h - 64];
    float outv = (h < 64) ? (xn * c - other * s) : (xn * c + other * s);
    __nv_bfloat16 hh, ll;
    split_bf16(outv, hh, ll);
    if (head < NQ) {
        size_t o = ((size_t)t * NQ + head) * HDIM + h;
        g_q_h[o] = hh; g_q_l[o] = ll;
    } else {
        size_t o = ((size_t)t * NKV + (head - NQ)) * HDIM + h;
        g_k_h[o] = hh; g_k_l[o] = ll;
    }
}

// ================= flash attention, bf16x3 HMMA, 128 q-rows / 8 warps, LPT, KV double-buffer =================
#define AT_RST  272
#define QT  (128 * AT_RST)
#define KVT (64 * AT_RST)
#define AT_QH 0
#define AT_QL QT
#define AT_KV0 (2 * QT)              // buffer b at AT_KV0 + b*4*KVT: KH, KL, VH, VL
#define AT_SMEM (2 * QT + 8 * KVT)   // 208896

__device__ __forceinline__ void attn_issue_kv(uint32_t sb, int j0, int kvh, int tid, int buf)
{
    uint32_t kb = sb + AT_KV0 + buf * (4 * KVT);
    int srow = tid >> 2, sp = tid & 3;
    size_t base = ((size_t)(j0 + srow) * NKV + kvh) * HDIM + sp * 32;
    uint32_t d = (uint32_t)(srow * AT_RST + sp * 64);
#pragma unroll
    for (int i = 0; i < 4; i++) {
        CP16(kb + d + i * 16,           g_k_h + base + i * 8);
        CP16(kb + KVT + d + i * 16,     g_k_l + base + i * 8);
        CP16(kb + 2 * KVT + d + i * 16, g_v_h + base + i * 8);
        CP16(kb + 3 * KVT + d + i * 16, g_v_l + base + i * 8);
    }
}

__global__ void __launch_bounds__(256) attn_kernel()
{
    extern __shared__ char sm[];
    uint32_t sb = smem_u32(sm);
    int bx = gridDim.x - 1 - blockIdx.x;   // LPT: heaviest CTAs scheduled first
    int m0 = bx * 128;
    int head = blockIdx.y;
    int kvh = head >> 2;
    int tid = threadIdx.x, wid = tid >> 5, l = tid & 31;
    const float scale = 0.08838834764831843f;

    int njt = 2 * bx + 2;

    {
        int srow = tid >> 1, sp = tid & 1;
        size_t qb = ((size_t)(m0 + srow) * NQ + head) * HDIM + sp * 64;
        uint32_t d = (uint32_t)(srow * AT_RST + sp * 128);
#pragma unroll
        for (int i = 0; i < 8; i++) {
            CP16(sb + AT_QH + d + i * 16, g_q_h + qb + i * 8);
            CP16(sb + AT_QL + d + i * 16, g_q_l + qb + i * 8);
        }
    }
    attn_issue_kv(sb, 0, kvh, tid, 0);
    CP_COMMIT();
    if (njt > 1) { attn_issue_kv(sb, 64, kvh, tid, 1); CP_COMMIT(); }

    int a_r = (l & 7) + ((l >> 3) & 1) * 8;
    int a_c = (l >> 4) * 8;
    int b_r = (l & 7) + (l >> 4) * 8;
    int b_c = ((l >> 3) & 1) * 8;

    float o[16][4];
#pragma unroll
    for (int nd = 0; nd < 16; nd++)
#pragma unroll
        for (int j = 0; j < 4; j++) o[nd][j] = 0.f;
    float m_i0 = -1e30f, m_i1 = -1e30f, l0 = 0.f, l1 = 0.f;

    int rA_glob = m0 + wid * 16 + (l >> 2);
    int rB_glob = rA_glob + 8;

    for (int jt = 0; jt < njt; jt++) {
        if (jt + 1 < njt) CP_WAIT1(); else CP_WAIT0();
        __syncthreads();
        uint32_t kb = sb + AT_KV0 + (jt & 1) * (4 * KVT);

        float s[8][4];
#pragma unroll
        for (int ni = 0; ni < 8; ni++)
#pragma unroll
            for (int j = 0; j < 4; j++) s[ni][j] = 0.f;
#pragma unroll
        for (int ks = 0; ks < 8; ks++) {
            uint32_t qh4[4], ql4[4];
            uint32_t qa = sb + (uint32_t)((wid * 16 + a_r) * AT_RST + (ks * 16 + a_c) * 2);
            ldsm4(qh4, qa + AT_QH);
            ldsm4(ql4, qa + AT_QL);
            uint32_t kh[4][4], kl[4][4];
#pragma unroll
            for (int q2 = 0; q2 < 4; q2++) {
                uint32_t ka = kb + (uint32_t)((q2 * 16 + b_r) * AT_RST + (ks * 16 + b_c) * 2);
                ldsm4(kh[q2], ka);
                ldsm4(kl[q2], ka + KVT);
            }
#pragma unroll
            for (int q2 = 0; q2 < 4; q2++) {
                mma16816(s[2 * q2],     qh4, &kh[q2][0]);
                mma16816(s[2 * q2 + 1], qh4, &kh[q2][2]);
            }
#pragma unroll
            for (int q2 = 0; q2 < 4; q2++) {
                mma16816(s[2 * q2],     qh4, &kl[q2][0]);
                mma16816(s[2 * q2 + 1], qh4, &kl[q2][2]);
            }
#pragma unroll
            for (int q2 = 0; q2 < 4; q2++) {
                mma16816(s[2 * q2],     ql4, &kh[q2][0]);
                mma16816(s[2 * q2 + 1], ql4, &kh[q2][2]);
            }
        }
#pragma unroll
        for (int ni = 0; ni < 8; ni++)
#pragma unroll
            for (int j = 0; j < 4; j++) s[ni][j] *= scale;
        if (jt >= njt - 2) {
            int jbase = jt * 64;
#pragma unroll
            for (int ni = 0; ni < 8; ni++) {
                int c0 = jbase + ni * 8 + 2 * (l & 3), c1 = c0 + 1;
                if (c0 > rA_glob) s[ni][0] = -1e30f;
                if (c1 > rA_glob) s[ni][1] = -1e30f;
                if (c0 > rB_glob) s[ni][2] = -1e30f;
                if (c1 > rB_glob) s[ni][3] = -1e30f;
            }
        }
        float mt0 = -1e30f, mt1 = -1e30f;
#pragma unroll
        for (int ni = 0; ni < 8; ni++) {
            mt0 = fmaxf(mt0, fmaxf(s[ni][0], s[ni][1]));
            mt1 = fmaxf(mt1, fmaxf(s[ni][2], s[ni][3]));
        }
        mt0 = fmaxf(mt0, __shfl_xor_sync(0xffffffffu, mt0, 1));
        mt0 = fmaxf(mt0, __shfl_xor_sync(0xffffffffu, mt0, 2));
        mt1 = fmaxf(mt1, __shfl_xor_sync(0xffffffffu, mt1, 1));
        mt1 = fmaxf(mt1, __shfl_xor_sync(0xffffffffu, mt1, 2));
        float mn0 = fmaxf(m_i0, mt0), mn1 = fmaxf(m_i1, mt1);
        float c0 = __expf(m_i0 - mn0), c1 = __expf(m_i1 - mn1);
        l0 *= c0; l1 *= c1;
#pragma unroll
        for (int nd = 0; nd < 16; nd++) {
            o[nd][0] *= c0; o[nd][1] *= c0; o[nd][2] *= c1; o[nd][3] *= c1;
        }
        m_i0 = mn0; m_i1 = mn1;
        float rs0 = 0.f, rs1 = 0.f;
        uint32_t pha[16], pla[16];
#pragma unroll
        for (int ni = 0; ni < 8; ni++) {
            float p0 = __expf(s[ni][0] - mn0), p1 = __expf(s[ni][1] - mn0);
            float p2 = __expf(s[ni][2] - mn1), p3 = __expf(s[ni][3] - mn1);
            rs0 += p0 + p1; rs1 += p2 + p3;
            __nv_bfloat16 h0, l0b, h1, l1b, h2, l2b, h3, l3b;
            split_bf16(p0, h0, l0b); split_bf16(p1, h1, l1b);
            split_bf16(p2, h2, l2b); split_bf16(p3, h3, l3b);
            pha[2 * ni]     = pack2bf(h0, h1);
            pha[2 * ni + 1] = pack2bf(h2, h3);
            pla[2 * ni]     = pack2bf(l0b, l1b);
            pla[2 * ni + 1] = pack2bf(l2b, l3b);
        }
        rs0 += __shfl_xor_sync(0xffffffffu, rs0, 1);
        rs0 += __shfl_xor_sync(0xffffffffu, rs0, 2);
        rs1 += __shfl_xor_sync(0xffffffffu, rs1, 1);
        rs1 += __shfl_xor_sync(0xffffffffu, rs1, 2);
        l0 += rs0; l1 += rs1;

#pragma unroll
        for (int ks = 0; ks < 4; ks++) {
            const uint32_t* ph = &pha[4 * ks];
            const uint32_t* pl = &pla[4 * ks];
#pragma unroll
            for (int dp = 0; dp < 4; dp++) {
                uint32_t vh[2][4], vl[2][4];
#pragma unroll
                for (int u = 0; u < 2; u++) {
                    uint32_t va = kb + 2 * KVT + (uint32_t)((ks * 16 + a_r) * AT_RST +
                                                            ((2 * dp + u) * 16 + a_c) * 2);
                    ldsm4t(vh[u], va);
                    ldsm4t(vl[u], va + KVT);
                }
                mma16816(o[4 * dp],     ph, &vh[0][0]);
                mma16816(o[4 * dp + 1], ph, &vh[0][2]);
                mma16816(o[4 * dp + 2], ph, &vh[1][0]);
                mma16816(o[4 * dp + 3], ph, &vh[1][2]);
                mma16816(o[4 * dp],     pl, &vh[0][0]);
                mma16816(o[4 * dp + 1], pl, &vh[0][2]);
                mma16816(o[4 * dp + 2], pl, &vh[1][0]);
                mma16816(o[4 * dp + 3], pl, &vh[1][2]);
                mma16816(o[4 * dp],     ph, &vl[0][0]);
                mma16816(o[4 * dp + 1], ph, &vl[0][2]);
                mma16816(o[4 * dp + 2], ph, &vl[1][0]);
                mma16816(o[4 * dp + 3], ph, &vl[1][2]);
            }
        }
        __syncthreads();   // all warps done reading buffer (jt&1) before refilling it
        if (jt + 2 < njt) { attn_issue_kv(sb, (jt + 2) * 64, kvh, tid, jt & 1); CP_COMMIT(); }
    }

    float inv0 = 1.f / l0, inv1 = 1.f / l1;
#pragma unroll
    for (int nd = 0; nd < 16; nd++) {
        int d = nd * 8 + 2 * (l & 3);
        float v0 = o[nd][0] * inv0, v1 = o[nd][1] * inv0;
        float v2 = o[nd][2] * inv1, v3 = o[nd][3] * inv1;
        __nv_bfloat16 h0, lo0, h1, lo1, h2, lo2, h3, lo3;
        split_bf16(v0, h0, lo0); split_bf16(v1, h1, lo1);
        split_bf16(v2, h2, lo2); split_bf16(v3, h3, lo3);
        size_t oA = (size_t)rA_glob * DD + head * HDIM + d;
        size_t oB = (size_t)rB_glob * DD + head * HDIM + d;
        *(uint32_t*)(g_attn_h + oA) = pack2bf(h0, h1);
        *(uint32_t*)(g_attn_l + oA) = pack2bf(lo0, lo1);
        *(uint32_t*)(g_attn_h + oB) = pack2bf(h2, h3);
        *(uint32_t*)(g_attn_l + oB) = pack2bf(lo2, lo3);
    }
}

// ================= routing =================
__global__ void zero_cnt_kernel() { if (threadIdx.x < NE) g_ecnt[threadIdx.x] = 0; }

__global__ void route_kernel(const float* __restrict__ gate_w)
{
    int t = blockIdx.x;
    int tid = threadIdx.x;
    const float* x = g_h2 + (size_t)t * DD;
    float acc[NE];
#pragma unroll
    for (int e = 0; e < NE; e++) acc[e] = 0.f;
    for (int d = tid; d < DD; d += 128) {
        float xv = x[d];
        const float* gw = gate_w + (size_t)d * NE;
#pragma unroll
        for (int e = 0; e < NE; e++) acc[e] += xv * gw[e];
    }
    __shared__ float s[NE * 128];
#pragma unroll
    for (int e = 0; e < NE; e++) s[e * 128 + tid] = acc[e];
    __syncthreads();
    __shared__ float logits[NE];
    if (tid < NE) {
        float sum = 0.f;
        for (int i = 0; i < 128; i++) sum += s[tid * 128 + i];
        logits[tid] = sum;
    }
    __syncthreads();
    if (tid == 0) {
        float mx = -1e30f;
        for (int e = 0; e < NE; e++) mx = fmaxf(mx, logits[e]);
        float p[NE], Z = 0.f;
        for (int e = 0; e < NE; e++) { p[e] = expf(logits[e] - mx); Z += p[e]; }
        for (int e = 0; e < NE; e++) p[e] /= Z;
        int idx[TOPK]; float val[TOPK]; bool used[NE] = {};
        float wsum = 0.f;
        for (int k = 0; k < TOPK; k++) {
            int best = -1; float bv = -1.f;
            for (int e = 0; e < NE; e++)
                if (!used[e] && p[e] > bv) { bv = p[e]; best = e; }
            used[best] = true; idx[k] = best; val[k] = bv; wsum += bv;
        }
        for (int k = 0; k < TOPK; k++) {
            int rowid = t * TOPK + k;
            g_rw[rowid] = val[k] / wsum;
            int e = idx[k];
            int pos = atomicAdd(&g_ecnt[e], 1);
            g_erows[e * TT + pos] = rowid;
        }
    }
}

// ================= launch =================
extern "C" void kernel_launch(void* const* d_in, const int* in_sizes, int n_in,
                              void* d_out, int out_size)
{
    const float* hidden  = (const float*)d_in[0];
    const float* cosb    = (const float*)d_in[1];
    const float* sinb    = (const float*)d_in[2];
    const float* in_ln   = (const float*)d_in[4];
    const float* post_ln = (const float*)d_in[5];
    const float* q_w     = (const float*)d_in[6];
    const float* k_w     = (const float*)d_in[7];
    const float* v_w     = (const float*)d_in[8];
    const float* o_w     = (const float*)d_in[9];
    const float* q_nw    = (const float*)d_in[10];
    const float* k_nw    = (const float*)d_in[11];
    const float* gate_w  = (const float*)d_in[12];
    const float* gup_w   = (const float*)d_in[13];
    const float* down_w  = (const float*)d_in[14];
    float* out = (float*)d_out;

    float *qkv, *hmid, *h2;
    __nv_bfloat16 *hn_h, *hn_l, *attn_h, *attn_l, *h2_h, *h2_l, *gated_h, *gated_l;
    __nv_bfloat16 *wqkv_h, *wqkv_l, *wo_h, *wo_l, *wgu_h, *wgu_l, *wdn_h, *wdn_l;
    cudaGetSymbolAddress((void**)&qkv,  g_qkv);
    cudaGetSymbolAddress((void**)&hmid, g_hmid);
    cudaGetSymbolAddress((void**)&h2,   g_h2);
    cudaGetSymbolAddress((void**)&hn_h, g_hn_h);
    cudaGetSymbolAddress((void**)&hn_l, g_hn_l);
    cudaGetSymbolAddress((void**)&attn_h, g_attn_h);
    cudaGetSymbolAddress((void**)&attn_l, g_attn_l);
    cudaGetSymbolAddress((void**)&h2_h, g_h2_h);
    cudaGetSymbolAddress((void**)&h2_l, g_h2_l);
    cudaGetSymbolAddress((void**)&gated_h, g_gated_h);
    cudaGetSymbolAddress((void**)&gated_l, g_gated_l);
    cudaGetSymbolAddress((void**)&wqkv_h, g_wqkv_h);
    cudaGetSymbolAddress((void**)&wqkv_l, g_wqkv_l);
    cudaGetSymbolAddress((void**)&wo_h,   g_wo_h);
    cudaGetSymbolAddress((void**)&wo_l,   g_wo_l);
    cudaGetSymbolAddress((void**)&wgu_h,  g_wgu_h);
    cudaGetSymbolAddress((void**)&wgu_l,  g_wgu_l);
    cudaGetSymbolAddress((void**)&wdn_h,  g_wdn_h);
    cudaGetSymbolAddress((void**)&wdn_l,  g_wdn_l);

    cudaFuncSetAttribute(bf16x3_gemm_kernel, cudaFuncAttributeMaxDynamicSharedMemorySize, GEMM_SMEM);
    cudaFuncSetAttribute(attn_kernel, cudaFuncAttributeMaxDynamicSharedMemorySize, AT_SMEM);

    // streaming weight split (gate_up column-interleaved for fused SiLU)
    wsplit_qkv_kernel<<<6144, 256>>>((const float4*)q_w, (const float4*)k_w,
                                     (const float4*)v_w, (uint2*)wqkv_h, (uint2*)wqkv_l);
    wsplit_kernel<<<4096, 256>>>((const float4*)o_w,    (uint2*)wo_h,  (uint2*)wo_l,  DD * DD / 4);
    wsplit_gu_kernel<<<32768, 256>>>((const float4*)gup_w, (uint4*)wgu_h, (uint4*)wgu_l);
    wsplit_kernel<<<32768, 256>>>((const float4*)down_w,(uint2*)wdn_h, (uint2*)wdn_l, NE * NF * DD / 4);

    // 1. pre-attn rmsnorm
    rmsnorm_kernel<<<TT, 256>>>(hidden, in_ln, nullptr, hn_h, hn_l, nullptr);
    // 2. fused QKV projection
    bf16x3_gemm_kernel<<<dim3(QKVW / 256, TT / 128), 512, GEMM_SMEM>>>(
        0, hn_h, hn_l, wqkv_h, wqkv_l, qkv, nullptr, QKVW, DD);
    // 3. per-head norm + rope + split
    normrope_kernel<<<dim3(TT, NQ + NKV + NKV), 128>>>(cosb, sinb, q_nw, k_nw);
    // 4. attention (128-row CTAs, 8 warps, LPT, double-buffered KV)
    attn_kernel<<<dim3(TT / 128, NQ), 256, AT_SMEM>>>();
    // 5. O projection + residual
    bf16x3_gemm_kernel<<<dim3(DD / 256, TT / 128), 512, GEMM_SMEM>>>(
        0, attn_h, attn_l, wo_h, wo_l, hmid, hidden, DD, DD);
    // 6. post-attn rmsnorm (+ copies hmid into out as residual init)
    rmsnorm_kernel<<<TT, 256>>>(hmid, post_ln, h2, h2_h, h2_l, out);
    // 7. routing
    zero_cnt_kernel<<<1, 32>>>();
    route_kernel<<<TT, 128>>>(gate_w);
    // 8. sparse expert GEMMs (gate_up fuses SiLU with coalesced stores)
    bf16x3_gemm_kernel<<<dim3((2 * NF) / 256, 16, NE), 512, GEMM_SMEM>>>(
        1, h2_h, h2_l, wgu_h, wgu_l, nullptr, nullptr, 2 * NF, DD);
    bf16x3_gemm_kernel<<<dim3(DD / 256, 16, NE), 512, GEMM_SMEM>>>(
        2, gated_h, gated_l, wdn_h, wdn_l, out, nullptr, DD, NF);
}

// round 16
// speedup vs baseline: 1.0806x; 1.0007x over previous
#include <cuda_runtime.h>
#include <cuda_bf16.h>
#include <math.h>
#include <stdint.h>

#define TT   2048
#define DD   2048
#define NQ   16
#define NKV  4
#define HDIM 128
#define NE   16
#define NF   1024
#define TOPK 4

#define QKVW 3072
#define KOFF 2048
#define VOFF 2560

// ---------------- scratch ----------------
__device__ float g_qkv  [TT * QKVW];
__device__ float g_hmid [TT * DD];
__device__ float g_h2   [TT * DD];
__device__ float g_rw   [TT * TOPK];
__device__ int   g_ecnt [NE];
__device__ int   g_erows[NE * TT];

__device__ __nv_bfloat16 g_hn_h   [TT * DD];
__device__ __nv_bfloat16 g_hn_l   [TT * DD];
__device__ __nv_bfloat16 g_q_h    [TT * NQ * HDIM];
__device__ __nv_bfloat16 g_q_l    [TT * NQ * HDIM];
__device__ __nv_bfloat16 g_k_h    [TT * NKV * HDIM];
__device__ __nv_bfloat16 g_k_l    [TT * NKV * HDIM];
__device__ __nv_bfloat16 g_v_h    [TT * NKV * HDIM];
__device__ __nv_bfloat16 g_v_l    [TT * NKV * HDIM];
__device__ __nv_bfloat16 g_attn_h [TT * DD];
__device__ __nv_bfloat16 g_attn_l [TT * DD];
__device__ __nv_bfloat16 g_h2_h   [TT * DD];
__device__ __nv_bfloat16 g_h2_l   [TT * DD];
__device__ __nv_bfloat16 g_gated_h[TT * TOPK * NF];
__device__ __nv_bfloat16 g_gated_l[TT * TOPK * NF];

// split-bf16 weights in NATURAL [K][N] layout (gate_up column-interleaved: 2f=gate_f, 2f+1=up_f)
__device__ __nv_bfloat16 g_wqkv_h[DD * QKVW];
__device__ __nv_bfloat16 g_wqkv_l[DD * QKVW];
__device__ __nv_bfloat16 g_wo_h  [DD * DD];
__device__ __nv_bfloat16 g_wo_l  [DD * DD];
__device__ __nv_bfloat16 g_wgu_h [NE * DD * (2 * NF)];
__device__ __nv_bfloat16 g_wgu_l [NE * DD * (2 * NF)];
__device__ __nv_bfloat16 g_wdn_h [NE * NF * DD];
__device__ __nv_bfloat16 g_wdn_l [NE * NF * DD];

// ================= helpers =================
__device__ __forceinline__ uint32_t smem_u32(const void* p) {
    uint32_t r;
    asm("{ .reg .u64 t; cvta.to.shared.u64 t, %1; cvt.u32.u64 %0, t; }" : "=r"(r) : "l"(p));
    return r;
}
__device__ __forceinline__ uint32_t pack2bf(__nv_bfloat16 a, __nv_bfloat16 b) {
    return (uint32_t)__bfloat16_as_ushort(a) | ((uint32_t)__bfloat16_as_ushort(b) << 16);
}
__device__ __forceinline__ void ldsm4(uint32_t* r, uint32_t a) {
    asm volatile("ldmatrix.sync.aligned.m8n8.x4.shared.b16 {%0,%1,%2,%3}, [%4];"
                 : "=r"(r[0]), "=r"(r[1]), "=r"(r[2]), "=r"(r[3]) : "r"(a));
}
__device__ __forceinline__ void ldsm4t(uint32_t* r, uint32_t a) {
    asm volatile("ldmatrix.sync.aligned.m8n8.x4.trans.shared.b16 {%0,%1,%2,%3}, [%4];"
                 : "=r"(r[0]), "=r"(r[1]), "=r"(r[2]), "=r"(r[3]) : "r"(a));
}
__device__ __forceinline__ void mma16816(float* c, const uint32_t* a, const uint32_t* b) {
    asm volatile("mma.sync.aligned.m16n8k16.row.col.f32.bf16.bf16.f32 "
                 "{%0,%1,%2,%3}, {%4,%5,%6,%7}, {%8,%9}, {%0,%1,%2,%3};"
                 : "+f"(c[0]), "+f"(c[1]), "+f"(c[2]), "+f"(c[3])
                 : "r"(a[0]), "r"(a[1]), "r"(a[2]), "r"(a[3]), "r"(b[0]), "r"(b[1]));
}
#define CP16(dst, src) \
    asm volatile("cp.async.cg.shared.global [%0], [%1], 16;" :: "r"(dst), "l"(src))
#define CP_COMMIT() asm volatile("cp.async.commit_group;" ::: "memory")
#define CP_WAIT1()  asm volatile("cp.async.wait_group 1;" ::: "memory")
#define CP_WAIT0()  asm volatile("cp.async.wait_group 0;" ::: "memory")

__device__ __forceinline__ void split_bf16(float v, __nv_bfloat16& h, __nv_bfloat16& l) {
    h = __float2bfloat16(v);
    l = __float2bfloat16(v - __bfloat162float(h));
}

// ================= streaming weight split (32B/thread) =================
__global__ void wsplit_kernel(const float4* __restrict__ in,
                              uint4* __restrict__ oh, uint4* __restrict__ ol, int n8)
{
    int i = blockIdx.x * blockDim.x + threadIdx.x;
    if (i >= n8) return;
    float4 a = in[2 * i], b = in[2 * i + 1];
    __nv_bfloat16 ha0, la0, ha1, la1, ha2, la2, ha3, la3;
    __nv_bfloat16 hb0, lb0, hb1, lb1, hb2, lb2, hb3, lb3;
    split_bf16(a.x, ha0, la0); split_bf16(a.y, ha1, la1);
    split_bf16(a.z, ha2, la2); split_bf16(a.w, ha3, la3);
    split_bf16(b.x, hb0, lb0); split_bf16(b.y, hb1, lb1);
    split_bf16(b.z, hb2, lb2); split_bf16(b.w, hb3, lb3);
    oh[i] = make_uint4(pack2bf(ha0, ha1), pack2bf(ha2, ha3),
                       pack2bf(hb0, hb1), pack2bf(hb2, hb3));
    ol[i] = make_uint4(pack2bf(la0, la1), pack2bf(la2, la3),
                       pack2bf(lb0, lb1), pack2bf(lb2, lb3));
}
__global__ void wsplit_qkv_kernel(const float4* __restrict__ q, const float4* __restrict__ k,
                                  const float4* __restrict__ v,
                                  uint4* __restrict__ oh, uint4* __restrict__ ol)
{
    int i = blockIdx.x * 256 + threadIdx.x;   // over 2048*384 (uint4 units, 8 bf16 each)
    int row = i / 384, c8 = i % 384;
    int c4 = 2 * c8;
    float4 a, b;
    if (c4 < 512)      { a = q[row * 512 + c4];          b = q[row * 512 + c4 + 1]; }
    else if (c4 < 640) { a = k[row * 128 + (c4 - 512)];  b = k[row * 128 + (c4 - 511)]; }
    else               { a = v[row * 128 + (c4 - 640)];  b = v[row * 128 + (c4 - 639)]; }
    __nv_bfloat16 ha0, la0, ha1, la1, ha2, la2, ha3, la3;
    __nv_bfloat16 hb0, lb0, hb1, lb1, hb2, lb2, hb3, lb3;
    split_bf16(a.x, ha0, la0); split_bf16(a.y, ha1, la1);
    split_bf16(a.z, ha2, la2); split_bf16(a.w, ha3, la3);
    split_bf16(b.x, hb0, lb0); split_bf16(b.y, hb1, lb1);
    split_bf16(b.z, hb2, lb2); split_bf16(b.w, hb3, lb3);
    oh[i] = make_uint4(pack2bf(ha0, ha1), pack2bf(ha2, ha3),
                       pack2bf(hb0, hb1), pack2bf(hb2, hb3));
    ol[i] = make_uint4(pack2bf(la0, la1), pack2bf(la2, la3),
                       pack2bf(lb0, lb1), pack2bf(lb2, lb3));
}
// gate_up, column-interleaved (2f=gate, 2f+1=up), fully vectorized 16B loads/stores
__global__ void wsplit_gu_kernel(const float4* __restrict__ in,   // [NE*DD][2NF/4]
                                 uint4* __restrict__ oh, uint4* __restrict__ ol)
{
    int i = blockIdx.x * 256 + threadIdx.x;   // over NE*DD*NF/4
    int per_row = NF / 4;                      // 256
    int row = i / per_row;
    int j = i % per_row;                       // f base = 4j
    const float4* base = in + (size_t)row * (2 * NF / 4);
    float4 gv = base[j];
    float4 uv = base[NF / 4 + j];
    __nv_bfloat16 gh0, gl0, gh1, gl1, gh2, gl2, gh3, gl3;
    __nv_bfloat16 uh0, ul0, uh1, ul1, uh2, ul2, uh3, ul3;
    split_bf16(gv.x, gh0, gl0); split_bf16(gv.y, gh1, gl1);
    split_bf16(gv.z, gh2, gl2); split_bf16(gv.w, gh3, gl3);
    split_bf16(uv.x, uh0, ul0); split_bf16(uv.y, uh1, ul1);
    split_bf16(uv.z, uh2, ul2); split_bf16(uv.w, uh3, ul3);
    oh[i] = make_uint4(pack2bf(gh0, uh0), pack2bf(gh1, uh1),
                       pack2bf(gh2, uh2), pack2bf(gh3, uh3));
    ol[i] = make_uint4(pack2bf(gl0, ul0), pack2bf(gl1, ul1),
                       pack2bf(gl2, ul2), pack2bf(gl3, ul3));
}

// ================= bf16x3 GEMM: 16 warps x (32x64), trans-B from [K][N] =================
#define KC 32
#define ARS 80
#define BRS 528
#define A_SZ (128 * ARS)
#define B_SZ (KC * BRS)
#define STG  (2 * A_SZ + 2 * B_SZ)
#define AH_O 0
#define AL_O A_SZ
#define BH_O (2 * A_SZ)
#define BL_O (2 * A_SZ + B_SZ)
#define EROFF (3 * STG)
#define GEMM_SMEM (EROFF + 512)
#define GRS 272                    // gated smem row stride (mode-1 epilogue)

// mode 0: dense C = A @ B (+addsrc)
// mode 1: moe gate_up, FUSED SiLU, smem-recoalesced -> g_gated_h/l (C unused)
// mode 2: moe down: atomicAdd into C[tok] * g_rw
__global__ void __launch_bounds__(512) bf16x3_gemm_kernel(
    int mode,
    const __nv_bfloat16* __restrict__ Ah, const __nv_bfloat16* __restrict__ Al,
    const __nv_bfloat16* __restrict__ Bh, const __nv_bfloat16* __restrict__ Bl,
    float* __restrict__ C, const float* __restrict__ addsrc, int N, int K)
{
    int e  = blockIdx.z;
    int m0 = blockIdx.y * 128;
    int n0 = blockIdx.x * 256;
    int cnt = 0;
    if (mode != 0) {
        cnt = g_ecnt[e];
        if (m0 >= cnt) return;
        Bh += (size_t)e * K * N;
        Bl += (size_t)e * K * N;
    }
    extern __shared__ char sm[];
    uint32_t sb = smem_u32(sm);
    int tid = threadIdx.x, wid = tid >> 5, l = tid & 31;
    int* erows_s = (int*)(sm + EROFF);
    if (mode != 0 && tid < 128)
        erows_s[tid] = (m0 + tid < cnt) ? g_erows[e * TT + m0 + tid] : 0;
    __syncthreads();

    int arow = tid >> 2, apart = tid & 3;
    size_t aro;
    if (mode == 0)      aro = (size_t)(m0 + arow) * K;
    else if (mode == 1) aro = (size_t)(erows_s[arow] >> 2) * DD;
    else                aro = (size_t)erows_s[arow] * NF;
    const __nv_bfloat16* aph = Ah + aro + apart * 8;
    const __nv_bfloat16* apl = Al + aro + apart * 8;
    uint32_t a_dst = (uint32_t)(arow * ARS + apart * 16);

    int brow = tid >> 4, bpart = tid & 15;
    size_t bo = (size_t)brow * N + n0 + bpart * 16;
    uint32_t b_dst = (uint32_t)(brow * BRS + bpart * 32);

    int NC = K / KC;

    int wm = wid >> 2, wn = wid & 3;
    int a_r = (l & 7) + ((l >> 3) & 1) * 8;
    int a_c = (l >> 4) * 8;
    uint32_t a_base = (uint32_t)((wm * 32 + a_r) * ARS + a_c * 2);
    uint32_t b_base = (uint32_t)(a_r * BRS + (wn * 64 + a_c) * 2);

    float acc[2][8][4];
#pragma unroll
    for (int mi = 0; mi < 2; mi++)
#pragma unroll
        for (int ni = 0; ni < 8; ni++)
#pragma unroll
            for (int j = 0; j < 4; j++) acc[mi][ni][j] = 0.f;

#pragma unroll
    for (int p = 0; p < 2; p++) {
        if (p < NC) {
            uint32_t st = sb + p * STG;
            int k0 = p * KC;
            CP16(st + AH_O + a_dst, aph + k0);
            CP16(st + AL_O + a_dst, apl + k0);
            const __nv_bfloat16* bsh = Bh + bo + (size_t)k0 * N;
            const __nv_bfloat16* bsl = Bl + bo + (size_t)k0 * N;
            CP16(st + BH_O + b_dst,      bsh);
            CP16(st + BH_O + b_dst + 16, bsh + 8);
            CP16(st + BL_O + b_dst,      bsl);
            CP16(st + BL_O + b_dst + 16, bsl + 8);
        }
        CP_COMMIT();
    }

    for (int c = 0; c < NC; c++) {
        if (c + 1 < NC) CP_WAIT1(); else CP_WAIT0();
        __syncthreads();
        if (c + 2 < NC) {
            int n2 = c + 2;
            uint32_t st = sb + (n2 % 3) * STG;
            int k0 = n2 * KC;
            CP16(st + AH_O + a_dst, aph + k0);
            CP16(st + AL_O + a_dst, apl + k0);
            const __nv_bfloat16* bsh = Bh + bo + (size_t)k0 * N;
            const __nv_bfloat16* bsl = Bl + bo + (size_t)k0 * N;
            CP16(st + BH_O + b_dst,      bsh);
            CP16(st + BH_O + b_dst + 16, bsh + 8);
            CP16(st + BL_O + b_dst,      bsl);
            CP16(st + BL_O + b_dst + 16, bsl + 8);
        }
        CP_COMMIT();

        uint32_t st = sb + (c % 3) * STG;
#pragma unroll
        for (int kk = 0; kk < 2; kk++) {
            uint32_t bh[4][4], bl[4][4];
#pragma unroll
            for (int q = 0; q < 4; q++)
                ldsm4t(bh[q], st + BH_O + b_base + kk * (16 * BRS) + q * 32);
#pragma unroll
            for (int q = 0; q < 4; q++)
                ldsm4t(bl[q], st + BL_O + b_base + kk * (16 * BRS) + q * 32);
#pragma unroll
            for (int mi = 0; mi < 2; mi++) {
                uint32_t ah[4], al[4];
                ldsm4(ah, st + AH_O + a_base + mi * (16 * ARS) + kk * 32);
                ldsm4(al, st + AL_O + a_base + mi * (16 * ARS) + kk * 32);
#pragma unroll
                for (int q = 0; q < 4; q++) {
                    mma16816(acc[mi][2 * q],     ah, &bh[q][0]);
                    mma16816(acc[mi][2 * q + 1], ah, &bh[q][2]);
                }
#pragma unroll
                for (int q = 0; q < 4; q++) {
                    mma16816(acc[mi][2 * q],     ah, &bl[q][0]);
                    mma16816(acc[mi][2 * q + 1], ah, &bl[q][2]);
                }
#pragma unroll
                for (int q = 0; q < 4; q++) {
                    mma16816(acc[mi][2 * q],     al, &bh[q][0]);
                    mma16816(acc[mi][2 * q + 1], al, &bh[q][2]);
                }
            }
        }
    }

    int g = l >> 2, tig = l & 3;

    if (mode == 1) {
        // ---- fused SiLU epilogue with smem re-coalescing ----
        __syncthreads();
#pragma unroll
        for (int mi = 0; mi < 2; mi++) {
            int r0 = wm * 32 + mi * 16 + g;
            int r1 = r0 + 8;
#pragma unroll
            for (int ni = 0; ni < 8; ni++) {
                int f_loc = wn * 32 + ni * 4 + tig;   // 0..127
                float* a = acc[mi][ni];
                float gt0 = a[0];
                float gd0 = a[1] * (gt0 / (1.f + __expf(-gt0)));
                float gt1 = a[2];
                float gd1 = a[3] * (gt1 / (1.f + __expf(-gt1)));
                __nv_bfloat16 h0, lo0, h1, lo1;
                split_bf16(gd0, h0, lo0);
                split_bf16(gd1, h1, lo1);
                *(__nv_bfloat16*)(sm + r0 * GRS + f_loc * 2)             = h0;
                *(__nv_bfloat16*)(sm + 128 * GRS + r0 * GRS + f_loc * 2) = lo0;
                *(__nv_bfloat16*)(sm + r1 * GRS + f_loc * 2)             = h1;
                *(__nv_bfloat16*)(sm + 128 * GRS + r1 * GRS + f_loc * 2) = lo1;
            }
        }
        __syncthreads();
        int fb = n0 >> 1;
        for (int it = tid; it < 2048; it += 512) {
            int row = it >> 4, seg = it & 15;
            if (m0 + row < cnt) {
                int rowid = erows_s[row];
                uint4 vh = *(uint4*)(sm + row * GRS + seg * 16);
                uint4 vl = *(uint4*)(sm + 128 * GRS + row * GRS + seg * 16);
                *(uint4*)(g_gated_h + (size_t)rowid * NF + fb + seg * 8) = vh;
                *(uint4*)(g_gated_l + (size_t)rowid * NF + fb + seg * 8) = vl;
            }
        }
        return;
    }

    // ---- standard epilogue (mode 0 / 2) ----
#pragma unroll
    for (int mi = 0; mi < 2; mi++) {
        int r0 = wm * 32 + mi * 16 + g;
        int r1 = r0 + 8;
        bool v0 = true, v1 = true;
        size_t ro0 = 0, ro1 = 0;
        float w0 = 0.f, w1 = 0.f;
        if (mode == 0) {
            ro0 = (size_t)(m0 + r0) * N;
            ro1 = (size_t)(m0 + r1) * N;
        } else {
            v0 = (m0 + r0) < cnt;
            v1 = (m0 + r1) < cnt;
            int rowid0 = erows_s[r0], rowid1 = erows_s[r1];
            ro0 = (size_t)(rowid0 >> 2) * DD;
            ro1 = (size_t)(rowid1 >> 2) * DD;
            if (v0) w0 = g_rw[rowid0];
            if (v1) w1 = g_rw[rowid1];
        }
#pragma unroll
        for (int ni = 0; ni < 8; ni++) {
            int cc = n0 + wn * 64 + ni * 8 + tig * 2;
            float* a = acc[mi][ni];
            if (mode == 0) {
                if (addsrc) {
                    float2 s0 = *(const float2*)(addsrc + ro0 + cc);
                    float2 s1 = *(const float2*)(addsrc + ro1 + cc);
                    *(float2*)(C + ro0 + cc) = make_float2(a[0] + s0.x, a[1] + s0.y);
                    *(float2*)(C + ro1 + cc) = make_float2(a[2] + s1.x, a[3] + s1.y);
                } else {
                    *(float2*)(C + ro0 + cc) = make_float2(a[0], a[1]);
                    *(float2*)(C + ro1 + cc) = make_float2(a[2], a[3]);
                }
            } else {
                if (v0) { atomicAdd(C + ro0 + cc, w0 * a[0]); atomicAdd(C + ro0 + cc + 1, w0 * a[1]); }
                if (v1) { atomicAdd(C + ro1 + cc, w1 * a[2]); atomicAdd(C + ro1 + cc + 1, w1 * a[3]); }
            }
        }
    }
}

// ================= RMSNorm (split-bf16 + optional fp32 out + optional passthrough copy) =================
// When ocopy != nullptr (the post-attn instance), block 0 also zeroes g_ecnt for routing.
__global__ void rmsnorm_kernel(const float* __restrict__ x,
                               const float* __restrict__ w,
                               float* __restrict__ ofp,
                               __nv_bfloat16* __restrict__ oh,
                               __nv_bfloat16* __restrict__ ol,
                               float* __restrict__ ocopy)
{
    int t = blockIdx.x;
    int tid = threadIdx.x;
    if (ocopy && t == 0 && tid < NE) g_ecnt[tid] = 0;
    const float4* xr = (const float4*)(x + (size_t)t * DD);
    const float4* wr = (const float4*)w;
    float4 v0 = xr[tid], v1 = xr[tid + 256];
    if (ocopy) {
        float4* orow = (float4*)(ocopy + (size_t)t * DD);
        orow[tid] = v0; orow[tid + 256] = v1;
    }
    float ss = v0.x*v0.x + v0.y*v0.y + v0.z*v0.z + v0.w*v0.w
             + v1.x*v1.x + v1.y*v1.y + v1.z*v1.z + v1.w*v1.w;
#pragma unroll
    for (int o = 16; o; o >>= 1) ss += __shfl_xor_sync(0xffffffffu, ss, o);
    __shared__ float red[8];
    if ((tid & 31) == 0) red[tid >> 5] = ss;
    __syncthreads();
    float tot = red[0]+red[1]+red[2]+red[3]+red[4]+red[5]+red[6]+red[7];
    float r = rsqrtf(tot / (float)DD + 1e-6f);
    float4 w0 = wr[tid], w1 = wr[tid + 256];
    float4 o0, o1;
    o0.x = v0.x*r*w0.x; o0.y = v0.y*r*w0.y; o0.z = v0.z*r*w0.z; o0.w = v0.w*r*w0.w;
    o1.x = v1.x*r*w1.x; o1.y = v1.y*r*w1.y; o1.z = v1.z*r*w1.z; o1.w = v1.w*r*w1.w;
    if (ofp) {
        float4* orow = (float4*)(ofp + (size_t)t * DD);
        orow[tid] = o0; orow[tid + 256] = o1;
    }
    __nv_bfloat16 h[8], lo[8];
    split_bf16(o0.x, h[0], lo[0]); split_bf16(o0.y, h[1], lo[1]);
    split_bf16(o0.z, h[2], lo[2]); split_bf16(o0.w, h[3], lo[3]);
    split_bf16(o1.x, h[4], lo[4]); split_bf16(o1.y, h[5], lo[5]);
    split_bf16(o1.z, h[6], lo[6]); split_bf16(o1.w, h[7], lo[7]);
    uint2* ohr = (uint2*)(oh + (size_t)t * DD);
    uint2* olr = (uint2*)(ol + (size_t)t * DD);
    ohr[tid]       = make_uint2(pack2bf(h[0], h[1]),  pack2bf(h[2], h[3]));
    ohr[tid + 256] = make_uint2(pack2bf(h[4], h[5]),  pack2bf(h[6], h[7]));
    olr[tid]       = make_uint2(pack2bf(lo[0], lo[1]), pack2bf(lo[2], lo[3]));
    olr[tid + 256] = make_uint2(pack2bf(lo[4], lo[5]), pack2bf(lo[6], lo[7]));
}

// ================= per-head RMSNorm + RoPE + split =================
__global__ void normrope_kernel(const float* __restrict__ cosb,
                                const float* __restrict__ sinb,
                                const float* __restrict__ qnw,
                                const float* __restrict__ knw)
{
    int t = blockIdx.x;
    int head = blockIdx.y;      // 0..15 q, 16..19 k, 20..23 v
    int h = threadIdx.x;
    if (head >= 20) {
        int kvh = head - 20;
        float v = g_qkv[(size_t)t * QKVW + VOFF + kvh * HDIM + h];
        __nv_bfloat16 hh, ll;
        split_bf16(v, hh, ll);
        size_t o = ((size_t)t * NKV + kvh) * HDIM + h;
        g_v_h[o] = hh; g_v_l[o] = ll;
        return;
    }
    const float* src;
    const float* nw;
    if (head < NQ) { src = g_qkv + (size_t)t * QKVW + head * HDIM;               nw = qnw; }
    else           { src = g_qkv + (size_t)t * QKVW + KOFF + (head - NQ) * HDIM; nw = knw; }
    float v = src[h];
    float ss = v * v;
#pragma unroll
    for (int o = 16; o; o >>= 1) ss += __shfl_xor_sync(0xffffffffu, ss, o);
    __shared__ float red[4];
    __shared__ float xs[128];
    if ((h & 31) == 0) red[h >> 5] = ss;
    __syncthreads();
    float tot = red[0] + red[1] + red[2] + red[3];
    float xn = v * rsqrtf(tot / (float)HDIM + 1e-6f) * nw[h];
    xs[h] = xn;
    __syncthreads();
    float c = cosb[(size_t)t * HDIM + h];
    float s = sinb[(size_t)t * HDIM + h];
    float other = (h < 64) ? xs[h + 64] : xs[h - 64];
    float outv = (h < 64) ? (xn * c - other * s) : (xn * c + other * s);
    __nv_bfloat16 hh, ll;
    split_bf16(outv, hh, ll);
    if (head < NQ) {
        size_t o = ((size_t)t * NQ + head) * HDIM + h;
        g_q_h[o] = hh; g_q_l[o] = ll;
    } else {
        size_t o = ((size_t)t * NKV + (head - NQ)) * HDIM + h;
        g_k_h[o] = hh; g_k_l[o] = ll;
    }
}

// ================= flash attention, bf16x3 HMMA, 128 q-rows / 8 warps, LPT, KV double-buffer =================
#define AT_RST  272
#define QT  (128 * AT_RST)
#define KVT (64 * AT_RST)
#define AT_QH 0
#define AT_QL QT
#define AT_KV0 (2 * QT)              // buffer b at AT_KV0 + b*4*KVT: KH, KL, VH, VL
#define AT_SMEM (2 * QT + 8 * KVT)   // 208896

__device__ __forceinline__ void attn_issue_kv(uint32_t sb, int j0, int kvh, int tid, int buf)
{
    uint32_t kb = sb + AT_KV0 + buf * (4 * KVT);
    int srow = tid >> 2, sp = tid & 3;
    size_t base = ((size_t)(j0 + srow) * NKV + kvh) * HDIM + sp * 32;
    uint32_t d = (uint32_t)(srow * AT_RST + sp * 64);
#pragma unroll
    for (int i = 0; i < 4; i++) {
        CP16(kb + d + i * 16,           g_k_h + base + i * 8);
        CP16(kb + KVT + d + i * 16,     g_k_l + base + i * 8);
        CP16(kb + 2 * KVT + d + i * 16, g_v_h + base + i * 8);
        CP16(kb + 3 * KVT + d + i * 16, g_v_l + base + i * 8);
    }
}

__global__ void __launch_bounds__(256) attn_kernel()
{
    extern __shared__ char sm[];
    uint32_t sb = smem_u32(sm);
    int bx = gridDim.x - 1 - blockIdx.x;   // LPT: heaviest CTAs scheduled first
    int m0 = bx * 128;
    int head = blockIdx.y;
    int kvh = head >> 2;
    int tid = threadIdx.x, wid = tid >> 5, l = tid & 31;
    const float scale = 0.08838834764831843f;

    int njt = 2 * bx + 2;

    {
        int srow = tid >> 1, sp = tid & 1;
        size_t qb = ((size_t)(m0 + srow) * NQ + head) * HDIM + sp * 64;
        uint32_t d = (uint32_t)(srow * AT_RST + sp * 128);
#pragma unroll
        for (int i = 0; i < 8; i++) {
            CP16(sb + AT_QH + d + i * 16, g_q_h + qb + i * 8);
            CP16(sb + AT_QL + d + i * 16, g_q_l + qb + i * 8);
        }
    }
    attn_issue_kv(sb, 0, kvh, tid, 0);
    CP_COMMIT();
    if (njt > 1) { attn_issue_kv(sb, 64, kvh, tid, 1); CP_COMMIT(); }

    int a_r = (l & 7) + ((l >> 3) & 1) * 8;
    int a_c = (l >> 4) * 8;
    int b_r = (l & 7) + (l >> 4) * 8;
    int b_c = ((l >> 3) & 1) * 8;

    float o[16][4];
#pragma unroll
    for (int nd = 0; nd < 16; nd++)
#pragma unroll
        for (int j = 0; j < 4; j++) o[nd][j] = 0.f;
    float m_i0 = -1e30f, m_i1 = -1e30f, l0 = 0.f, l1 = 0.f;

    int rA_glob = m0 + wid * 16 + (l >> 2);
    int rB_glob = rA_glob + 8;

    for (int jt = 0; jt < njt; jt++) {
        if (jt + 1 < njt) CP_WAIT1(); else CP_WAIT0();
        __syncthreads();
        uint32_t kb = sb + AT_KV0 + (jt & 1) * (4 * KVT);

        float s[8][4];
#pragma unroll
        for (int ni = 0; ni < 8; ni++)
#pragma unroll
            for (int j = 0; j < 4; j++) s[ni][j] = 0.f;
#pragma unroll
        for (int ks = 0; ks < 8; ks++) {
            uint32_t qh4[4], ql4[4];
            uint32_t qa = sb + (uint32_t)((wid * 16 + a_r) * AT_RST + (ks * 16 + a_c) * 2);
            ldsm4(qh4, qa + AT_QH);
            ldsm4(ql4, qa + AT_QL);
            uint32_t kh[4][4], kl[4][4];
#pragma unroll
            for (int q2 = 0; q2 < 4; q2++) {
                uint32_t ka = kb + (uint32_t)((q2 * 16 + b_r) * AT_RST + (ks * 16 + b_c) * 2);
                ldsm4(kh[q2], ka);
                ldsm4(kl[q2], ka + KVT);
            }
#pragma unroll
            for (int q2 = 0; q2 < 4; q2++) {
                mma16816(s[2 * q2],     qh4, &kh[q2][0]);
                mma16816(s[2 * q2 + 1], qh4, &kh[q2][2]);
            }
#pragma unroll
            for (int q2 = 0; q2 < 4; q2++) {
                mma16816(s[2 * q2],     qh4, &kl[q2][0]);
                mma16816(s[2 * q2 + 1], qh4, &kl[q2][2]);
            }
#pragma unroll
            for (int q2 = 0; q2 < 4; q2++) {
                mma16816(s[2 * q2],     ql4, &kh[q2][0]);
                mma16816(s[2 * q2 + 1], ql4, &kh[q2][2]);
            }
        }
#pragma unroll
        for (int ni = 0; ni < 8; ni++)
#pragma unroll
            for (int j = 0; j < 4; j++) s[ni][j] *= scale;
        if (jt >= njt - 2) {
            int jbase = jt * 64;
#pragma unroll
            for (int ni = 0; ni < 8; ni++) {
                int c0 = jbase + ni * 8 + 2 * (l & 3), c1 = c0 + 1;
                if (c0 > rA_glob) s[ni][0] = -1e30f;
                if (c1 > rA_glob) s[ni][1] = -1e30f;
                if (c0 > rB_glob) s[ni][2] = -1e30f;
                if (c1 > rB_glob) s[ni][3] = -1e30f;
            }
        }
        float mt0 = -1e30f, mt1 = -1e30f;
#pragma unroll
        for (int ni = 0; ni < 8; ni++) {
            mt0 = fmaxf(mt0, fmaxf(s[ni][0], s[ni][1]));
            mt1 = fmaxf(mt1, fmaxf(s[ni][2], s[ni][3]));
        }
        mt0 = fmaxf(mt0, __shfl_xor_sync(0xffffffffu, mt0, 1));
        mt0 = fmaxf(mt0, __shfl_xor_sync(0xffffffffu, mt0, 2));
        mt1 = fmaxf(mt1, __shfl_xor_sync(0xffffffffu, mt1, 1));
        mt1 = fmaxf(mt1, __shfl_xor_sync(0xffffffffu, mt1, 2));
        float mn0 = fmaxf(m_i0, mt0), mn1 = fmaxf(m_i1, mt1);
        float c0 = __expf(m_i0 - mn0), c1 = __expf(m_i1 - mn1);
        l0 *= c0; l1 *= c1;
#pragma unroll
        for (int nd = 0; nd < 16; nd++) {
            o[nd][0] *= c0; o[nd][1] *= c0; o[nd][2] *= c1; o[nd][3] *= c1;
        }
        m_i0 = mn0; m_i1 = mn1;
        float rs0 = 0.f, rs1 = 0.f;
        uint32_t pha[16], pla[16];
#pragma unroll
        for (int ni = 0; ni < 8; ni++) {
            float p0 = __expf(s[ni][0] - mn0), p1 = __expf(s[ni][1] - mn0);
            float p2 = __expf(s[ni][2] - mn1), p3 = __expf(s[ni][3] - mn1);
            rs0 += p0 + p1; rs1 += p2 + p3;
            __nv_bfloat16 h0, l0b, h1, l1b, h2, l2b, h3, l3b;
            split_bf16(p0, h0, l0b); split_bf16(p1, h1, l1b);
            split_bf16(p2, h2, l2b); split_bf16(p3, h3, l3b);
            pha[2 * ni]     = pack2bf(h0, h1);
            pha[2 * ni + 1] = pack2bf(h2, h3);
            pla[2 * ni]     = pack2bf(l0b, l1b);
            pla[2 * ni + 1] = pack2bf(l2b, l3b);
        }
        rs0 += __shfl_xor_sync(0xffffffffu, rs0, 1);
        rs0 += __shfl_xor_sync(0xffffffffu, rs0, 2);
        rs1 += __shfl_xor_sync(0xffffffffu, rs1, 1);
        rs1 += __shfl_xor_sync(0xffffffffu, rs1, 2);
        l0 += rs0; l1 += rs1;

#pragma unroll
        for (int ks = 0; ks < 4; ks++) {
            const uint32_t* ph = &pha[4 * ks];
            const uint32_t* pl = &pla[4 * ks];
#pragma unroll
            for (int dp = 0; dp < 4; dp++) {
                uint32_t vh[2][4], vl[2][4];
#pragma unroll
                for (int u = 0; u < 2; u++) {
                    uint32_t va = kb + 2 * KVT + (uint32_t)((ks * 16 + a_r) * AT_RST +
                                                            ((2 * dp + u) * 16 + a_c) * 2);
                    ldsm4t(vh[u], va);
                    ldsm4t(vl[u], va + KVT);
                }
                mma16816(o[4 * dp],     ph, &vh[0][0]);
                mma16816(o[4 * dp + 1], ph, &vh[0][2]);
                mma16816(o[4 * dp + 2], ph, &vh[1][0]);
                mma16816(o[4 * dp + 3], ph, &vh[1][2]);
                mma16816(o[4 * dp],     pl, &vh[0][0]);
                mma16816(o[4 * dp + 1], pl, &vh[0][2]);
                mma16816(o[4 * dp + 2], pl, &vh[1][0]);
                mma16816(o[4 * dp + 3], pl, &vh[1][2]);
                mma16816(o[4 * dp],     ph, &vl[0][0]);
                mma16816(o[4 * dp + 1], ph, &vl[0][2]);
                mma16816(o[4 * dp + 2], ph, &vl[1][0]);
                mma16816(o[4 * dp + 3], ph, &vl[1][2]);
            }
        }
        __syncthreads();   // all warps done reading buffer (jt&1) before refilling it
        if (jt + 2 < njt) { attn_issue_kv(sb, (jt + 2) * 64, kvh, tid, jt & 1); CP_COMMIT(); }
    }

    float inv0 = 1.f / l0, inv1 = 1.f / l1;
#pragma unroll
    for (int nd = 0; nd < 16; nd++) {
        int d = nd * 8 + 2 * (l & 3);
        float v0 = o[nd][0] * inv0, v1 = o[nd][1] * inv0;
        float v2 = o[nd][2] * inv1, v3 = o[nd][3] * inv1;
        __nv_bfloat16 h0, lo0, h1, lo1, h2, lo2, h3, lo3;
        split_bf16(v0, h0, lo0); split_bf16(v1, h1, lo1);
        split_bf16(v2, h2, lo2); split_bf16(v3, h3, lo3);
        size_t oA = (size_t)rA_glob * DD + head * HDIM + d;
        size_t oB = (size_t)rB_glob * DD + head * HDIM + d;
        *(uint32_t*)(g_attn_h + oA) = pack2bf(h0, h1);
        *(uint32_t*)(g_attn_l + oA) = pack2bf(lo0, lo1);
        *(uint32_t*)(g_attn_h + oB) = pack2bf(h2, h3);
        *(uint32_t*)(g_attn_l + oB) = pack2bf(lo2, lo3);
    }
}

// ================= routing =================
__global__ void route_kernel(const float* __restrict__ gate_w)
{
    int t = blockIdx.x;
    int tid = threadIdx.x;
    const float* x = g_h2 + (size_t)t * DD;
    float acc[NE];
#pragma unroll
    for (int e = 0; e < NE; e++) acc[e] = 0.f;
    for (int d = tid; d < DD; d += 128) {
        float xv = x[d];
        const float* gw = gate_w + (size_t)d * NE;
#pragma unroll
        for (int e = 0; e < NE; e++) acc[e] += xv * gw[e];
    }
    __shared__ float s[NE * 128];
#pragma unroll
    for (int e = 0; e < NE; e++) s[e * 128 + tid] = acc[e];
    __syncthreads();
    __shared__ float logits[NE];
    if (tid < NE) {
        float sum = 0.f;
        for (int i = 0; i < 128; i++) sum += s[tid * 128 + i];
        logits[tid] = sum;
    }
    __syncthreads();
    if (tid == 0) {
        float mx = -1e30f;
        for (int e = 0; e < NE; e++) mx = fmaxf(mx, logits[e]);
        float p[NE], Z = 0.f;
        for (int e = 0; e < NE; e++) { p[e] = expf(logits[e] - mx); Z += p[e]; }
        for (int e = 0; e < NE; e++) p[e] /= Z;
        int idx[TOPK]; float val[TOPK]; bool used[NE] = {};
        float wsum = 0.f;
        for (int k = 0; k < TOPK; k++) {
            int best = -1; float bv = -1.f;
            for (int e = 0; e < NE; e++)
                if (!used[e] && p[e] > bv) { bv = p[e]; best = e; }
            used[best] = true; idx[k] = best; val[k] = bv; wsum += bv;
        }
        for (int k = 0; k < TOPK; k++) {
            int rowid = t * TOPK + k;
            g_rw[rowid] = val[k] / wsum;
            int e = idx[k];
            int pos = atomicAdd(&g_ecnt[e], 1);
            g_erows[e * TT + pos] = rowid;
        }
    }
}

// ================= launch =================
extern "C" void kernel_launch(void* const* d_in, const int* in_sizes, int n_in,
                              void* d_out, int out_size)
{
    const float* hidden  = (const float*)d_in[0];
    const float* cosb    = (const float*)d_in[1];
    const float* sinb    = (const float*)d_in[2];
    const float* in_ln   = (const float*)d_in[4];
    const float* post_ln = (const float*)d_in[5];
    const float* q_w     = (const float*)d_in[6];
    const float* k_w     = (const float*)d_in[7];
    const float* v_w     = (const float*)d_in[8];
    const float* o_w     = (const float*)d_in[9];
    const float* q_nw    = (const float*)d_in[10];
    const float* k_nw    = (const float*)d_in[11];
    const float* gate_w  = (const float*)d_in[12];
    const float* gup_w   = (const float*)d_in[13];
    const float* down_w  = (const float*)d_in[14];
    float* out = (float*)d_out;

    float *qkv, *hmid, *h2;
    __nv_bfloat16 *hn_h, *hn_l, *attn_h, *attn_l, *h2_h, *h2_l, *gated_h, *gated_l;
    __nv_bfloat16 *wqkv_h, *wqkv_l, *wo_h, *wo_l, *wgu_h, *wgu_l, *wdn_h, *wdn_l;
    cudaGetSymbolAddress((void**)&qkv,  g_qkv);
    cudaGetSymbolAddress((void**)&hmid, g_hmid);
    cudaGetSymbolAddress((void**)&h2,   g_h2);
    cudaGetSymbolAddress((void**)&hn_h, g_hn_h);
    cudaGetSymbolAddress((void**)&hn_l, g_hn_l);
    cudaGetSymbolAddress((void**)&attn_h, g_attn_h);
    cudaGetSymbolAddress((void**)&attn_l, g_attn_l);
    cudaGetSymbolAddress((void**)&h2_h, g_h2_h);
    cudaGetSymbolAddress((void**)&h2_l, g_h2_l);
    cudaGetSymbolAddress((void**)&gated_h, g_gated_h);
    cudaGetSymbolAddress((void**)&gated_l, g_gated_l);
    cudaGetSymbolAddress((void**)&wqkv_h, g_wqkv_h);
    cudaGetSymbolAddress((void**)&wqkv_l, g_wqkv_l);
    cudaGetSymbolAddress((void**)&wo_h,   g_wo_h);
    cudaGetSymbolAddress((void**)&wo_l,   g_wo_l);
    cudaGetSymbolAddress((void**)&wgu_h,  g_wgu_h);
    cudaGetSymbolAddress((void**)&wgu_l,  g_wgu_l);
    cudaGetSymbolAddress((void**)&wdn_h,  g_wdn_h);
    cudaGetSymbolAddress((void**)&wdn_l,  g_wdn_l);

    cudaFuncSetAttribute(bf16x3_gemm_kernel, cudaFuncAttributeMaxDynamicSharedMemorySize, GEMM_SMEM);
    cudaFuncSetAttribute(attn_kernel, cudaFuncAttributeMaxDynamicSharedMemorySize, AT_SMEM);

    // streaming weight split (32B/thread; gate_up column-interleaved for fused SiLU)
    wsplit_qkv_kernel<<<3072, 256>>>((const float4*)q_w, (const float4*)k_w,
                                     (const float4*)v_w, (uint4*)wqkv_h, (uint4*)wqkv_l);
    wsplit_kernel<<<2048, 256>>>((const float4*)o_w,    (uint4*)wo_h,  (uint4*)wo_l,  DD * DD / 8);
    wsplit_gu_kernel<<<32768, 256>>>((const float4*)gup_w, (uint4*)wgu_h, (uint4*)wgu_l);
    wsplit_kernel<<<16384, 256>>>((const float4*)down_w,(uint4*)wdn_h, (uint4*)wdn_l, NE * NF * DD / 8);

    // 1. pre-attn rmsnorm
    rmsnorm_kernel<<<TT, 256>>>(hidden, in_ln, nullptr, hn_h, hn_l, nullptr);
    // 2. fused QKV projection
    bf16x3_gemm_kernel<<<dim3(QKVW / 256, TT / 128), 512, GEMM_SMEM>>>(
        0, hn_h, hn_l, wqkv_h, wqkv_l, qkv, nullptr, QKVW, DD);
    // 3. per-head norm + rope + split
    normrope_kernel<<<dim3(TT, NQ + NKV + NKV), 128>>>(cosb, sinb, q_nw, k_nw);
    // 4. attention (128-row CTAs, 8 warps, LPT, double-buffered KV)
    attn_kernel<<<dim3(TT / 128, NQ), 256, AT_SMEM>>>();
    // 5. O projection + residual
    bf16x3_gemm_kernel<<<dim3(DD / 256, TT / 128), 512, GEMM_SMEM>>>(
        0, attn_h, attn_l, wo_h, wo_l, hmid, hidden, DD, DD);
    // 6. post-attn rmsnorm (+ copies hmid into out; block 0 zeroes g_ecnt)
    rmsnorm_kernel<<<TT, 256>>>(hmid, post_ln, h2, h2_h, h2_l, out);
    // 7. routing
    route_kernel<<<TT, 128>>>(gate_w);
    // 8. sparse expert GEMMs (gate_up fuses SiLU with coalesced stores)
    bf16x3_gemm_kernel<<<dim3((2 * NF) / 256, 16, NE), 512, GEMM_SMEM>>>(
        1, h2_h, h2_l, wgu_h, wgu_l, nullptr, nullptr, 2 * NF, DD);
    bf16x3_gemm_kernel<<<dim3(DD / 256, 16, NE), 512, GEMM_SMEM>>>(
        2, gated_h, gated_l, wdn_h, wdn_l, out, nullptr, DD, NF);
}